// round 1
// baseline (speedup 1.0000x reference)
#include <cuda_runtime.h>
#include <cuda_bf16.h>
#include <math.h>

#define DI __device__ __forceinline__

namespace enc {

constexpr int Bn = 16, Tn = 512, Dn = 1024, Hn = 16, HSn = 64, Ln = 4, DFFn = 4096, NCn = 3;
constexpr int BTn = Bn * Tn;  // 8192

// ---- scratch (static device allocations; no cudaMalloc anywhere) ----
__device__ float g_h  [(size_t)BTn * Dn];           // 32 MB  residual stream
__device__ float g_z  [(size_t)BTn * Dn];           // 32 MB  LN out / attn out (reused)
__device__ float g_qkv[(size_t)3 * BTn * Dn];       // 96 MB  q,k,v in [BT, H*HS] layout
__device__ float g_att[(size_t)Bn * Hn * Tn * Tn];  // 256 MB attention probs
__device__ float g_ffn[(size_t)BTn * DFFn];         // 128 MB FFN hidden
__device__ float g_w  [(size_t)3 * Dn * Dn];        // 12 MB  permuted QKV weights for one layer

DI float warp_sum(float v) {
#pragma unroll
    for (int o = 16; o > 0; o >>= 1) v += __shfl_xor_sync(0xffffffffu, v, o);
    return v;
}

DI float gelu_exact(float x) {
    return 0.5f * x * (1.0f + erff(x * 0.70710678118654752440f));
}

// ---- embedding: h = tok_emb[x] + pos_emb ----
__global__ void embed_kernel(const int* __restrict__ x,
                             const float* __restrict__ tok,
                             const float* __restrict__ pos) {
    long long i4 = (long long)blockIdx.x * blockDim.x + threadIdx.x;
    long long o = i4 * 4;
    if (o >= (long long)BTn * Dn) return;
    int d = (int)(o & (Dn - 1));
    long long r = o >> 10;          // row = b*T + t
    int t = (int)(r & (Tn - 1));
    int tk = x[r];
    float4 a = *(const float4*)(tok + (long long)tk * Dn + d);
    float4 p = *(const float4*)(pos + (long long)t * Dn + d);
    float4 u;
    u.x = a.x + p.x; u.y = a.y + p.y; u.z = a.z + p.z; u.w = a.w + p.w;
    *(float4*)(g_h + o) = u;
}

// ---- layernorm over D=1024, one block (256 thr) per row ----
__global__ void ln_kernel(const float* __restrict__ in, const float* __restrict__ gw,
                          const float* __restrict__ bw, float* __restrict__ out) {
    long long row = blockIdx.x;
    int tid = threadIdx.x;
    const float* xr = in + row * Dn;
    float4 x4 = *(const float4*)(xr + tid * 4);
    float s  = x4.x + x4.y + x4.z + x4.w;
    float s2 = x4.x * x4.x + x4.y * x4.y + x4.z * x4.z + x4.w * x4.w;
    s = warp_sum(s); s2 = warp_sum(s2);
    __shared__ float sh[2][8];
    int w = tid >> 5;
    if ((tid & 31) == 0) { sh[0][w] = s; sh[1][w] = s2; }
    __syncthreads();
    float ts = 0.f, ts2 = 0.f;
#pragma unroll
    for (int i = 0; i < 8; i++) { ts += sh[0][i]; ts2 += sh[1][i]; }
    float mu = ts * (1.0f / Dn);
    float var = ts2 * (1.0f / Dn) - mu * mu;
    float rinv = rsqrtf(var + 1e-5f);
    float4 g4 = *(const float4*)(gw + tid * 4);
    float4 b4 = *(const float4*)(bw + tid * 4);
    float4 u;
    u.x = (x4.x - mu) * rinv * g4.x + b4.x;
    u.y = (x4.y - mu) * rinv * g4.y + b4.y;
    u.z = (x4.z - mu) * rinv * g4.z + b4.z;
    u.w = (x4.w - mu) * rinv * g4.w + b4.w;
    *(float4*)(out + row * Dn + tid * 4) = u;
}

// ---- permute Wq/Wk/Wv [H,D,HS] -> [D, H*HS] for layer l ----
__global__ void permute_w_kernel(const float* __restrict__ Wq, const float* __restrict__ Wk,
                                 const float* __restrict__ Wv, int l) {
    int which = blockIdx.y;
    const float* W = which == 0 ? Wq : (which == 1 ? Wk : Wv);
    long long i4 = (long long)blockIdx.x * blockDim.x + threadIdx.x;
    long long o = i4 * 4;
    if (o >= (long long)Dn * Dn) return;
    int d = (int)(o >> 10);
    int n = (int)(o & 1023);
    int h = n >> 6, e = n & 63;
    float4 v = *(const float4*)(W + (((long long)(l * Hn + h) * Dn + d) * HSn + e));
    *(float4*)(g_w + (long long)which * Dn * Dn + o) = v;
}

// ---- generic tiled SGEMM: C[M,N] = A[M,K] * B[K,N] (+epilogue), batched via z ----
enum { EPI_STORE = 0, EPI_BIAS = 1, EPI_BIAS_RESID = 2, EPI_BIAS_GELU = 3, EPI_SCALE = 4 };
enum { MODE_LIN = 0, MODE_ATT = 1 };  // ATT: offset = (z/16)*T*D + (z%16)*HS

template <int BN, int TN, int EPI, bool TRANSB, int AMODE, int BMODE, int CMODE>
__global__ void __launch_bounds__(256) sgemm_kernel(
    int M, int N, int K,
    const float* __restrict__ A, int lda, long long sA,
    const float* __restrict__ Bm, int ldb, long long sB,
    float* __restrict__ C, int ldc, long long sC,
    const float* __restrict__ bias, float scale)
{
    constexpr int BM = 128, BK = 16, TM = 8;
    constexpr int NT = (BM / TM) * (BN / TN);
    static_assert(NT == 256, "block must be 256 threads");
    __shared__ float As[BK][BM];
    __shared__ float Bs[BK][BN];

    const int tid = threadIdx.x;
    const int z = blockIdx.z;
    long long aoff = (AMODE == MODE_ATT)
        ? ((long long)(z >> 4) * Tn * Dn + (long long)(z & 15) * HSn) : sA * z;
    long long boff = (BMODE == MODE_ATT)
        ? ((long long)(z >> 4) * Tn * Dn + (long long)(z & 15) * HSn) : sB * z;
    long long coff = (CMODE == MODE_ATT)
        ? ((long long)(z >> 4) * Tn * Dn + (long long)(z & 15) * HSn) : sC * z;

    const float* Ab = A + aoff + (long long)blockIdx.x * BM * lda;
    const float* Bb = Bm + boff;
    const int n0 = blockIdx.y * BN;
    float* Cb = C + coff + (long long)blockIdx.x * BM * ldc + n0;

    constexpr int NTX = BN / TN;
    const int tx = tid % NTX;
    const int ty = tid / NTX;

    float acc[TM][TN];
#pragma unroll
    for (int i = 0; i < TM; i++)
#pragma unroll
        for (int j = 0; j < TN; j++) acc[i][j] = 0.f;

    constexpr int ALOADS = (BM * BK / 4) / NT;  // 2
    constexpr int BLOADS = (BN * BK / 4) / NT;  // 2 (BN=128) or 1 (BN=64)

    for (int k0 = 0; k0 < K; k0 += BK) {
#pragma unroll
        for (int j = 0; j < ALOADS; j++) {
            int li = tid + j * NT;
            int ar = li >> 2;            // BK/4 = 4 float4 per row
            int kc = (li & 3) * 4;
            float4 a4 = *(const float4*)(Ab + (long long)ar * lda + (k0 + kc));
            As[kc + 0][ar] = a4.x;
            As[kc + 1][ar] = a4.y;
            As[kc + 2][ar] = a4.z;
            As[kc + 3][ar] = a4.w;
        }
        if (!TRANSB) {
#pragma unroll
            for (int j = 0; j < BLOADS; j++) {
                int li = tid + j * NT;
                int br = li / (BN / 4);
                int bc = (li % (BN / 4)) * 4;
                float4 b4 = *(const float4*)(Bb + (long long)(k0 + br) * ldb + (n0 + bc));
                *(float4*)(&Bs[br][bc]) = b4;
            }
        } else {
            // Bs[kk][n] = B[(n0+n)*ldb + k0+kk]   (B stored [N,K] row-major)
#pragma unroll
            for (int j = 0; j < BLOADS; j++) {
                int li = tid + j * NT;
                int nr = li >> 2;
                int kc = (li & 3) * 4;
                float4 b4 = *(const float4*)(Bb + (long long)(n0 + nr) * ldb + (k0 + kc));
                Bs[kc + 0][nr] = b4.x;
                Bs[kc + 1][nr] = b4.y;
                Bs[kc + 2][nr] = b4.z;
                Bs[kc + 3][nr] = b4.w;
            }
        }
        __syncthreads();
#pragma unroll
        for (int kk = 0; kk < BK; kk++) {
            float4 rav[TM / 4];
            float4 rbv[TN / 4];
#pragma unroll
            for (int i = 0; i < TM / 4; i++)
                rav[i] = *(const float4*)(&As[kk][ty * TM + i * 4]);
#pragma unroll
            for (int j = 0; j < TN / 4; j++)
                rbv[j] = *(const float4*)(&Bs[kk][tx * TN + j * 4]);
            const float* ra = (const float*)rav;
            const float* rb = (const float*)rbv;
#pragma unroll
            for (int i = 0; i < TM; i++)
#pragma unroll
                for (int j = 0; j < TN; j++)
                    acc[i][j] = fmaf(ra[i], rb[j], acc[i][j]);
        }
        __syncthreads();
    }

    // epilogue (float4 coalesced)
#pragma unroll
    for (int i = 0; i < TM; i++) {
        float* Crow = Cb + (long long)(ty * TM + i) * ldc + tx * TN;
#pragma unroll
        for (int j0 = 0; j0 < TN; j0 += 4) {
            float4 v = make_float4(acc[i][j0], acc[i][j0 + 1], acc[i][j0 + 2], acc[i][j0 + 3]);
            if (EPI == EPI_SCALE) { v.x *= scale; v.y *= scale; v.z *= scale; v.w *= scale; }
            if (EPI == EPI_BIAS || EPI == EPI_BIAS_RESID || EPI == EPI_BIAS_GELU) {
                float4 bb = *(const float4*)(bias + n0 + tx * TN + j0);
                v.x += bb.x; v.y += bb.y; v.z += bb.z; v.w += bb.w;
            }
            if (EPI == EPI_BIAS_GELU) {
                v.x = gelu_exact(v.x); v.y = gelu_exact(v.y);
                v.z = gelu_exact(v.z); v.w = gelu_exact(v.w);
            }
            if (EPI == EPI_BIAS_RESID) {
                float4 r = *(const float4*)(Crow + j0);
                v.x += r.x; v.y += r.y; v.z += r.z; v.w += r.w;
            }
            *(float4*)(Crow + j0) = v;
        }
    }
}

// ---- softmax over rows of 512 (one block of 128 threads per row) ----
__global__ void softmax_kernel(float* __restrict__ att) {
    long long row = blockIdx.x;
    float* p = att + row * Tn;
    int tid = threadIdx.x;
    float4 v = ((float4*)p)[tid];
    float m = fmaxf(fmaxf(v.x, v.y), fmaxf(v.z, v.w));
#pragma unroll
    for (int o = 16; o > 0; o >>= 1) m = fmaxf(m, __shfl_xor_sync(0xffffffffu, m, o));
    __shared__ float shm[4], shs[4];
    int w = tid >> 5;
    if ((tid & 31) == 0) shm[w] = m;
    __syncthreads();
    m = fmaxf(fmaxf(shm[0], shm[1]), fmaxf(shm[2], shm[3]));
    float4 e;
    e.x = expf(v.x - m); e.y = expf(v.y - m);
    e.z = expf(v.z - m); e.w = expf(v.w - m);
    float s = e.x + e.y + e.z + e.w;
    s = warp_sum(s);
    if ((tid & 31) == 0) shs[w] = s;
    __syncthreads();
    float inv = 1.0f / (shs[0] + shs[1] + shs[2] + shs[3]);
    e.x *= inv; e.y *= inv; e.z *= inv; e.w *= inv;
    ((float4*)p)[tid] = e;
}

// ---- logits: out[b,c] = sum_i hf[b,i] * Wout[i,c] + bout[c] ----
__global__ void logits_kernel(const float* __restrict__ hf, const float* __restrict__ Wout,
                              const float* __restrict__ bout, float* __restrict__ out) {
    int b = blockIdx.x;
    const float* hb = hf + (long long)b * Tn * Dn;
    float a[3] = {0.f, 0.f, 0.f};
    for (int i = threadIdx.x; i < Tn * Dn; i += blockDim.x) {
        float v = hb[i];
        const float* wr = Wout + (long long)i * NCn;
        a[0] = fmaf(v, wr[0], a[0]);
        a[1] = fmaf(v, wr[1], a[1]);
        a[2] = fmaf(v, wr[2], a[2]);
    }
    __shared__ float sm[3][16];
    int w = threadIdx.x >> 5, ln = threadIdx.x & 31;
#pragma unroll
    for (int c = 0; c < 3; c++) {
        float v = warp_sum(a[c]);
        if (ln == 0) sm[c][w] = v;
    }
    __syncthreads();
    if (threadIdx.x < 3) {
        float t = 0.f;
#pragma unroll
        for (int i = 0; i < 16; i++) t += sm[threadIdx.x][i];
        out[b * NCn + threadIdx.x] = t + bout[threadIdx.x];
    }
}

}  // namespace enc

extern "C" void kernel_launch(void* const* d_in, const int* in_sizes, int n_in,
                              void* d_out, int out_size) {
    using namespace enc;
    (void)in_sizes; (void)n_in; (void)out_size;

    const int*   x     = (const int*)d_in[0];
    const float* tok   = (const float*)d_in[1];
    const float* pos   = (const float*)d_in[2];
    const float* Wq    = (const float*)d_in[3];
    const float* Wk    = (const float*)d_in[4];
    const float* Wv    = (const float*)d_in[5];
    const float* Wproj = (const float*)d_in[6];
    const float* bproj = (const float*)d_in[7];
    const float* ln1g  = (const float*)d_in[8];
    const float* ln1b  = (const float*)d_in[9];
    const float* ln2g  = (const float*)d_in[10];
    const float* ln2b  = (const float*)d_in[11];
    const float* W1    = (const float*)d_in[12];
    const float* b1    = (const float*)d_in[13];
    const float* W2    = (const float*)d_in[14];
    const float* b2    = (const float*)d_in[15];
    const float* lnfg  = (const float*)d_in[16];
    const float* lnfb  = (const float*)d_in[17];
    const float* Wout  = (const float*)d_in[18];
    const float* bout  = (const float*)d_in[19];
    float* out = (float*)d_out;

    static float *ph = nullptr, *pz, *pqkv, *patt, *pffn, *pw;
    if (!ph) {
        cudaGetSymbolAddress((void**)&ph,   g_h);
        cudaGetSymbolAddress((void**)&pz,   g_z);
        cudaGetSymbolAddress((void**)&pqkv, g_qkv);
        cudaGetSymbolAddress((void**)&patt, g_att);
        cudaGetSymbolAddress((void**)&pffn, g_ffn);
        cudaGetSymbolAddress((void**)&pw,   g_w);
    }

    embed_kernel<<<(BTn * Dn / 4 + 255) / 256, 256>>>(x, tok, pos);

    for (int l = 0; l < Ln; l++) {
        // z = LN1(h)
        ln_kernel<<<BTn, 256>>>(ph, ln1g + l * Dn, ln1b + l * Dn, pz);
        // permute this layer's Wq/Wk/Wv to [D, H*HS]
        permute_w_kernel<<<dim3(1024, 3), 256>>>(Wq, Wk, Wv, l);
        // q,k,v = z @ Wp   (batched over 3 via z; A stride 0)
        sgemm_kernel<128, 8, EPI_STORE, false, MODE_LIN, MODE_LIN, MODE_LIN>
            <<<dim3(BTn / 128, Dn / 128, 3), 256>>>(
                BTn, Dn, Dn,
                pz, Dn, 0LL,
                pw, Dn, (long long)Dn * Dn,
                pqkv, Dn, (long long)BTn * Dn,
                nullptr, 1.f);
        // scores = scale * Q K^T  (batched over B*H)
        sgemm_kernel<128, 8, EPI_SCALE, true, MODE_ATT, MODE_ATT, MODE_LIN>
            <<<dim3(Tn / 128, Tn / 128, Bn * Hn), 256>>>(
                Tn, Tn, HSn,
                pqkv, Dn, 0LL,
                pqkv + (long long)BTn * Dn, Dn, 0LL,
                patt, Tn, (long long)Tn * Tn,
                nullptr, 0.125f);
        softmax_kernel<<<Bn * Hn * Tn, 128>>>(patt);
        // o = P V  (written straight into [BT, H*HS] layout in g_z)
        sgemm_kernel<64, 4, EPI_STORE, false, MODE_LIN, MODE_ATT, MODE_ATT>
            <<<dim3(Tn / 128, 1, Bn * Hn), 256>>>(
                Tn, HSn, Tn,
                patt, Tn, (long long)Tn * Tn,
                pqkv + 2LL * BTn * Dn, Dn, 0LL,
                pz, Dn, 0LL,
                nullptr, 1.f);
        // h += o @ Wproj + bproj  (in-place residual)
        sgemm_kernel<128, 8, EPI_BIAS_RESID, false, MODE_LIN, MODE_LIN, MODE_LIN>
            <<<dim3(BTn / 128, Dn / 128, 1), 256>>>(
                BTn, Dn, Dn,
                pz, Dn, 0LL,
                Wproj + (long long)l * Dn * Dn, Dn, 0LL,
                ph, Dn, 0LL,
                bproj + l * Dn, 1.f);
        // z = LN2(h)
        ln_kernel<<<BTn, 256>>>(ph, ln2g + l * Dn, ln2b + l * Dn, pz);
        // ffn = gelu(z @ W1 + b1)
        sgemm_kernel<128, 8, EPI_BIAS_GELU, false, MODE_LIN, MODE_LIN, MODE_LIN>
            <<<dim3(BTn / 128, DFFn / 128, 1), 256>>>(
                BTn, DFFn, Dn,
                pz, Dn, 0LL,
                W1 + (long long)l * Dn * DFFn, DFFn, 0LL,
                pffn, DFFn, 0LL,
                b1 + l * DFFn, 1.f);
        // h += ffn @ W2 + b2
        sgemm_kernel<128, 8, EPI_BIAS_RESID, false, MODE_LIN, MODE_LIN, MODE_LIN>
            <<<dim3(BTn / 128, Dn / 128, 1), 256>>>(
                BTn, Dn, DFFn,
                pffn, DFFn, 0LL,
                W2 + (long long)l * DFFn * Dn, Dn, 0LL,
                ph, Dn, 0LL,
                b2 + l * Dn, 1.f);
    }
    // final LN + logits
    ln_kernel<<<BTn, 256>>>(ph, lnfg, lnfb, pz);
    logits_kernel<<<Bn, 512>>>(pz, Wout, bout, out);
}

// round 2
// speedup vs baseline: 1.0003x; 1.0003x over previous
#include <cuda_runtime.h>
#include <cuda_bf16.h>
#include <math.h>

#define DI __device__ __forceinline__

namespace enc {

constexpr int Bn = 16, Tn = 512, Dn = 1024, Hn = 16, HSn = 64, Ln = 4, DFFn = 4096, NCn = 3;
constexpr int BTn = Bn * Tn;  // 8192

// ---- scratch (static device allocations; no cudaMalloc anywhere) ----
__device__ float g_h  [(size_t)BTn * Dn];           // 32 MB  residual stream
__device__ float g_z  [(size_t)BTn * Dn];           // 32 MB  LN out / attn out (reused)
__device__ float g_qkv[(size_t)3 * BTn * Dn];       // 96 MB  q,k,v in [BT, H*HS] layout
__device__ float g_att[(size_t)Bn * Hn * Tn * Tn];  // 256 MB attention probs
__device__ float g_ffn[(size_t)BTn * DFFn];         // 128 MB FFN hidden
__device__ float g_w  [(size_t)3 * Dn * Dn];        // 12 MB  permuted QKV weights for one layer

DI float warp_sum(float v) {
#pragma unroll
    for (int o = 16; o > 0; o >>= 1) v += __shfl_xor_sync(0xffffffffu, v, o);
    return v;
}

DI float gelu_exact(float x) {
    return 0.5f * x * (1.0f + erff(x * 0.70710678118654752440f));
}

// ---- embedding: h = tok_emb[x] + pos_emb ----
__global__ void embed_kernel(const int* __restrict__ x,
                             const float* __restrict__ tok,
                             const float* __restrict__ pos) {
    long long i4 = (long long)blockIdx.x * blockDim.x + threadIdx.x;
    long long o = i4 * 4;
    if (o >= (long long)BTn * Dn) return;
    int d = (int)(o & (Dn - 1));
    long long r = o >> 10;          // row = b*T + t
    int t = (int)(r & (Tn - 1));
    int tk = x[r];
    float4 a = *(const float4*)(tok + (long long)tk * Dn + d);
    float4 p = *(const float4*)(pos + (long long)t * Dn + d);
    float4 u;
    u.x = a.x + p.x; u.y = a.y + p.y; u.z = a.z + p.z; u.w = a.w + p.w;
    *(float4*)(g_h + o) = u;
}

// ---- layernorm over D=1024, one block (256 thr) per row ----
__global__ void ln_kernel(const float* __restrict__ in, const float* __restrict__ gw,
                          const float* __restrict__ bw, float* __restrict__ out) {
    long long row = blockIdx.x;
    int tid = threadIdx.x;
    const float* xr = in + row * Dn;
    float4 x4 = *(const float4*)(xr + tid * 4);
    float s  = x4.x + x4.y + x4.z + x4.w;
    float s2 = x4.x * x4.x + x4.y * x4.y + x4.z * x4.z + x4.w * x4.w;
    s = warp_sum(s); s2 = warp_sum(s2);
    __shared__ float sh[2][8];
    int w = tid >> 5;
    if ((tid & 31) == 0) { sh[0][w] = s; sh[1][w] = s2; }
    __syncthreads();
    float ts = 0.f, ts2 = 0.f;
#pragma unroll
    for (int i = 0; i < 8; i++) { ts += sh[0][i]; ts2 += sh[1][i]; }
    float mu = ts * (1.0f / Dn);
    float var = ts2 * (1.0f / Dn) - mu * mu;
    float rinv = rsqrtf(var + 1e-5f);
    float4 g4 = *(const float4*)(gw + tid * 4);
    float4 b4 = *(const float4*)(bw + tid * 4);
    float4 u;
    u.x = (x4.x - mu) * rinv * g4.x + b4.x;
    u.y = (x4.y - mu) * rinv * g4.y + b4.y;
    u.z = (x4.z - mu) * rinv * g4.z + b4.z;
    u.w = (x4.w - mu) * rinv * g4.w + b4.w;
    *(float4*)(out + row * Dn + tid * 4) = u;
}

// ---- permute Wq/Wk/Wv [H,D,HS] -> [D, H*HS] for layer l ----
__global__ void permute_w_kernel(const float* __restrict__ Wq, const float* __restrict__ Wk,
                                 const float* __restrict__ Wv, int l) {
    int which = blockIdx.y;
    const float* W = which == 0 ? Wq : (which == 1 ? Wk : Wv);
    long long i4 = (long long)blockIdx.x * blockDim.x + threadIdx.x;
    long long o = i4 * 4;
    if (o >= (long long)Dn * Dn) return;
    int d = (int)(o >> 10);
    int n = (int)(o & 1023);
    int h = n >> 6, e = n & 63;
    float4 v = *(const float4*)(W + (((long long)(l * Hn + h) * Dn + d) * HSn + e));
    *(float4*)(g_w + (long long)which * Dn * Dn + o) = v;
}

// ---- generic tiled SGEMM: C[M,N] = A[M,K] * B[K,N] (+epilogue), batched via z ----
enum { EPI_STORE = 0, EPI_BIAS = 1, EPI_BIAS_RESID = 2, EPI_BIAS_GELU = 3, EPI_SCALE = 4 };
enum { MODE_LIN = 0, MODE_ATT = 1 };  // ATT: offset = (z/16)*T*D + (z%16)*HS

template <int BN, int TN, int EPI, bool TRANSB, int AMODE, int BMODE, int CMODE>
__global__ void __launch_bounds__(256) sgemm_kernel(
    int M, int N, int K,
    const float* __restrict__ A, int lda, long long sA,
    const float* __restrict__ Bm, int ldb, long long sB,
    float* __restrict__ C, int ldc, long long sC,
    const float* __restrict__ bias, float scale)
{
    constexpr int BM = 128, BK = 16, TM = 8;
    constexpr int NT = (BM / TM) * (BN / TN);
    static_assert(NT == 256, "block must be 256 threads");
    __shared__ float As[BK][BM];
    __shared__ float Bs[BK][BN];

    const int tid = threadIdx.x;
    const int z = blockIdx.z;
    long long aoff = (AMODE == MODE_ATT)
        ? ((long long)(z >> 4) * Tn * Dn + (long long)(z & 15) * HSn) : sA * z;
    long long boff = (BMODE == MODE_ATT)
        ? ((long long)(z >> 4) * Tn * Dn + (long long)(z & 15) * HSn) : sB * z;
    long long coff = (CMODE == MODE_ATT)
        ? ((long long)(z >> 4) * Tn * Dn + (long long)(z & 15) * HSn) : sC * z;

    const float* Ab = A + aoff + (long long)blockIdx.x * BM * lda;
    const float* Bb = Bm + boff;
    const int n0 = blockIdx.y * BN;
    float* Cb = C + coff + (long long)blockIdx.x * BM * ldc + n0;

    constexpr int NTX = BN / TN;
    const int tx = tid % NTX;
    const int ty = tid / NTX;

    float acc[TM][TN];
#pragma unroll
    for (int i = 0; i < TM; i++)
#pragma unroll
        for (int j = 0; j < TN; j++) acc[i][j] = 0.f;

    constexpr int ALOADS = (BM * BK / 4) / NT;  // 2
    constexpr int BLOADS = (BN * BK / 4) / NT;  // 2 (BN=128) or 1 (BN=64)

    for (int k0 = 0; k0 < K; k0 += BK) {
#pragma unroll
        for (int j = 0; j < ALOADS; j++) {
            int li = tid + j * NT;
            int ar = li >> 2;            // BK/4 = 4 float4 per row
            int kc = (li & 3) * 4;
            float4 a4 = *(const float4*)(Ab + (long long)ar * lda + (k0 + kc));
            As[kc + 0][ar] = a4.x;
            As[kc + 1][ar] = a4.y;
            As[kc + 2][ar] = a4.z;
            As[kc + 3][ar] = a4.w;
        }
        if (!TRANSB) {
#pragma unroll
            for (int j = 0; j < BLOADS; j++) {
                int li = tid + j * NT;
                int br = li / (BN / 4);
                int bc = (li % (BN / 4)) * 4;
                float4 b4 = *(const float4*)(Bb + (long long)(k0 + br) * ldb + (n0 + bc));
                *(float4*)(&Bs[br][bc]) = b4;
            }
        } else {
            // Bs[kk][n] = B[(n0+n)*ldb + k0+kk]   (B stored [N,K] row-major)
#pragma unroll
            for (int j = 0; j < BLOADS; j++) {
                int li = tid + j * NT;
                int nr = li >> 2;
                int kc = (li & 3) * 4;
                float4 b4 = *(const float4*)(Bb + (long long)(n0 + nr) * ldb + (k0 + kc));
                Bs[kc + 0][nr] = b4.x;
                Bs[kc + 1][nr] = b4.y;
                Bs[kc + 2][nr] = b4.z;
                Bs[kc + 3][nr] = b4.w;
            }
        }
        __syncthreads();
#pragma unroll
        for (int kk = 0; kk < BK; kk++) {
            float4 rav[TM / 4];
            float4 rbv[TN / 4];
#pragma unroll
            for (int i = 0; i < TM / 4; i++)
                rav[i] = *(const float4*)(&As[kk][ty * TM + i * 4]);
#pragma unroll
            for (int j = 0; j < TN / 4; j++)
                rbv[j] = *(const float4*)(&Bs[kk][tx * TN + j * 4]);
            const float* ra = (const float*)rav;
            const float* rb = (const float*)rbv;
#pragma unroll
            for (int i = 0; i < TM; i++)
#pragma unroll
                for (int j = 0; j < TN; j++)
                    acc[i][j] = fmaf(ra[i], rb[j], acc[i][j]);
        }
        __syncthreads();
    }

    // epilogue (float4 coalesced)
#pragma unroll
    for (int i = 0; i < TM; i++) {
        float* Crow = Cb + (long long)(ty * TM + i) * ldc + tx * TN;
#pragma unroll
        for (int j0 = 0; j0 < TN; j0 += 4) {
            float4 v = make_float4(acc[i][j0], acc[i][j0 + 1], acc[i][j0 + 2], acc[i][j0 + 3]);
            if (EPI == EPI_SCALE) { v.x *= scale; v.y *= scale; v.z *= scale; v.w *= scale; }
            if (EPI == EPI_BIAS || EPI == EPI_BIAS_RESID || EPI == EPI_BIAS_GELU) {
                float4 bb = *(const float4*)(bias + n0 + tx * TN + j0);
                v.x += bb.x; v.y += bb.y; v.z += bb.z; v.w += bb.w;
            }
            if (EPI == EPI_BIAS_GELU) {
                v.x = gelu_exact(v.x); v.y = gelu_exact(v.y);
                v.z = gelu_exact(v.z); v.w = gelu_exact(v.w);
            }
            if (EPI == EPI_BIAS_RESID) {
                float4 r = *(const float4*)(Crow + j0);
                v.x += r.x; v.y += r.y; v.z += r.z; v.w += r.w;
            }
            *(float4*)(Crow + j0) = v;
        }
    }
}

// ---- softmax over rows of 512 (one block of 128 threads per row) ----
__global__ void softmax_kernel(float* __restrict__ att) {
    long long row = blockIdx.x;
    float* p = att + row * Tn;
    int tid = threadIdx.x;
    float4 v = ((float4*)p)[tid];
    float m = fmaxf(fmaxf(v.x, v.y), fmaxf(v.z, v.w));
#pragma unroll
    for (int o = 16; o > 0; o >>= 1) m = fmaxf(m, __shfl_xor_sync(0xffffffffu, m, o));
    __shared__ float shm[4], shs[4];
    int w = tid >> 5;
    if ((tid & 31) == 0) shm[w] = m;
    __syncthreads();
    m = fmaxf(fmaxf(shm[0], shm[1]), fmaxf(shm[2], shm[3]));
    float4 e;
    e.x = expf(v.x - m); e.y = expf(v.y - m);
    e.z = expf(v.z - m); e.w = expf(v.w - m);
    float s = e.x + e.y + e.z + e.w;
    s = warp_sum(s);
    if ((tid & 31) == 0) shs[w] = s;
    __syncthreads();
    float inv = 1.0f / (shs[0] + shs[1] + shs[2] + shs[3]);
    e.x *= inv; e.y *= inv; e.z *= inv; e.w *= inv;
    ((float4*)p)[tid] = e;
}

// ---- logits: out[b,c] = sum_i hf[b,i] * Wout[i,c] + bout[c] ----
__global__ void logits_kernel(const float* __restrict__ hf, const float* __restrict__ Wout,
                              const float* __restrict__ bout, float* __restrict__ out) {
    int b = blockIdx.x;
    const float* hb = hf + (long long)b * Tn * Dn;
    float a[3] = {0.f, 0.f, 0.f};
    for (int i = threadIdx.x; i < Tn * Dn; i += blockDim.x) {
        float v = hb[i];
        const float* wr = Wout + (long long)i * NCn;
        a[0] = fmaf(v, wr[0], a[0]);
        a[1] = fmaf(v, wr[1], a[1]);
        a[2] = fmaf(v, wr[2], a[2]);
    }
    __shared__ float sm[3][16];
    int w = threadIdx.x >> 5, ln = threadIdx.x & 31;
#pragma unroll
    for (int c = 0; c < 3; c++) {
        float v = warp_sum(a[c]);
        if (ln == 0) sm[c][w] = v;
    }
    __syncthreads();
    if (threadIdx.x < 3) {
        float t = 0.f;
#pragma unroll
        for (int i = 0; i < 16; i++) t += sm[threadIdx.x][i];
        out[b * NCn + threadIdx.x] = t + bout[threadIdx.x];
    }
}

}  // namespace enc

extern "C" void kernel_launch(void* const* d_in, const int* in_sizes, int n_in,
                              void* d_out, int out_size) {
    using namespace enc;
    (void)in_sizes; (void)n_in; (void)out_size;

    const int*   x     = (const int*)d_in[0];
    const float* tok   = (const float*)d_in[1];
    const float* pos   = (const float*)d_in[2];
    const float* Wq    = (const float*)d_in[3];
    const float* Wk    = (const float*)d_in[4];
    const float* Wv    = (const float*)d_in[5];
    const float* Wproj = (const float*)d_in[6];
    const float* bproj = (const float*)d_in[7];
    const float* ln1g  = (const float*)d_in[8];
    const float* ln1b  = (const float*)d_in[9];
    const float* ln2g  = (const float*)d_in[10];
    const float* ln2b  = (const float*)d_in[11];
    const float* W1    = (const float*)d_in[12];
    const float* b1    = (const float*)d_in[13];
    const float* W2    = (const float*)d_in[14];
    const float* b2    = (const float*)d_in[15];
    const float* lnfg  = (const float*)d_in[16];
    const float* lnfb  = (const float*)d_in[17];
    const float* Wout  = (const float*)d_in[18];
    const float* bout  = (const float*)d_in[19];
    float* out = (float*)d_out;

    static float *ph = nullptr, *pz, *pqkv, *patt, *pffn, *pw;
    if (!ph) {
        cudaGetSymbolAddress((void**)&ph,   g_h);
        cudaGetSymbolAddress((void**)&pz,   g_z);
        cudaGetSymbolAddress((void**)&pqkv, g_qkv);
        cudaGetSymbolAddress((void**)&patt, g_att);
        cudaGetSymbolAddress((void**)&pffn, g_ffn);
        cudaGetSymbolAddress((void**)&pw,   g_w);
    }

    embed_kernel<<<(BTn * Dn / 4 + 255) / 256, 256>>>(x, tok, pos);

    for (int l = 0; l < Ln; l++) {
        // z = LN1(h)
        ln_kernel<<<BTn, 256>>>(ph, ln1g + l * Dn, ln1b + l * Dn, pz);
        // permute this layer's Wq/Wk/Wv to [D, H*HS]
        permute_w_kernel<<<dim3(1024, 3), 256>>>(Wq, Wk, Wv, l);
        // q,k,v = z @ Wp   (batched over 3 via z; A stride 0)
        sgemm_kernel<128, 8, EPI_STORE, false, MODE_LIN, MODE_LIN, MODE_LIN>
            <<<dim3(BTn / 128, Dn / 128, 3), 256>>>(
                BTn, Dn, Dn,
                pz, Dn, 0LL,
                pw, Dn, (long long)Dn * Dn,
                pqkv, Dn, (long long)BTn * Dn,
                nullptr, 1.f);
        // scores = scale * Q K^T  (batched over B*H)
        sgemm_kernel<128, 8, EPI_SCALE, true, MODE_ATT, MODE_ATT, MODE_LIN>
            <<<dim3(Tn / 128, Tn / 128, Bn * Hn), 256>>>(
                Tn, Tn, HSn,
                pqkv, Dn, 0LL,
                pqkv + (long long)BTn * Dn, Dn, 0LL,
                patt, Tn, (long long)Tn * Tn,
                nullptr, 0.125f);
        softmax_kernel<<<Bn * Hn * Tn, 128>>>(patt);
        // o = P V  (written straight into [BT, H*HS] layout in g_z)
        sgemm_kernel<64, 4, EPI_STORE, false, MODE_LIN, MODE_ATT, MODE_ATT>
            <<<dim3(Tn / 128, 1, Bn * Hn), 256>>>(
                Tn, HSn, Tn,
                patt, Tn, (long long)Tn * Tn,
                pqkv + 2LL * BTn * Dn, Dn, 0LL,
                pz, Dn, 0LL,
                nullptr, 1.f);
        // h += o @ Wproj + bproj  (in-place residual)
        sgemm_kernel<128, 8, EPI_BIAS_RESID, false, MODE_LIN, MODE_LIN, MODE_LIN>
            <<<dim3(BTn / 128, Dn / 128, 1), 256>>>(
                BTn, Dn, Dn,
                pz, Dn, 0LL,
                Wproj + (long long)l * Dn * Dn, Dn, 0LL,
                ph, Dn, 0LL,
                bproj + l * Dn, 1.f);
        // z = LN2(h)
        ln_kernel<<<BTn, 256>>>(ph, ln2g + l * Dn, ln2b + l * Dn, pz);
        // ffn = gelu(z @ W1 + b1)
        sgemm_kernel<128, 8, EPI_BIAS_GELU, false, MODE_LIN, MODE_LIN, MODE_LIN>
            <<<dim3(BTn / 128, DFFn / 128, 1), 256>>>(
                BTn, DFFn, Dn,
                pz, Dn, 0LL,
                W1 + (long long)l * Dn * DFFn, DFFn, 0LL,
                pffn, DFFn, 0LL,
                b1 + l * DFFn, 1.f);
        // h += ffn @ W2 + b2
        sgemm_kernel<128, 8, EPI_BIAS_RESID, false, MODE_LIN, MODE_LIN, MODE_LIN>
            <<<dim3(BTn / 128, Dn / 128, 1), 256>>>(
                BTn, Dn, DFFn,
                pffn, DFFn, 0LL,
                W2 + (long long)l * DFFn * Dn, Dn, 0LL,
                ph, Dn, 0LL,
                b2 + l * Dn, 1.f);
    }
    // final LN + logits
    ln_kernel<<<BTn, 256>>>(ph, lnfg, lnfb, pz);
    logits_kernel<<<Bn, 512>>>(pz, Wout, bout, out);
}

// round 4
// speedup vs baseline: 1.9292x; 1.9287x over previous
#include <cuda_runtime.h>
#include <cuda_fp16.h>
#include <cuda_bf16.h>
#include <math.h>
#include <stdint.h>

#define DI __device__ __forceinline__

// ===================== portable PTX helpers (compile for plain sm_103) =====
DI uint32_t smem_u32(const void* p) {
    uint32_t a;
    asm("{ .reg .u64 t; cvta.to.shared.u64 t, %1; cvt.u32.u64 %0, t; }" : "=r"(a) : "l"(p));
    return a;
}
DI void cp16(uint32_t d, const void* s) {
    asm volatile("cp.async.cg.shared.global [%0], [%1], 16;" :: "r"(d), "l"(s) : "memory");
}
#define CP_COMMIT() asm volatile("cp.async.commit_group;" ::: "memory")
#define CP_WAIT1()  asm volatile("cp.async.wait_group 1;" ::: "memory")
#define CP_WAIT0()  asm volatile("cp.async.wait_group 0;" ::: "memory")

DI void ldsm4(uint32_t addr, uint32_t* r) {
    asm volatile("ldmatrix.sync.aligned.m8n8.x4.shared.b16 {%0,%1,%2,%3}, [%4];"
                 : "=r"(r[0]), "=r"(r[1]), "=r"(r[2]), "=r"(r[3]) : "r"(addr));
}
DI void ldsm2(uint32_t addr, uint32_t* r) {
    asm volatile("ldmatrix.sync.aligned.m8n8.x2.shared.b16 {%0,%1}, [%2];"
                 : "=r"(r[0]), "=r"(r[1]) : "r"(addr));
}
DI void mma16816(float* c, const uint32_t* a, const uint32_t* b) {
    asm volatile("mma.sync.aligned.m16n8k16.row.col.f32.f16.f16.f32 "
                 "{%0,%1,%2,%3},{%4,%5,%6,%7},{%8,%9},{%0,%1,%2,%3};"
                 : "+f"(c[0]), "+f"(c[1]), "+f"(c[2]), "+f"(c[3])
                 : "r"(a[0]), "r"(a[1]), "r"(a[2]), "r"(a[3]), "r"(b[0]), "r"(b[1]));
}

namespace enc {

constexpr int Bn = 16, Tn = 512, Dn = 1024, Hn = 16, HSn = 64, Ln = 4, DFFn = 4096, NCn = 3;
constexpr int BTn = Bn * Tn;  // 8192
constexpr float WSCALE = 64.0f;
constexpr float INV_WSCALE = 1.0f / 64.0f;

// ---- scratch ----
__device__ __align__(16) float g_h  [(size_t)BTn * Dn];
__device__ __align__(16) float g_z  [(size_t)BTn * Dn];
__device__ __align__(16) float g_qkv[(size_t)3 * BTn * Dn];
__device__ __align__(16) float g_att[(size_t)Bn * Hn * Tn * Tn];
// activations in hi/lo fp16
__device__ __align__(16) __half g_zh  [(size_t)BTn * Dn];
__device__ __align__(16) __half g_zl  [(size_t)BTn * Dn];
__device__ __align__(16) __half g_ffnh[(size_t)BTn * DFFn];
__device__ __align__(16) __half g_ffnl[(size_t)BTn * DFFn];
// fp16 hi/lo weights, [N,K] layout, scaled by 64
__device__ __align__(16) __half g_wqkv_h[(size_t)Ln * 3 * Dn * Dn];
__device__ __align__(16) __half g_wqkv_l[(size_t)Ln * 3 * Dn * Dn];
__device__ __align__(16) __half g_wproj_h[(size_t)Ln * Dn * Dn];
__device__ __align__(16) __half g_wproj_l[(size_t)Ln * Dn * Dn];
__device__ __align__(16) __half g_w1_h[(size_t)Ln * Dn * DFFn];
__device__ __align__(16) __half g_w1_l[(size_t)Ln * Dn * DFFn];
__device__ __align__(16) __half g_w2_h[(size_t)Ln * DFFn * Dn];
__device__ __align__(16) __half g_w2_l[(size_t)Ln * DFFn * Dn];

DI float warp_sum(float v) {
#pragma unroll
    for (int o = 16; o > 0; o >>= 1) v += __shfl_xor_sync(0xffffffffu, v, o);
    return v;
}
DI float gelu_exact(float x) {
    return 0.5f * x * (1.0f + erff(x * 0.70710678118654752440f));
}

// ---- embedding ----
__global__ void embed_kernel(const int* __restrict__ x,
                             const float* __restrict__ tok,
                             const float* __restrict__ pos) {
    long long i4 = (long long)blockIdx.x * blockDim.x + threadIdx.x;
    long long o = i4 * 4;
    if (o >= (long long)BTn * Dn) return;
    int d = (int)(o & (Dn - 1));
    long long r = o >> 10;
    int t = (int)(r & (Tn - 1));
    int tk = x[r];
    float4 a = *(const float4*)(tok + (long long)tk * Dn + d);
    float4 p = *(const float4*)(pos + (long long)t * Dn + d);
    float4 u;
    u.x = a.x + p.x; u.y = a.y + p.y; u.z = a.z + p.z; u.w = a.w + p.w;
    *(float4*)(g_h + o) = u;
}

// ---- layernorm; HILO=true writes split fp16, else fp32 ----
template <bool HILO>
__global__ void ln_kernel(const float* __restrict__ in, const float* __restrict__ gw,
                          const float* __restrict__ bw, float* __restrict__ outf,
                          __half* __restrict__ oh, __half* __restrict__ ol) {
    long long row = blockIdx.x;
    int tid = threadIdx.x;
    const float* xr = in + row * Dn;
    float4 x4 = *(const float4*)(xr + tid * 4);
    float s  = x4.x + x4.y + x4.z + x4.w;
    float s2 = x4.x * x4.x + x4.y * x4.y + x4.z * x4.z + x4.w * x4.w;
    s = warp_sum(s); s2 = warp_sum(s2);
    __shared__ float sh[2][8];
    int w = tid >> 5;
    if ((tid & 31) == 0) { sh[0][w] = s; sh[1][w] = s2; }
    __syncthreads();
    float ts = 0.f, ts2 = 0.f;
#pragma unroll
    for (int i = 0; i < 8; i++) { ts += sh[0][i]; ts2 += sh[1][i]; }
    float mu = ts * (1.0f / Dn);
    float var = ts2 * (1.0f / Dn) - mu * mu;
    float rinv = rsqrtf(var + 1e-5f);
    float4 g4 = *(const float4*)(gw + tid * 4);
    float4 b4 = *(const float4*)(bw + tid * 4);
    float v[4];
    v[0] = (x4.x - mu) * rinv * g4.x + b4.x;
    v[1] = (x4.y - mu) * rinv * g4.y + b4.y;
    v[2] = (x4.z - mu) * rinv * g4.z + b4.z;
    v[3] = (x4.w - mu) * rinv * g4.w + b4.w;
    if (HILO) {
        __half h[4], l[4];
#pragma unroll
        for (int i = 0; i < 4; i++) {
            h[i] = __float2half_rn(v[i]);
            l[i] = __float2half_rn(v[i] - __half2float(h[i]));
        }
        long long o = row * Dn + tid * 4;
        *(__half2*)(oh + o)     = __halves2half2(h[0], h[1]);
        *(__half2*)(oh + o + 2) = __halves2half2(h[2], h[3]);
        *(__half2*)(ol + o)     = __halves2half2(l[0], l[1]);
        *(__half2*)(ol + o + 2) = __halves2half2(l[2], l[3]);
    } else {
        *(float4*)(outf + row * Dn + tid * 4) = make_float4(v[0], v[1], v[2], v[3]);
    }
}

// ---- fp32 -> hi/lo fp16 split ----
__global__ void hilo_kernel(const float* __restrict__ s, __half* __restrict__ dh,
                            __half* __restrict__ dl) {
    long long o = ((long long)blockIdx.x * blockDim.x + threadIdx.x) * 4;
    float4 v = *(const float4*)(s + o);
    float vv[4] = {v.x, v.y, v.z, v.w};
    __half h[4], l[4];
#pragma unroll
    for (int i = 0; i < 4; i++) {
        h[i] = __float2half_rn(vv[i]);
        l[i] = __float2half_rn(vv[i] - __half2float(h[i]));
    }
    *(__half2*)(dh + o)     = __halves2half2(h[0], h[1]);
    *(__half2*)(dh + o + 2) = __halves2half2(h[2], h[3]);
    *(__half2*)(dl + o)     = __halves2half2(l[0], l[1]);
    *(__half2*)(dl + o + 2) = __halves2half2(l[2], l[3]);
}

// ---- weight prep: transpose [K,N] -> hi/lo fp16 [N,K], scale by 64 ----
__global__ void wprep_lin(const float* __restrict__ src, __half* __restrict__ dh,
                          __half* __restrict__ dl, int K, int N) {
    int l = blockIdx.z;
    src += (long long)l * K * N;
    dh += (long long)l * N * K;
    dl += (long long)l * N * K;
    __shared__ float t[32][33];
    int k0 = blockIdx.x * 32, n0 = blockIdx.y * 32;
    int tx = threadIdx.x, ty = threadIdx.y;  // 32 x 8
#pragma unroll
    for (int j = 0; j < 4; j++)
        t[ty + 8 * j][tx] = src[(long long)(k0 + ty + 8 * j) * N + n0 + tx];
    __syncthreads();
#pragma unroll
    for (int j = 0; j < 4; j++) {
        float v = t[tx][ty + 8 * j] * WSCALE;
        __half h = __float2half_rn(v);
        __half lo = __float2half_rn(v - __half2float(h));
        long long o = (long long)(n0 + ty + 8 * j) * K + k0 + tx;
        dh[o] = h; dl[o] = lo;
    }
}

// ---- qkv weight prep: [L,H,D,HS] -> [N=H*HS, K=D] hi/lo ----
__global__ void wprep_qkv(const float* __restrict__ Wq, const float* __restrict__ Wk,
                          const float* __restrict__ Wv) {
    int z = blockIdx.z;
    int h = z & 15, which = (z >> 4) % 3, l = z / 48;
    const float* W = which == 0 ? Wq : (which == 1 ? Wk : Wv);
    const float* src = W + ((long long)(l * Hn + h) * Dn) * HSn;
    long long base = ((long long)(l * 3 + which)) * Dn * Dn;
    __shared__ float t[32][33];
    int k0 = blockIdx.x * 32, n0 = blockIdx.y * 32;
    int tx = threadIdx.x, ty = threadIdx.y;
#pragma unroll
    for (int j = 0; j < 4; j++)
        t[ty + 8 * j][tx] = src[(long long)(k0 + ty + 8 * j) * HSn + n0 + tx];
    __syncthreads();
#pragma unroll
    for (int j = 0; j < 4; j++) {
        float v = t[tx][ty + 8 * j] * WSCALE;
        __half h2 = __float2half_rn(v);
        __half lo = __float2half_rn(v - __half2float(h2));
        long long o = base + (long long)(h * HSn + n0 + ty + 8 * j) * Dn + k0 + tx;
        g_wqkv_h[o] = h2; g_wqkv_l[o] = lo;
    }
}

// ===================== mma.sync fp16-split GEMM =====================
// C[128x128 tiles] = A(hi/lo)[M,K] * B(hi/lo)[N,K]^T, 3-pass split, BK=32.
enum { EPI_STORE = 0, EPI_BIAS = 1, EPI_BIAS_RESID = 2, EPI_BIAS_GELU = 3, EPI_SCALE = 4 };

// smem stage layout (halfs, row stride 40 = 80B, conflict-free for ldmatrix):
//   Ah @ 0B, Al @ 10240B, Bh @ 20480B, Bl @ 30720B ; stage = 40960B, x2 buffers
constexpr int TG_STAGE_B = 40960;
constexpr int TG_SMEM = 2 * TG_STAGE_B;  // 81920

DI void tg_load(uint32_t sd, const __half* __restrict__ Ah, const __half* __restrict__ Al,
                const __half* __restrict__ Bh, const __half* __restrict__ Bl,
                int K, int k0, int tid) {
#pragma unroll
    for (int j = 0; j < 2; j++) {
        int cid = tid + j * 256;          // 0..511
        int r = cid >> 2;                 // 0..127
        int kc = (cid & 3) * 8;           // 0,8,16,24
        uint32_t d = sd + (uint32_t)(r * 80 + kc * 2);
        long long go = (long long)r * K + k0 + kc;
        cp16(d,          Ah + go);
        cp16(d + 10240u, Al + go);
        cp16(d + 20480u, Bh + go);
        cp16(d + 30720u, Bl + go);
    }
}

DI void tg_compute(uint32_t sb, int wm, int wn, int lane, float acc[4][4][4]) {
    const int i4 = lane >> 3;     // 0..3
    const int l8 = lane & 7;
#pragma unroll
    for (int ks = 0; ks < 2; ks++) {
        uint32_t ahf[4][4], alf[4][4], bhf[4][2], blf[4][2];
#pragma unroll
        for (int mt = 0; mt < 4; mt++) {
            int row = wm * 64 + mt * 16 + (i4 & 1) * 8 + l8;
            int kk  = ks * 16 + (i4 >> 1) * 8;
            uint32_t ad = sb + (uint32_t)(row * 80 + kk * 2);
            ldsm4(ad, ahf[mt]);
            ldsm4(ad + 10240u, alf[mt]);
        }
#pragma unroll
        for (int nt = 0; nt < 4; nt++) {
            int rowb = wn * 32 + nt * 8 + l8;
            int kkb  = ks * 16 + (i4 & 1) * 8;
            uint32_t bd = sb + 20480u + (uint32_t)(rowb * 80 + kkb * 2);
            ldsm2(bd, bhf[nt]);
            ldsm2(bd + 10240u, blf[nt]);
        }
#pragma unroll
        for (int mt = 0; mt < 4; mt++)
#pragma unroll
            for (int nt = 0; nt < 4; nt++) {
                mma16816(acc[mt][nt], ahf[mt], bhf[nt]);
                mma16816(acc[mt][nt], ahf[mt], blf[nt]);
                mma16816(acc[mt][nt], alf[mt], bhf[nt]);
            }
    }
}

template <int EPI>
__global__ void __launch_bounds__(256, 1) tgemm(
    const __half* __restrict__ Ah, const __half* __restrict__ Al,
    const __half* __restrict__ Bh, const __half* __restrict__ Bl, long long sB,
    float* __restrict__ C, int ldc, long long sC,
    const float* __restrict__ bias, int K,
    __half* __restrict__ Ch, __half* __restrict__ Cl)
{
    extern __shared__ char smraw[];
    const uint32_t sb0 = smem_u32(smraw);
    const int tid = threadIdx.x;
    const int lane = tid & 31, wid = tid >> 5;
    const int wm = wid & 1, wn = wid >> 1;

    const __half* Ahp = Ah + (long long)blockIdx.x * 128 * K;
    const __half* Alp = Al + (long long)blockIdx.x * 128 * K;
    const __half* Bhp = Bh + sB * blockIdx.z + (long long)blockIdx.y * 128 * K;
    const __half* Blp = Bl + sB * blockIdx.z + (long long)blockIdx.y * 128 * K;

    float acc[4][4][4];
#pragma unroll
    for (int a = 0; a < 4; a++)
#pragma unroll
        for (int b = 0; b < 4; b++)
#pragma unroll
            for (int c = 0; c < 4; c++) acc[a][b][c] = 0.f;

    const int NI = K >> 5;
    tg_load(sb0, Ahp, Alp, Bhp, Blp, K, 0, tid);
    CP_COMMIT();
    for (int it = 0; it < NI; it++) {
        if (it + 1 < NI) {
            tg_load(sb0 + (uint32_t)(((it + 1) & 1) * TG_STAGE_B),
                    Ahp, Alp, Bhp, Blp, K, (it + 1) << 5, tid);
            CP_COMMIT();
            CP_WAIT1();
        } else {
            CP_WAIT0();
        }
        __syncthreads();
        tg_compute(sb0 + (uint32_t)((it & 1) * TG_STAGE_B), wm, wn, lane, acc);
        __syncthreads();
    }

    // epilogue
    const int q = lane >> 2;
    const int cp2 = (lane & 3) * 2;
    const int gr = blockIdx.x * 128 + wm * 64;
    const int gc = blockIdx.y * 128 + wn * 32;
    float* Cz = (EPI == EPI_BIAS_GELU) ? nullptr : (C + sC * blockIdx.z);
#pragma unroll
    for (int mt = 0; mt < 4; mt++) {
#pragma unroll
        for (int nt = 0; nt < 4; nt++) {
            const float* a = acc[mt][nt];
            int cc = gc + nt * 8 + cp2;
#pragma unroll
            for (int half = 0; half < 2; half++) {
                int rr = gr + mt * 16 + q + half * 8;
                float v0 = a[half * 2 + 0] * INV_WSCALE;
                float v1 = a[half * 2 + 1] * INV_WSCALE;
                if (EPI == EPI_BIAS_RESID || EPI == EPI_BIAS_GELU) {
                    v0 += bias[cc]; v1 += bias[cc + 1];
                }
                if (EPI == EPI_BIAS_GELU) {
                    v0 = gelu_exact(v0); v1 = gelu_exact(v1);
                    __half h0 = __float2half_rn(v0), h1 = __float2half_rn(v1);
                    __half l0 = __float2half_rn(v0 - __half2float(h0));
                    __half l1 = __float2half_rn(v1 - __half2float(h1));
                    long long o = (long long)rr * ldc + cc;
                    *(__half2*)(Ch + o) = __halves2half2(h0, h1);
                    *(__half2*)(Cl + o) = __halves2half2(l0, l1);
                } else {
                    float* cp = Cz + (long long)rr * ldc + cc;
                    if (EPI == EPI_BIAS_RESID) {
                        float2 r = *(float2*)cp;
                        v0 += r.x; v1 += r.y;
                    }
                    *(float2*)cp = make_float2(v0, v1);
                }
            }
        }
    }
}

// ===================== attention path (fp32 SGEMM, proven) =====================
enum { MODE_LIN = 0, MODE_ATT = 1 };

template <int BN, int TN, int EPI, bool TRANSB, int AMODE, int BMODE, int CMODE>
__global__ void __launch_bounds__(256) sgemm_kernel(
    int M, int N, int K,
    const float* __restrict__ A, int lda, long long sA,
    const float* __restrict__ Bm, int ldb, long long sB,
    float* __restrict__ C, int ldc, long long sC,
    const float* __restrict__ bias, float scale)
{
    constexpr int BM = 128, BK = 16, TM = 8;
    constexpr int NT = (BM / TM) * (BN / TN);
    static_assert(NT == 256, "block must be 256 threads");
    __shared__ float As[BK][BM];
    __shared__ float Bs[BK][BN];

    const int tid = threadIdx.x;
    const int z = blockIdx.z;
    long long aoff = (AMODE == MODE_ATT)
        ? ((long long)(z >> 4) * Tn * Dn + (long long)(z & 15) * HSn) : sA * z;
    long long boff = (BMODE == MODE_ATT)
        ? ((long long)(z >> 4) * Tn * Dn + (long long)(z & 15) * HSn) : sB * z;
    long long coff = (CMODE == MODE_ATT)
        ? ((long long)(z >> 4) * Tn * Dn + (long long)(z & 15) * HSn) : sC * z;

    const float* Ab = A + aoff + (long long)blockIdx.x * BM * lda;
    const float* Bb = Bm + boff;
    const int n0 = blockIdx.y * BN;
    float* Cb = C + coff + (long long)blockIdx.x * BM * ldc + n0;

    constexpr int NTX = BN / TN;
    const int tx = tid % NTX;
    const int ty = tid / NTX;

    float acc[TM][TN];
#pragma unroll
    for (int i = 0; i < TM; i++)
#pragma unroll
        for (int j = 0; j < TN; j++) acc[i][j] = 0.f;

    constexpr int ALOADS = (BM * BK / 4) / NT;
    constexpr int BLOADS = (BN * BK / 4) / NT;

    for (int k0 = 0; k0 < K; k0 += BK) {
#pragma unroll
        for (int j = 0; j < ALOADS; j++) {
            int li = tid + j * NT;
            int ar = li >> 2;
            int kc = (li & 3) * 4;
            float4 a4 = *(const float4*)(Ab + (long long)ar * lda + (k0 + kc));
            As[kc + 0][ar] = a4.x;
            As[kc + 1][ar] = a4.y;
            As[kc + 2][ar] = a4.z;
            As[kc + 3][ar] = a4.w;
        }
        if (!TRANSB) {
#pragma unroll
            for (int j = 0; j < BLOADS; j++) {
                int li = tid + j * NT;
                int br = li / (BN / 4);
                int bc = (li % (BN / 4)) * 4;
                float4 b4 = *(const float4*)(Bb + (long long)(k0 + br) * ldb + (n0 + bc));
                *(float4*)(&Bs[br][bc]) = b4;
            }
        } else {
#pragma unroll
            for (int j = 0; j < BLOADS; j++) {
                int li = tid + j * NT;
                int nr = li >> 2;
                int kc = (li & 3) * 4;
                float4 b4 = *(const float4*)(Bb + (long long)(n0 + nr) * ldb + (k0 + kc));
                Bs[kc + 0][nr] = b4.x;
                Bs[kc + 1][nr] = b4.y;
                Bs[kc + 2][nr] = b4.z;
                Bs[kc + 3][nr] = b4.w;
            }
        }
        __syncthreads();
#pragma unroll
        for (int kk = 0; kk < BK; kk++) {
            float4 rav[TM / 4];
            float4 rbv[TN / 4];
#pragma unroll
            for (int i = 0; i < TM / 4; i++)
                rav[i] = *(const float4*)(&As[kk][ty * TM + i * 4]);
#pragma unroll
            for (int j = 0; j < TN / 4; j++)
                rbv[j] = *(const float4*)(&Bs[kk][tx * TN + j * 4]);
            const float* ra = (const float*)rav;
            const float* rb = (const float*)rbv;
#pragma unroll
            for (int i = 0; i < TM; i++)
#pragma unroll
                for (int j = 0; j < TN; j++)
                    acc[i][j] = fmaf(ra[i], rb[j], acc[i][j]);
        }
        __syncthreads();
    }

#pragma unroll
    for (int i = 0; i < TM; i++) {
        float* Crow = Cb + (long long)(ty * TM + i) * ldc + tx * TN;
#pragma unroll
        for (int j0 = 0; j0 < TN; j0 += 4) {
            float4 v = make_float4(acc[i][j0], acc[i][j0 + 1], acc[i][j0 + 2], acc[i][j0 + 3]);
            if (EPI == EPI_SCALE) { v.x *= scale; v.y *= scale; v.z *= scale; v.w *= scale; }
            *(float4*)(Crow + j0) = v;
        }
    }
}

// ---- softmax over rows of 512 ----
__global__ void softmax_kernel(float* __restrict__ att) {
    long long row = blockIdx.x;
    float* p = att + row * Tn;
    int tid = threadIdx.x;
    float4 v = ((float4*)p)[tid];
    float m = fmaxf(fmaxf(v.x, v.y), fmaxf(v.z, v.w));
#pragma unroll
    for (int o = 16; o > 0; o >>= 1) m = fmaxf(m, __shfl_xor_sync(0xffffffffu, m, o));
    __shared__ float shm[4], shs[4];
    int w = tid >> 5;
    if ((tid & 31) == 0) shm[w] = m;
    __syncthreads();
    m = fmaxf(fmaxf(shm[0], shm[1]), fmaxf(shm[2], shm[3]));
    float4 e;
    e.x = expf(v.x - m); e.y = expf(v.y - m);
    e.z = expf(v.z - m); e.w = expf(v.w - m);
    float s = e.x + e.y + e.z + e.w;
    s = warp_sum(s);
    if ((tid & 31) == 0) shs[w] = s;
    __syncthreads();
    float inv = 1.0f / (shs[0] + shs[1] + shs[2] + shs[3]);
    e.x *= inv; e.y *= inv; e.z *= inv; e.w *= inv;
    ((float4*)p)[tid] = e;
}

// ---- logits ----
__global__ void logits_kernel(const float* __restrict__ hf, const float* __restrict__ Wout,
                              const float* __restrict__ bout, float* __restrict__ out) {
    int b = blockIdx.x;
    const float* hb = hf + (long long)b * Tn * Dn;
    float a[3] = {0.f, 0.f, 0.f};
    for (int i = threadIdx.x; i < Tn * Dn; i += blockDim.x) {
        float v = hb[i];
        const float* wr = Wout + (long long)i * NCn;
        a[0] = fmaf(v, wr[0], a[0]);
        a[1] = fmaf(v, wr[1], a[1]);
        a[2] = fmaf(v, wr[2], a[2]);
    }
    __shared__ float sm[3][16];
    int w = threadIdx.x >> 5, ln = threadIdx.x & 31;
#pragma unroll
    for (int c = 0; c < 3; c++) {
        float v = warp_sum(a[c]);
        if (ln == 0) sm[c][w] = v;
    }
    __syncthreads();
    if (threadIdx.x < 3) {
        float t = 0.f;
#pragma unroll
        for (int i = 0; i < 16; i++) t += sm[threadIdx.x][i];
        out[b * NCn + threadIdx.x] = t + bout[threadIdx.x];
    }
}

}  // namespace enc

extern "C" void kernel_launch(void* const* d_in, const int* in_sizes, int n_in,
                              void* d_out, int out_size) {
    using namespace enc;
    (void)in_sizes; (void)n_in; (void)out_size;

    const int*   x     = (const int*)d_in[0];
    const float* tok   = (const float*)d_in[1];
    const float* pos   = (const float*)d_in[2];
    const float* Wq    = (const float*)d_in[3];
    const float* Wk    = (const float*)d_in[4];
    const float* Wv    = (const float*)d_in[5];
    const float* Wproj = (const float*)d_in[6];
    const float* bproj = (const float*)d_in[7];
    const float* ln1g  = (const float*)d_in[8];
    const float* ln1b  = (const float*)d_in[9];
    const float* ln2g  = (const float*)d_in[10];
    const float* ln2b  = (const float*)d_in[11];
    const float* W1    = (const float*)d_in[12];
    const float* b1    = (const float*)d_in[13];
    const float* W2    = (const float*)d_in[14];
    const float* b2    = (const float*)d_in[15];
    const float* lnfg  = (const float*)d_in[16];
    const float* lnfb  = (const float*)d_in[17];
    const float* Wout  = (const float*)d_in[18];
    const float* bout  = (const float*)d_in[19];
    float* out = (float*)d_out;

    static float *ph = nullptr, *pz, *pqkv, *patt;
    static __half *zh, *zl, *fh, *fl;
    static __half *wqh, *wql, *wph, *wpl, *w1h, *w1l, *w2h, *w2l;
    if (!ph) {
        cudaGetSymbolAddress((void**)&ph,   g_h);
        cudaGetSymbolAddress((void**)&pz,   g_z);
        cudaGetSymbolAddress((void**)&pqkv, g_qkv);
        cudaGetSymbolAddress((void**)&patt, g_att);
        cudaGetSymbolAddress((void**)&zh, g_zh);
        cudaGetSymbolAddress((void**)&zl, g_zl);
        cudaGetSymbolAddress((void**)&fh, g_ffnh);
        cudaGetSymbolAddress((void**)&fl, g_ffnl);
        cudaGetSymbolAddress((void**)&wqh, g_wqkv_h);
        cudaGetSymbolAddress((void**)&wql, g_wqkv_l);
        cudaGetSymbolAddress((void**)&wph, g_wproj_h);
        cudaGetSymbolAddress((void**)&wpl, g_wproj_l);
        cudaGetSymbolAddress((void**)&w1h, g_w1_h);
        cudaGetSymbolAddress((void**)&w1l, g_w1_l);
        cudaGetSymbolAddress((void**)&w2h, g_w2_h);
        cudaGetSymbolAddress((void**)&w2l, g_w2_l);
        cudaFuncSetAttribute(tgemm<EPI_STORE>,      cudaFuncAttributeMaxDynamicSharedMemorySize, TG_SMEM);
        cudaFuncSetAttribute(tgemm<EPI_BIAS_RESID>, cudaFuncAttributeMaxDynamicSharedMemorySize, TG_SMEM);
        cudaFuncSetAttribute(tgemm<EPI_BIAS_GELU>,  cudaFuncAttributeMaxDynamicSharedMemorySize, TG_SMEM);
    }

    // ---- prep ----
    embed_kernel<<<(BTn * Dn / 4 + 255) / 256, 256>>>(x, tok, pos);
    wprep_qkv<<<dim3(Dn / 32, HSn / 32, Ln * 3 * Hn), dim3(32, 8)>>>(Wq, Wk, Wv);
    wprep_lin<<<dim3(Dn / 32, Dn / 32, Ln),   dim3(32, 8)>>>(Wproj, wph, wpl, Dn, Dn);
    wprep_lin<<<dim3(Dn / 32, DFFn / 32, Ln), dim3(32, 8)>>>(W1, w1h, w1l, Dn, DFFn);
    wprep_lin<<<dim3(DFFn / 32, Dn / 32, Ln), dim3(32, 8)>>>(W2, w2h, w2l, DFFn, Dn);

    for (int l = 0; l < Ln; l++) {
        // z = LN1(h) -> hi/lo
        ln_kernel<true><<<BTn, 256>>>(ph, ln1g + l * Dn, ln1b + l * Dn, nullptr, zh, zl);
        // q,k,v = z @ W  (tensor, batched over 3)
        tgemm<EPI_STORE><<<dim3(BTn / 128, Dn / 128, 3), 256, TG_SMEM>>>(
            zh, zl,
            wqh + (long long)l * 3 * Dn * Dn, wql + (long long)l * 3 * Dn * Dn, (long long)Dn * Dn,
            pqkv, Dn, (long long)BTn * Dn, nullptr, Dn, nullptr, nullptr);
        // scores = scale * Q K^T
        sgemm_kernel<128, 8, EPI_SCALE, true, MODE_ATT, MODE_ATT, MODE_LIN>
            <<<dim3(Tn / 128, Tn / 128, Bn * Hn), 256>>>(
                Tn, Tn, HSn,
                pqkv, Dn, 0LL,
                pqkv + (long long)BTn * Dn, Dn, 0LL,
                patt, Tn, (long long)Tn * Tn, nullptr, 0.125f);
        softmax_kernel<<<Bn * Hn * Tn, 128>>>(patt);
        // o = P V  -> g_z fp32
        sgemm_kernel<64, 4, EPI_STORE, false, MODE_LIN, MODE_ATT, MODE_ATT>
            <<<dim3(Tn / 128, 1, Bn * Hn), 256>>>(
                Tn, HSn, Tn,
                patt, Tn, (long long)Tn * Tn,
                pqkv + 2LL * BTn * Dn, Dn, 0LL,
                pz, Dn, 0LL, nullptr, 1.f);
        // o -> hi/lo
        hilo_kernel<<<BTn * Dn / 4 / 256, 256>>>(pz, zh, zl);
        // h += o @ Wproj + bproj
        tgemm<EPI_BIAS_RESID><<<dim3(BTn / 128, Dn / 128, 1), 256, TG_SMEM>>>(
            zh, zl,
            wph + (long long)l * Dn * Dn, wpl + (long long)l * Dn * Dn, 0LL,
            ph, Dn, 0LL, bproj + l * Dn, Dn, nullptr, nullptr);
        // z = LN2(h) -> hi/lo
        ln_kernel<true><<<BTn, 256>>>(ph, ln2g + l * Dn, ln2b + l * Dn, nullptr, zh, zl);
        // ffn = gelu(z @ W1 + b1) -> hi/lo fp16
        tgemm<EPI_BIAS_GELU><<<dim3(BTn / 128, DFFn / 128, 1), 256, TG_SMEM>>>(
            zh, zl,
            w1h + (long long)l * Dn * DFFn, w1l + (long long)l * Dn * DFFn, 0LL,
            nullptr, DFFn, 0LL, b1 + l * DFFn, Dn, fh, fl);
        // h += ffn @ W2 + b2
        tgemm<EPI_BIAS_RESID><<<dim3(BTn / 128, Dn / 128, 1), 256, TG_SMEM>>>(
            fh, fl,
            w2h + (long long)l * DFFn * Dn, w2l + (long long)l * DFFn * Dn, 0LL,
            ph, Dn, 0LL, b2 + l * Dn, DFFn, nullptr, nullptr);
    }
    ln_kernel<false><<<BTn, 256>>>(ph, lnfg, lnfb, pz, nullptr, nullptr);
    logits_kernel<<<Bn, 512>>>(pz, Wout, bout, out);
}

// round 5
// speedup vs baseline: 2.0729x; 1.0745x over previous
#include <cuda_runtime.h>
#include <cuda_fp16.h>
#include <cuda_bf16.h>
#include <math.h>
#include <stdint.h>

#define DI __device__ __forceinline__

// ===================== portable PTX helpers (plain sm_103) =====================
DI uint32_t smem_u32(const void* p) {
    uint32_t a;
    asm("{ .reg .u64 t; cvta.to.shared.u64 t, %1; cvt.u32.u64 %0, t; }" : "=r"(a) : "l"(p));
    return a;
}
DI void cp16(uint32_t d, const void* s) {
    asm volatile("cp.async.cg.shared.global [%0], [%1], 16;" :: "r"(d), "l"(s) : "memory");
}
#define CP_COMMIT() asm volatile("cp.async.commit_group;" ::: "memory")
#define CP_WAIT1()  asm volatile("cp.async.wait_group 1;" ::: "memory")
#define CP_WAIT0()  asm volatile("cp.async.wait_group 0;" ::: "memory")

DI void ldsm4(uint32_t addr, uint32_t* r) {
    asm volatile("ldmatrix.sync.aligned.m8n8.x4.shared.b16 {%0,%1,%2,%3}, [%4];"
                 : "=r"(r[0]), "=r"(r[1]), "=r"(r[2]), "=r"(r[3]) : "r"(addr));
}
DI void ldsm2(uint32_t addr, uint32_t* r) {
    asm volatile("ldmatrix.sync.aligned.m8n8.x2.shared.b16 {%0,%1}, [%2];"
                 : "=r"(r[0]), "=r"(r[1]) : "r"(addr));
}
DI void mma16816(float* c, const uint32_t* a, const uint32_t* b) {
    asm volatile("mma.sync.aligned.m16n8k16.row.col.f32.f16.f16.f32 "
                 "{%0,%1,%2,%3},{%4,%5,%6,%7},{%8,%9},{%0,%1,%2,%3};"
                 : "+f"(c[0]), "+f"(c[1]), "+f"(c[2]), "+f"(c[3])
                 : "r"(a[0]), "r"(a[1]), "r"(a[2]), "r"(a[3]), "r"(b[0]), "r"(b[1]));
}

namespace enc {

constexpr int Bn = 16, Tn = 512, Dn = 1024, Hn = 16, HSn = 64, Ln = 4, DFFn = 4096, NCn = 3;
constexpr int BTn = Bn * Tn;  // 8192
constexpr float WSCALE = 64.0f;
constexpr float INV_WSCALE = 1.0f / 64.0f;

// ---- scratch ----
__device__ __align__(16) float g_h  [(size_t)BTn * Dn];
__device__ __align__(16) float g_z  [(size_t)BTn * Dn];
__device__ __align__(16) float g_att[(size_t)Bn * Hn * Tn * Tn];
// activations hi/lo fp16
__device__ __align__(16) __half g_zh  [(size_t)BTn * Dn];
__device__ __align__(16) __half g_zl  [(size_t)BTn * Dn];
__device__ __align__(16) __half g_qkvh[(size_t)3 * BTn * Dn];
__device__ __align__(16) __half g_qkvl[(size_t)3 * BTn * Dn];
__device__ __align__(16) __half g_ph  [(size_t)Bn * Hn * Tn * Tn];
__device__ __align__(16) __half g_pl  [(size_t)Bn * Hn * Tn * Tn];
__device__ __align__(16) __half g_vth [(size_t)BTn * Dn];
__device__ __align__(16) __half g_vtl [(size_t)BTn * Dn];
__device__ __align__(16) __half g_ffnh[(size_t)BTn * DFFn];
__device__ __align__(16) __half g_ffnl[(size_t)BTn * DFFn];
// fp16 hi/lo weights, [N,K] layout, scaled by 64
__device__ __align__(16) __half g_wqkv_h[(size_t)Ln * 3 * Dn * Dn];
__device__ __align__(16) __half g_wqkv_l[(size_t)Ln * 3 * Dn * Dn];
__device__ __align__(16) __half g_wproj_h[(size_t)Ln * Dn * Dn];
__device__ __align__(16) __half g_wproj_l[(size_t)Ln * Dn * Dn];
__device__ __align__(16) __half g_w1_h[(size_t)Ln * Dn * DFFn];
__device__ __align__(16) __half g_w1_l[(size_t)Ln * Dn * DFFn];
__device__ __align__(16) __half g_w2_h[(size_t)Ln * DFFn * Dn];
__device__ __align__(16) __half g_w2_l[(size_t)Ln * DFFn * Dn];

DI float warp_sum(float v) {
#pragma unroll
    for (int o = 16; o > 0; o >>= 1) v += __shfl_xor_sync(0xffffffffu, v, o);
    return v;
}
DI float gelu_exact(float x) {
    return 0.5f * x * (1.0f + erff(x * 0.70710678118654752440f));
}

// ---- embedding ----
__global__ void embed_kernel(const int* __restrict__ x,
                             const float* __restrict__ tok,
                             const float* __restrict__ pos) {
    long long i4 = (long long)blockIdx.x * blockDim.x + threadIdx.x;
    long long o = i4 * 4;
    if (o >= (long long)BTn * Dn) return;
    int d = (int)(o & (Dn - 1));
    long long r = o >> 10;
    int t = (int)(r & (Tn - 1));
    int tk = x[r];
    float4 a = *(const float4*)(tok + (long long)tk * Dn + d);
    float4 p = *(const float4*)(pos + (long long)t * Dn + d);
    float4 u;
    u.x = a.x + p.x; u.y = a.y + p.y; u.z = a.z + p.z; u.w = a.w + p.w;
    *(float4*)(g_h + o) = u;
}

// ---- layernorm; HILO=true writes split fp16 ----
template <bool HILO>
__global__ void ln_kernel(const float* __restrict__ in, const float* __restrict__ gw,
                          const float* __restrict__ bw, float* __restrict__ outf,
                          __half* __restrict__ oh, __half* __restrict__ ol) {
    long long row = blockIdx.x;
    int tid = threadIdx.x;
    const float* xr = in + row * Dn;
    float4 x4 = *(const float4*)(xr + tid * 4);
    float s  = x4.x + x4.y + x4.z + x4.w;
    float s2 = x4.x * x4.x + x4.y * x4.y + x4.z * x4.z + x4.w * x4.w;
    s = warp_sum(s); s2 = warp_sum(s2);
    __shared__ float sh[2][8];
    int w = tid >> 5;
    if ((tid & 31) == 0) { sh[0][w] = s; sh[1][w] = s2; }
    __syncthreads();
    float ts = 0.f, ts2 = 0.f;
#pragma unroll
    for (int i = 0; i < 8; i++) { ts += sh[0][i]; ts2 += sh[1][i]; }
    float mu = ts * (1.0f / Dn);
    float var = ts2 * (1.0f / Dn) - mu * mu;
    float rinv = rsqrtf(var + 1e-5f);
    float4 g4 = *(const float4*)(gw + tid * 4);
    float4 b4 = *(const float4*)(bw + tid * 4);
    float v[4];
    v[0] = (x4.x - mu) * rinv * g4.x + b4.x;
    v[1] = (x4.y - mu) * rinv * g4.y + b4.y;
    v[2] = (x4.z - mu) * rinv * g4.z + b4.z;
    v[3] = (x4.w - mu) * rinv * g4.w + b4.w;
    if (HILO) {
        __half h[4], l[4];
#pragma unroll
        for (int i = 0; i < 4; i++) {
            h[i] = __float2half_rn(v[i]);
            l[i] = __float2half_rn(v[i] - __half2float(h[i]));
        }
        long long o = row * Dn + tid * 4;
        *(__half2*)(oh + o)     = __halves2half2(h[0], h[1]);
        *(__half2*)(oh + o + 2) = __halves2half2(h[2], h[3]);
        *(__half2*)(ol + o)     = __halves2half2(l[0], l[1]);
        *(__half2*)(ol + o + 2) = __halves2half2(l[2], l[3]);
    } else {
        *(float4*)(outf + row * Dn + tid * 4) = make_float4(v[0], v[1], v[2], v[3]);
    }
}

// ---- weight prep: transpose [K,N] -> hi/lo fp16 [N,K], scale by 64 ----
__global__ void wprep_lin(const float* __restrict__ src, __half* __restrict__ dh,
                          __half* __restrict__ dl, int K, int N) {
    int l = blockIdx.z;
    src += (long long)l * K * N;
    dh += (long long)l * N * K;
    dl += (long long)l * N * K;
    __shared__ float t[32][33];
    int k0 = blockIdx.x * 32, n0 = blockIdx.y * 32;
    int tx = threadIdx.x, ty = threadIdx.y;
#pragma unroll
    for (int j = 0; j < 4; j++)
        t[ty + 8 * j][tx] = src[(long long)(k0 + ty + 8 * j) * N + n0 + tx];
    __syncthreads();
#pragma unroll
    for (int j = 0; j < 4; j++) {
        float v = t[tx][ty + 8 * j] * WSCALE;
        __half h = __float2half_rn(v);
        __half lo = __float2half_rn(v - __half2float(h));
        long long o = (long long)(n0 + ty + 8 * j) * K + k0 + tx;
        dh[o] = h; dl[o] = lo;
    }
}

// ---- qkv weight prep: [L,H,D,HS] -> [N=H*HS, K=D] hi/lo ----
__global__ void wprep_qkv(const float* __restrict__ Wq, const float* __restrict__ Wk,
                          const float* __restrict__ Wv) {
    int z = blockIdx.z;
    int h = z & 15, which = (z >> 4) % 3, l = z / 48;
    const float* W = which == 0 ? Wq : (which == 1 ? Wk : Wv);
    const float* src = W + ((long long)(l * Hn + h) * Dn) * HSn;
    long long base = ((long long)(l * 3 + which)) * Dn * Dn;
    __shared__ float t[32][33];
    int k0 = blockIdx.x * 32, n0 = blockIdx.y * 32;
    int tx = threadIdx.x, ty = threadIdx.y;
#pragma unroll
    for (int j = 0; j < 4; j++)
        t[ty + 8 * j][tx] = src[(long long)(k0 + ty + 8 * j) * HSn + n0 + tx];
    __syncthreads();
#pragma unroll
    for (int j = 0; j < 4; j++) {
        float v = t[tx][ty + 8 * j] * WSCALE;
        __half h2 = __float2half_rn(v);
        __half lo = __float2half_rn(v - __half2float(h2));
        long long o = base + (long long)(h * HSn + n0 + ty + 8 * j) * Dn + k0 + tx;
        g_wqkv_h[o] = h2; g_wqkv_l[o] = lo;
    }
}

// ---- V transpose: [b*T+t, h*64+e] fp16 hi/lo -> [bh, e, t] ----
__global__ void vtrans_kernel(const __half* __restrict__ vh, const __half* __restrict__ vl,
                              __half* __restrict__ oth, __half* __restrict__ otl) {
    int bh = blockIdx.z, b = bh >> 4, h = bh & 15;
    int t0 = blockIdx.x * 32, e0 = blockIdx.y * 32;
    __shared__ __half sh[32][34], sl[32][34];
    int tx = threadIdx.x, ty = threadIdx.y;
#pragma unroll
    for (int j = 0; j < 4; j++) {
        long long gi = ((long long)(b * Tn + t0 + ty + 8 * j)) * Dn + h * HSn + e0 + tx;
        sh[ty + 8 * j][tx] = vh[gi];
        sl[ty + 8 * j][tx] = vl[gi];
    }
    __syncthreads();
#pragma unroll
    for (int j = 0; j < 4; j++) {
        long long go = ((long long)bh * HSn + e0 + ty + 8 * j) * Tn + t0 + tx;
        oth[go] = sh[tx][ty + 8 * j];
        otl[go] = sl[tx][ty + 8 * j];
    }
}

// ===================== mma.sync fp16-split GEMM =====================
enum { EPI_F32 = 0, EPI_HILO = 1, EPI_BIAS_RESID = 2, EPI_BIAS_GELU = 3 };
enum { MODE_LIN = 0, MODE_ATT = 1 };

// stage layout: Ah@0 (10240B), Al@10240, Bh@20480, Bl@20480+BN*80
template <int BN> struct TgCfg {
    static constexpr int B_ST = BN * 80;
    static constexpr int STAGE = 20480 + 2 * B_ST;
    static constexpr int SMEM = 2 * STAGE;
    static constexpr int WN = BN / 4;
    static constexpr int NTN = WN / 8;
};

template <int BN>
DI void tg_load(uint32_t sd, const __half* __restrict__ Ahp, const __half* __restrict__ Alp,
                int lda, const __half* __restrict__ Bhp, const __half* __restrict__ Blp,
                int ldb, int k0, int tid) {
#pragma unroll
    for (int j = 0; j < 2; j++) {
        int cid = tid + j * 256;
        int r = cid >> 2;
        int kc = (cid & 3) * 8;
        uint32_t d = sd + (uint32_t)(r * 80 + kc * 2);
        long long go = (long long)r * lda + k0 + kc;
        cp16(d, Ahp + go);
        cp16(d + 10240u, Alp + go);
    }
#pragma unroll
    for (int j = 0; j < BN / 64; j++) {
        int cid = tid + j * 256;
        int r = cid >> 2;
        int kc = (cid & 3) * 8;
        uint32_t d = sd + 20480u + (uint32_t)(r * 80 + kc * 2);
        long long go = (long long)r * ldb + k0 + kc;
        cp16(d, Bhp + go);
        cp16(d + (uint32_t)TgCfg<BN>::B_ST, Blp + go);
    }
}

template <int BN>
DI void tg_compute(uint32_t sb, int wm, int wn, int lane, float acc[4][TgCfg<BN>::NTN][4]) {
    constexpr int NTN = TgCfg<BN>::NTN;
    const int i4 = lane >> 3;
    const int l8 = lane & 7;
#pragma unroll
    for (int ks = 0; ks < 2; ks++) {
        uint32_t ahf[4][4], alf[4][4], bhf[NTN][2], blf[NTN][2];
#pragma unroll
        for (int mt = 0; mt < 4; mt++) {
            int row = wm * 64 + mt * 16 + (i4 & 1) * 8 + l8;
            int kk  = ks * 16 + (i4 >> 1) * 8;
            uint32_t ad = sb + (uint32_t)(row * 80 + kk * 2);
            ldsm4(ad, ahf[mt]);
            ldsm4(ad + 10240u, alf[mt]);
        }
#pragma unroll
        for (int nt = 0; nt < NTN; nt++) {
            int rowb = wn * TgCfg<BN>::WN + nt * 8 + l8;
            int kkb  = ks * 16 + (i4 & 1) * 8;
            uint32_t bd = sb + 20480u + (uint32_t)(rowb * 80 + kkb * 2);
            ldsm2(bd, bhf[nt]);
            ldsm2(bd + (uint32_t)TgCfg<BN>::B_ST, blf[nt]);
        }
#pragma unroll
        for (int mt = 0; mt < 4; mt++)
#pragma unroll
            for (int nt = 0; nt < NTN; nt++) {
                mma16816(acc[mt][nt], ahf[mt], bhf[nt]);
                mma16816(acc[mt][nt], ahf[mt], blf[nt]);
                mma16816(acc[mt][nt], alf[mt], bhf[nt]);
            }
    }
}

template <int EPI, int BN, int AMODE, int BMODE, int CMODE>
__global__ void __launch_bounds__(256, 1) tgemm(
    const __half* __restrict__ Ah, const __half* __restrict__ Al, int lda, long long sA,
    const __half* __restrict__ Bh, const __half* __restrict__ Bl, int ldb, long long sB,
    float* __restrict__ Cf, __half* __restrict__ Ch, __half* __restrict__ Cl,
    int ldc, long long sC, const float* __restrict__ bias, int Kext, float oscale)
{
    constexpr int NTN = TgCfg<BN>::NTN;
    extern __shared__ char smraw[];
    const uint32_t sb0 = smem_u32(smraw);
    const int tid = threadIdx.x;
    const int lane = tid & 31, wid = tid >> 5;
    const int wm = wid & 1, wn = wid >> 1;
    const int z = blockIdx.z;

    long long aoff = (AMODE == MODE_ATT)
        ? ((long long)(z >> 4) * Tn * Dn + (long long)(z & 15) * HSn) : sA * z;
    long long boff = (BMODE == MODE_ATT)
        ? ((long long)(z >> 4) * Tn * Dn + (long long)(z & 15) * HSn) : sB * z;
    long long coff = (CMODE == MODE_ATT)
        ? ((long long)(z >> 4) * Tn * Dn + (long long)(z & 15) * HSn) : sC * z;

    const __half* Ahp = Ah + aoff + (long long)blockIdx.x * 128 * lda;
    const __half* Alp = Al + aoff + (long long)blockIdx.x * 128 * lda;
    const __half* Bhp = Bh + boff + (long long)blockIdx.y * BN * ldb;
    const __half* Blp = Bl + boff + (long long)blockIdx.y * BN * ldb;

    float acc[4][NTN][4];
#pragma unroll
    for (int a = 0; a < 4; a++)
#pragma unroll
        for (int b = 0; b < NTN; b++)
#pragma unroll
            for (int c = 0; c < 4; c++) acc[a][b][c] = 0.f;

    const int NI = Kext >> 5;
    tg_load<BN>(sb0, Ahp, Alp, lda, Bhp, Blp, ldb, 0, tid);
    CP_COMMIT();
    for (int it = 0; it < NI; it++) {
        if (it + 1 < NI) {
            tg_load<BN>(sb0 + (uint32_t)(((it + 1) & 1) * TgCfg<BN>::STAGE),
                        Ahp, Alp, lda, Bhp, Blp, ldb, (it + 1) << 5, tid);
            CP_COMMIT();
            CP_WAIT1();
        } else {
            CP_WAIT0();
        }
        __syncthreads();
        tg_compute<BN>(sb0 + (uint32_t)((it & 1) * TgCfg<BN>::STAGE), wm, wn, lane, acc);
        __syncthreads();
    }

    // epilogue
    const int q = lane >> 2;
    const int cp2 = (lane & 3) * 2;
    const int gc = blockIdx.y * BN + wn * TgCfg<BN>::WN;
#pragma unroll
    for (int mt = 0; mt < 4; mt++) {
#pragma unroll
        for (int nt = 0; nt < NTN; nt++) {
            const float* a = acc[mt][nt];
            int cc = gc + nt * 8 + cp2;
#pragma unroll
            for (int half = 0; half < 2; half++) {
                int rr = blockIdx.x * 128 + wm * 64 + mt * 16 + q + half * 8;
                float v0 = a[half * 2 + 0] * oscale;
                float v1 = a[half * 2 + 1] * oscale;
                long long o = coff + (long long)rr * ldc + cc;
                if (EPI == EPI_BIAS_RESID || EPI == EPI_BIAS_GELU) {
                    v0 += bias[cc]; v1 += bias[cc + 1];
                }
                if (EPI == EPI_F32) {
                    *(float2*)(Cf + o) = make_float2(v0, v1);
                } else if (EPI == EPI_BIAS_RESID) {
                    float2 r = *(float2*)(Cf + o);
                    *(float2*)(Cf + o) = make_float2(v0 + r.x, v1 + r.y);
                } else {  // HILO / BIAS_GELU
                    if (EPI == EPI_BIAS_GELU) { v0 = gelu_exact(v0); v1 = gelu_exact(v1); }
                    __half h0 = __float2half_rn(v0), h1 = __float2half_rn(v1);
                    __half l0 = __float2half_rn(v0 - __half2float(h0));
                    __half l1 = __float2half_rn(v1 - __half2float(h1));
                    *(__half2*)(Ch + o) = __halves2half2(h0, h1);
                    *(__half2*)(Cl + o) = __halves2half2(l0, l1);
                }
            }
        }
    }
}

// ---- softmax over rows of 512, fp32 in -> hi/lo fp16 out ----
__global__ void softmax_kernel(const float* __restrict__ att, __half* __restrict__ ph,
                               __half* __restrict__ pl) {
    long long row = blockIdx.x;
    const float* p = att + row * Tn;
    int tid = threadIdx.x;
    float4 v = ((const float4*)p)[tid];
    float m = fmaxf(fmaxf(v.x, v.y), fmaxf(v.z, v.w));
#pragma unroll
    for (int o = 16; o > 0; o >>= 1) m = fmaxf(m, __shfl_xor_sync(0xffffffffu, m, o));
    __shared__ float shm[4], shs[4];
    int w = tid >> 5;
    if ((tid & 31) == 0) shm[w] = m;
    __syncthreads();
    m = fmaxf(fmaxf(shm[0], shm[1]), fmaxf(shm[2], shm[3]));
    float4 e;
    e.x = expf(v.x - m); e.y = expf(v.y - m);
    e.z = expf(v.z - m); e.w = expf(v.w - m);
    float s = e.x + e.y + e.z + e.w;
    s = warp_sum(s);
    if ((tid & 31) == 0) shs[w] = s;
    __syncthreads();
    float inv = 1.0f / (shs[0] + shs[1] + shs[2] + shs[3]);
    float vv[4] = {e.x * inv, e.y * inv, e.z * inv, e.w * inv};
    __half h[4], l[4];
#pragma unroll
    for (int i = 0; i < 4; i++) {
        h[i] = __float2half_rn(vv[i]);
        l[i] = __float2half_rn(vv[i] - __half2float(h[i]));
    }
    long long o = row * Tn + tid * 4;
    *(__half2*)(ph + o)     = __halves2half2(h[0], h[1]);
    *(__half2*)(ph + o + 2) = __halves2half2(h[2], h[3]);
    *(__half2*)(pl + o)     = __halves2half2(l[0], l[1]);
    *(__half2*)(pl + o + 2) = __halves2half2(l[2], l[3]);
}

// ---- logits ----
__global__ void logits_kernel(const float* __restrict__ hf, const float* __restrict__ Wout,
                              const float* __restrict__ bout, float* __restrict__ out) {
    int b = blockIdx.x;
    const float* hb = hf + (long long)b * Tn * Dn;
    float a[3] = {0.f, 0.f, 0.f};
    for (int i = threadIdx.x; i < Tn * Dn; i += blockDim.x) {
        float v = hb[i];
        const float* wr = Wout + (long long)i * NCn;
        a[0] = fmaf(v, wr[0], a[0]);
        a[1] = fmaf(v, wr[1], a[1]);
        a[2] = fmaf(v, wr[2], a[2]);
    }
    __shared__ float sm[3][16];
    int w = threadIdx.x >> 5, ln = threadIdx.x & 31;
#pragma unroll
    for (int c = 0; c < 3; c++) {
        float v = warp_sum(a[c]);
        if (ln == 0) sm[c][w] = v;
    }
    __syncthreads();
    if (threadIdx.x < 3) {
        float t = 0.f;
#pragma unroll
        for (int i = 0; i < 16; i++) t += sm[threadIdx.x][i];
        out[b * NCn + threadIdx.x] = t + bout[threadIdx.x];
    }
}

}  // namespace enc

extern "C" void kernel_launch(void* const* d_in, const int* in_sizes, int n_in,
                              void* d_out, int out_size) {
    using namespace enc;
    (void)in_sizes; (void)n_in; (void)out_size;

    const int*   x     = (const int*)d_in[0];
    const float* tok   = (const float*)d_in[1];
    const float* pos   = (const float*)d_in[2];
    const float* Wq    = (const float*)d_in[3];
    const float* Wk    = (const float*)d_in[4];
    const float* Wv    = (const float*)d_in[5];
    const float* Wproj = (const float*)d_in[6];
    const float* bproj = (const float*)d_in[7];
    const float* ln1g  = (const float*)d_in[8];
    const float* ln1b  = (const float*)d_in[9];
    const float* ln2g  = (const float*)d_in[10];
    const float* ln2b  = (const float*)d_in[11];
    const float* W1    = (const float*)d_in[12];
    const float* b1    = (const float*)d_in[13];
    const float* W2    = (const float*)d_in[14];
    const float* b2    = (const float*)d_in[15];
    const float* lnfg  = (const float*)d_in[16];
    const float* lnfb  = (const float*)d_in[17];
    const float* Wout  = (const float*)d_in[18];
    const float* bout  = (const float*)d_in[19];
    float* out = (float*)d_out;

    constexpr long long TT = (long long)Tn * Tn;

    static float *ph = nullptr, *pz, *patt;
    static __half *zh, *zl, *qh, *ql, *pph, *ppl, *vth, *vtl, *fh, *fl;
    static __half *wqh, *wql, *wph, *wpl, *w1h, *w1l, *w2h, *w2l;
    if (!ph) {
        cudaGetSymbolAddress((void**)&ph,   g_h);
        cudaGetSymbolAddress((void**)&pz,   g_z);
        cudaGetSymbolAddress((void**)&patt, g_att);
        cudaGetSymbolAddress((void**)&zh, g_zh);
        cudaGetSymbolAddress((void**)&zl, g_zl);
        cudaGetSymbolAddress((void**)&qh, g_qkvh);
        cudaGetSymbolAddress((void**)&ql, g_qkvl);
        cudaGetSymbolAddress((void**)&pph, g_ph);
        cudaGetSymbolAddress((void**)&ppl, g_pl);
        cudaGetSymbolAddress((void**)&vth, g_vth);
        cudaGetSymbolAddress((void**)&vtl, g_vtl);
        cudaGetSymbolAddress((void**)&fh, g_ffnh);
        cudaGetSymbolAddress((void**)&fl, g_ffnl);
        cudaGetSymbolAddress((void**)&wqh, g_wqkv_h);
        cudaGetSymbolAddress((void**)&wql, g_wqkv_l);
        cudaGetSymbolAddress((void**)&wph, g_wproj_h);
        cudaGetSymbolAddress((void**)&wpl, g_wproj_l);
        cudaGetSymbolAddress((void**)&w1h, g_w1_h);
        cudaGetSymbolAddress((void**)&w1l, g_w1_l);
        cudaGetSymbolAddress((void**)&w2h, g_w2_h);
        cudaGetSymbolAddress((void**)&w2l, g_w2_l);
        cudaFuncSetAttribute((const void*)tgemm<EPI_HILO, 128, MODE_LIN, MODE_LIN, MODE_LIN>,
                             cudaFuncAttributeMaxDynamicSharedMemorySize, TgCfg<128>::SMEM);
        cudaFuncSetAttribute((const void*)tgemm<EPI_F32, 128, MODE_ATT, MODE_ATT, MODE_LIN>,
                             cudaFuncAttributeMaxDynamicSharedMemorySize, TgCfg<128>::SMEM);
        cudaFuncSetAttribute((const void*)tgemm<EPI_HILO, 64, MODE_LIN, MODE_LIN, MODE_ATT>,
                             cudaFuncAttributeMaxDynamicSharedMemorySize, TgCfg<64>::SMEM);
        cudaFuncSetAttribute((const void*)tgemm<EPI_BIAS_RESID, 128, MODE_LIN, MODE_LIN, MODE_LIN>,
                             cudaFuncAttributeMaxDynamicSharedMemorySize, TgCfg<128>::SMEM);
        cudaFuncSetAttribute((const void*)tgemm<EPI_BIAS_GELU, 128, MODE_LIN, MODE_LIN, MODE_LIN>,
                             cudaFuncAttributeMaxDynamicSharedMemorySize, TgCfg<128>::SMEM);
    }

    // ---- prep ----
    embed_kernel<<<(BTn * Dn / 4 + 255) / 256, 256>>>(x, tok, pos);
    wprep_qkv<<<dim3(Dn / 32, HSn / 32, Ln * 3 * Hn), dim3(32, 8)>>>(Wq, Wk, Wv);
    wprep_lin<<<dim3(Dn / 32, Dn / 32, Ln),   dim3(32, 8)>>>(Wproj, wph, wpl, Dn, Dn);
    wprep_lin<<<dim3(Dn / 32, DFFn / 32, Ln), dim3(32, 8)>>>(W1, w1h, w1l, Dn, DFFn);
    wprep_lin<<<dim3(DFFn / 32, Dn / 32, Ln), dim3(32, 8)>>>(W2, w2h, w2l, DFFn, Dn);

    for (int l = 0; l < Ln; l++) {
        // z = LN1(h) -> hi/lo
        ln_kernel<true><<<BTn, 256>>>(ph, ln1g + l * Dn, ln1b + l * Dn, nullptr, zh, zl);
        // q,k,v = z @ W -> hi/lo fp16 directly
        tgemm<EPI_HILO, 128, MODE_LIN, MODE_LIN, MODE_LIN>
            <<<dim3(BTn / 128, Dn / 128, 3), 256, TgCfg<128>::SMEM>>>(
                zh, zl, Dn, 0LL,
                wqh + (long long)l * 3 * Dn * Dn, wql + (long long)l * 3 * Dn * Dn, Dn,
                (long long)Dn * Dn,
                nullptr, qh, ql, Dn, (long long)BTn * Dn, nullptr, Dn, INV_WSCALE);
        // V^T hi/lo
        vtrans_kernel<<<dim3(Tn / 32, HSn / 32, Bn * Hn), dim3(32, 8)>>>(
            qh + 2LL * BTn * Dn, ql + 2LL * BTn * Dn, vth, vtl);
        // scores = 0.125 * Q K^T (tensor)
        tgemm<EPI_F32, 128, MODE_ATT, MODE_ATT, MODE_LIN>
            <<<dim3(Tn / 128, Tn / 128, Bn * Hn), 256, TgCfg<128>::SMEM>>>(
                qh, ql, Dn, 0LL,
                qh + (long long)BTn * Dn, ql + (long long)BTn * Dn, Dn, 0LL,
                patt, nullptr, nullptr, Tn, TT, nullptr, HSn, 0.125f);
        // softmax -> P hi/lo
        softmax_kernel<<<Bn * Hn * Tn, 128>>>(patt, pph, ppl);
        // o = P V (tensor) -> zh/zl in [BT, H*HS] layout
        tgemm<EPI_HILO, 64, MODE_LIN, MODE_LIN, MODE_ATT>
            <<<dim3(Tn / 128, 1, Bn * Hn), 256, TgCfg<64>::SMEM>>>(
                pph, ppl, Tn, TT,
                vth, vtl, Tn, (long long)HSn * Tn,
                nullptr, zh, zl, Dn, 0LL, nullptr, Tn, 1.0f);
        // h += o @ Wproj + bproj
        tgemm<EPI_BIAS_RESID, 128, MODE_LIN, MODE_LIN, MODE_LIN>
            <<<dim3(BTn / 128, Dn / 128, 1), 256, TgCfg<128>::SMEM>>>(
                zh, zl, Dn, 0LL,
                wph + (long long)l * Dn * Dn, wpl + (long long)l * Dn * Dn, Dn, 0LL,
                ph, nullptr, nullptr, Dn, 0LL, bproj + l * Dn, Dn, INV_WSCALE);
        // z = LN2(h) -> hi/lo
        ln_kernel<true><<<BTn, 256>>>(ph, ln2g + l * Dn, ln2b + l * Dn, nullptr, zh, zl);
        // ffn = gelu(z @ W1 + b1) -> hi/lo
        tgemm<EPI_BIAS_GELU, 128, MODE_LIN, MODE_LIN, MODE_LIN>
            <<<dim3(BTn / 128, DFFn / 128, 1), 256, TgCfg<128>::SMEM>>>(
                zh, zl, Dn, 0LL,
                w1h + (long long)l * Dn * DFFn, w1l + (long long)l * Dn * DFFn, Dn, 0LL,
                nullptr, fh, fl, DFFn, 0LL, b1 + l * DFFn, Dn, INV_WSCALE);
        // h += ffn @ W2 + b2
        tgemm<EPI_BIAS_RESID, 128, MODE_LIN, MODE_LIN, MODE_LIN>
            <<<dim3(BTn / 128, Dn / 128, 1), 256, TgCfg<128>::SMEM>>>(
                fh, fl, DFFn, 0LL,
                w2h + (long long)l * DFFn * Dn, w2l + (long long)l * DFFn * Dn, DFFn, 0LL,
                ph, nullptr, nullptr, Dn, 0LL, b2 + l * Dn, DFFn, INV_WSCALE);
    }
    ln_kernel<false><<<BTn, 256>>>(ph, lnfg, lnfb, pz, nullptr, nullptr);
    logits_kernel<<<Bn, 512>>>(pz, Wout, bout, out);
}

// round 6
// speedup vs baseline: 2.4137x; 1.1644x over previous
#include <cuda_runtime.h>
#include <cuda_fp16.h>
#include <cuda_bf16.h>
#include <math.h>
#include <stdint.h>

#define DI __device__ __forceinline__

// ===================== portable PTX helpers (plain sm_103) =====================
DI uint32_t smem_u32(const void* p) {
    uint32_t a;
    asm("{ .reg .u64 t; cvta.to.shared.u64 t, %1; cvt.u32.u64 %0, t; }" : "=r"(a) : "l"(p));
    return a;
}
DI void cp16(uint32_t d, const void* s) {
    asm volatile("cp.async.cg.shared.global [%0], [%1], 16;" :: "r"(d), "l"(s) : "memory");
}
#define CP_COMMIT() asm volatile("cp.async.commit_group;" ::: "memory")
#define CP_WAIT1()  asm volatile("cp.async.wait_group 1;" ::: "memory")
#define CP_WAIT0()  asm volatile("cp.async.wait_group 0;" ::: "memory")

DI void ldsm4(uint32_t addr, uint32_t* r) {
    asm volatile("ldmatrix.sync.aligned.m8n8.x4.shared.b16 {%0,%1,%2,%3}, [%4];"
                 : "=r"(r[0]), "=r"(r[1]), "=r"(r[2]), "=r"(r[3]) : "r"(addr));
}
DI void ldsm2(uint32_t addr, uint32_t* r) {
    asm volatile("ldmatrix.sync.aligned.m8n8.x2.shared.b16 {%0,%1}, [%2];"
                 : "=r"(r[0]), "=r"(r[1]) : "r"(addr));
}
DI void mma16816(float* c, const uint32_t* a, const uint32_t* b) {
    asm volatile("mma.sync.aligned.m16n8k16.row.col.f32.f16.f16.f32 "
                 "{%0,%1,%2,%3},{%4,%5,%6,%7},{%8,%9},{%0,%1,%2,%3};"
                 : "+f"(c[0]), "+f"(c[1]), "+f"(c[2]), "+f"(c[3])
                 : "r"(a[0]), "r"(a[1]), "r"(a[2]), "r"(a[3]), "r"(b[0]), "r"(b[1]));
}

namespace enc {

constexpr int Bn = 16, Tn = 512, Dn = 1024, Hn = 16, HSn = 64, Ln = 4, DFFn = 4096, NCn = 3;
constexpr int BTn = Bn * Tn;  // 8192
constexpr float WSCALE = 64.0f;
constexpr float INV_WSCALE = 1.0f / 64.0f;

// ---- scratch ----
__device__ __align__(16) float g_h  [(size_t)BTn * Dn];
__device__ __align__(16) float g_z  [(size_t)BTn * Dn];
__device__ __align__(16) float g_att[(size_t)Bn * Hn * Tn * Tn];
// activations hi/lo fp16
__device__ __align__(16) __half g_zh  [(size_t)BTn * Dn];
__device__ __align__(16) __half g_zl  [(size_t)BTn * Dn];
__device__ __align__(16) __half g_qkvh[(size_t)3 * BTn * Dn];
__device__ __align__(16) __half g_qkvl[(size_t)3 * BTn * Dn];
__device__ __align__(16) __half g_ph  [(size_t)Bn * Hn * Tn * Tn];
__device__ __align__(16) __half g_pl  [(size_t)Bn * Hn * Tn * Tn];
__device__ __align__(16) __half g_vth [(size_t)BTn * Dn];
__device__ __align__(16) __half g_vtl [(size_t)BTn * Dn];
__device__ __align__(16) __half g_ffnh[(size_t)BTn * DFFn];
__device__ __align__(16) __half g_ffnl[(size_t)BTn * DFFn];
// fp16 hi/lo weights, [N,K] layout, scaled by 64
__device__ __align__(16) __half g_wqkv_h[(size_t)Ln * 3 * Dn * Dn];
__device__ __align__(16) __half g_wqkv_l[(size_t)Ln * 3 * Dn * Dn];
__device__ __align__(16) __half g_wproj_h[(size_t)Ln * Dn * Dn];
__device__ __align__(16) __half g_wproj_l[(size_t)Ln * Dn * Dn];
__device__ __align__(16) __half g_w1_h[(size_t)Ln * Dn * DFFn];
__device__ __align__(16) __half g_w1_l[(size_t)Ln * Dn * DFFn];
__device__ __align__(16) __half g_w2_h[(size_t)Ln * DFFn * Dn];
__device__ __align__(16) __half g_w2_l[(size_t)Ln * DFFn * Dn];

DI float warp_sum(float v) {
#pragma unroll
    for (int o = 16; o > 0; o >>= 1) v += __shfl_xor_sync(0xffffffffu, v, o);
    return v;
}
DI float gelu_exact(float x) {
    return 0.5f * x * (1.0f + erff(x * 0.70710678118654752440f));
}

// ---- embedding ----
__global__ void embed_kernel(const int* __restrict__ x,
                             const float* __restrict__ tok,
                             const float* __restrict__ pos) {
    long long i4 = (long long)blockIdx.x * blockDim.x + threadIdx.x;
    long long o = i4 * 4;
    if (o >= (long long)BTn * Dn) return;
    int d = (int)(o & (Dn - 1));
    long long r = o >> 10;
    int t = (int)(r & (Tn - 1));
    int tk = x[r];
    float4 a = *(const float4*)(tok + (long long)tk * Dn + d);
    float4 p = *(const float4*)(pos + (long long)t * Dn + d);
    float4 u;
    u.x = a.x + p.x; u.y = a.y + p.y; u.z = a.z + p.z; u.w = a.w + p.w;
    *(float4*)(g_h + o) = u;
}

// ---- layernorm; HILO=true writes split fp16 ----
template <bool HILO>
__global__ void ln_kernel(const float* __restrict__ in, const float* __restrict__ gw,
                          const float* __restrict__ bw, float* __restrict__ outf,
                          __half* __restrict__ oh, __half* __restrict__ ol) {
    long long row = blockIdx.x;
    int tid = threadIdx.x;
    const float* xr = in + row * Dn;
    float4 x4 = *(const float4*)(xr + tid * 4);
    float s  = x4.x + x4.y + x4.z + x4.w;
    float s2 = x4.x * x4.x + x4.y * x4.y + x4.z * x4.z + x4.w * x4.w;
    s = warp_sum(s); s2 = warp_sum(s2);
    __shared__ float sh[2][8];
    int w = tid >> 5;
    if ((tid & 31) == 0) { sh[0][w] = s; sh[1][w] = s2; }
    __syncthreads();
    float ts = 0.f, ts2 = 0.f;
#pragma unroll
    for (int i = 0; i < 8; i++) { ts += sh[0][i]; ts2 += sh[1][i]; }
    float mu = ts * (1.0f / Dn);
    float var = ts2 * (1.0f / Dn) - mu * mu;
    float rinv = rsqrtf(var + 1e-5f);
    float4 g4 = *(const float4*)(gw + tid * 4);
    float4 b4 = *(const float4*)(bw + tid * 4);
    float v[4];
    v[0] = (x4.x - mu) * rinv * g4.x + b4.x;
    v[1] = (x4.y - mu) * rinv * g4.y + b4.y;
    v[2] = (x4.z - mu) * rinv * g4.z + b4.z;
    v[3] = (x4.w - mu) * rinv * g4.w + b4.w;
    if (HILO) {
        __half h[4], l[4];
#pragma unroll
        for (int i = 0; i < 4; i++) {
            h[i] = __float2half_rn(v[i]);
            l[i] = __float2half_rn(v[i] - __half2float(h[i]));
        }
        long long o = row * Dn + tid * 4;
        *(__half2*)(oh + o)     = __halves2half2(h[0], h[1]);
        *(__half2*)(oh + o + 2) = __halves2half2(h[2], h[3]);
        *(__half2*)(ol + o)     = __halves2half2(l[0], l[1]);
        *(__half2*)(ol + o + 2) = __halves2half2(l[2], l[3]);
    } else {
        *(float4*)(outf + row * Dn + tid * 4) = make_float4(v[0], v[1], v[2], v[3]);
    }
}

// ---- weight prep: transpose [K,N] -> hi/lo fp16 [N,K], scale by 64 ----
__global__ void wprep_lin(const float* __restrict__ src, __half* __restrict__ dh,
                          __half* __restrict__ dl, int K, int N) {
    int l = blockIdx.z;
    src += (long long)l * K * N;
    dh += (long long)l * N * K;
    dl += (long long)l * N * K;
    __shared__ float t[32][33];
    int k0 = blockIdx.x * 32, n0 = blockIdx.y * 32;
    int tx = threadIdx.x, ty = threadIdx.y;
#pragma unroll
    for (int j = 0; j < 4; j++)
        t[ty + 8 * j][tx] = src[(long long)(k0 + ty + 8 * j) * N + n0 + tx];
    __syncthreads();
#pragma unroll
    for (int j = 0; j < 4; j++) {
        float v = t[tx][ty + 8 * j] * WSCALE;
        __half h = __float2half_rn(v);
        __half lo = __float2half_rn(v - __half2float(h));
        long long o = (long long)(n0 + ty + 8 * j) * K + k0 + tx;
        dh[o] = h; dl[o] = lo;
    }
}

// ---- qkv weight prep: [L,H,D,HS] -> [N=H*HS, K=D] hi/lo ----
__global__ void wprep_qkv(const float* __restrict__ Wq, const float* __restrict__ Wk,
                          const float* __restrict__ Wv) {
    int z = blockIdx.z;
    int h = z & 15, which = (z >> 4) % 3, l = z / 48;
    const float* W = which == 0 ? Wq : (which == 1 ? Wk : Wv);
    const float* src = W + ((long long)(l * Hn + h) * Dn) * HSn;
    long long base = ((long long)(l * 3 + which)) * Dn * Dn;
    __shared__ float t[32][33];
    int k0 = blockIdx.x * 32, n0 = blockIdx.y * 32;
    int tx = threadIdx.x, ty = threadIdx.y;
#pragma unroll
    for (int j = 0; j < 4; j++)
        t[ty + 8 * j][tx] = src[(long long)(k0 + ty + 8 * j) * HSn + n0 + tx];
    __syncthreads();
#pragma unroll
    for (int j = 0; j < 4; j++) {
        float v = t[tx][ty + 8 * j] * WSCALE;
        __half h2 = __float2half_rn(v);
        __half lo = __float2half_rn(v - __half2float(h2));
        long long o = base + (long long)(h * HSn + n0 + ty + 8 * j) * Dn + k0 + tx;
        g_wqkv_h[o] = h2; g_wqkv_l[o] = lo;
    }
}

// ---- V transpose: [b*T+t, h*64+e] fp16 hi/lo -> [bh, e, t] ----
__global__ void vtrans_kernel(const __half* __restrict__ vh, const __half* __restrict__ vl,
                              __half* __restrict__ oth, __half* __restrict__ otl) {
    int bh = blockIdx.z, b = bh >> 4, h = bh & 15;
    int t0 = blockIdx.x * 32, e0 = blockIdx.y * 32;
    __shared__ __half sh[32][34], sl[32][34];
    int tx = threadIdx.x, ty = threadIdx.y;
#pragma unroll
    for (int j = 0; j < 4; j++) {
        long long gi = ((long long)(b * Tn + t0 + ty + 8 * j)) * Dn + h * HSn + e0 + tx;
        sh[ty + 8 * j][tx] = vh[gi];
        sl[ty + 8 * j][tx] = vl[gi];
    }
    __syncthreads();
#pragma unroll
    for (int j = 0; j < 4; j++) {
        long long go = ((long long)bh * HSn + e0 + ty + 8 * j) * Tn + t0 + tx;
        oth[go] = sh[tx][ty + 8 * j];
        otl[go] = sl[tx][ty + 8 * j];
    }
}

// ===================== mma.sync fp16-split GEMM =====================
enum { EPI_F32 = 0, EPI_HILO = 1, EPI_BIAS_RESID = 2, EPI_BIAS_GELU = 3 };
enum { MODE_LIN = 0, MODE_ATT = 1 };

// stage layout: Ah@0 (10240B), Al@10240, Bh@20480, Bl@20480+BN*80
template <int BN> struct TgCfg {
    static constexpr int B_ST = BN * 80;
    static constexpr int STAGE = 20480 + 2 * B_ST;
    static constexpr int SMEM = 2 * STAGE;
    static constexpr int WN = BN / 4;
    static constexpr int NTN = WN / 8;
};

template <int BN>
DI void tg_load(uint32_t sd, const __half* __restrict__ Ahp, const __half* __restrict__ Alp,
                int lda, const __half* __restrict__ Bhp, const __half* __restrict__ Blp,
                int ldb, int k0, int tid) {
#pragma unroll
    for (int j = 0; j < 2; j++) {
        int cid = tid + j * 256;
        int r = cid >> 2;
        int kc = (cid & 3) * 8;
        uint32_t d = sd + (uint32_t)(r * 80 + kc * 2);
        long long go = (long long)r * lda + k0 + kc;
        cp16(d, Ahp + go);
        cp16(d + 10240u, Alp + go);
    }
#pragma unroll
    for (int j = 0; j < BN / 64; j++) {
        int cid = tid + j * 256;
        int r = cid >> 2;
        int kc = (cid & 3) * 8;
        uint32_t d = sd + 20480u + (uint32_t)(r * 80 + kc * 2);
        long long go = (long long)r * ldb + k0 + kc;
        cp16(d, Bhp + go);
        cp16(d + (uint32_t)TgCfg<BN>::B_ST, Blp + go);
    }
}

// register-lean compute: B-frags for a ks live across mt; only one mt's A-frags live
template <int BN>
DI void tg_compute(uint32_t sb, int wm, int wn, int lane, float acc[4][TgCfg<BN>::NTN][4]) {
    constexpr int NTN = TgCfg<BN>::NTN;
    const int i4 = lane >> 3;
    const int l8 = lane & 7;
#pragma unroll
    for (int ks = 0; ks < 2; ks++) {
        uint32_t bhf[NTN][2], blf[NTN][2];
#pragma unroll
        for (int nt = 0; nt < NTN; nt++) {
            int rowb = wn * TgCfg<BN>::WN + nt * 8 + l8;
            int kkb  = ks * 16 + (i4 & 1) * 8;
            uint32_t bd = sb + 20480u + (uint32_t)(rowb * 80 + kkb * 2);
            ldsm2(bd, bhf[nt]);
            ldsm2(bd + (uint32_t)TgCfg<BN>::B_ST, blf[nt]);
        }
#pragma unroll
        for (int mt = 0; mt < 4; mt++) {
            uint32_t ahf[4], alf[4];
            int row = wm * 64 + mt * 16 + (i4 & 1) * 8 + l8;
            int kk  = ks * 16 + (i4 >> 1) * 8;
            uint32_t ad = sb + (uint32_t)(row * 80 + kk * 2);
            ldsm4(ad, ahf);
            ldsm4(ad + 10240u, alf);
#pragma unroll
            for (int nt = 0; nt < NTN; nt++) {
                mma16816(acc[mt][nt], ahf, bhf[nt]);
                mma16816(acc[mt][nt], ahf, blf[nt]);
                mma16816(acc[mt][nt], alf, bhf[nt]);
            }
        }
    }
}

template <int EPI, int BN, int AMODE, int BMODE, int CMODE>
__global__ void __launch_bounds__(256, 2) tgemm(
    const __half* __restrict__ Ah, const __half* __restrict__ Al, int lda, long long sA,
    const __half* __restrict__ Bh, const __half* __restrict__ Bl, int ldb, long long sB,
    float* __restrict__ Cf, __half* __restrict__ Ch, __half* __restrict__ Cl,
    int ldc, long long sC, const float* __restrict__ bias, int Kext, float oscale)
{
    constexpr int NTN = TgCfg<BN>::NTN;
    extern __shared__ char smraw[];
    const uint32_t sb0 = smem_u32(smraw);
    const int tid = threadIdx.x;
    const int lane = tid & 31, wid = tid >> 5;
    const int wm = wid & 1, wn = wid >> 1;
    const int z = blockIdx.z;

    long long aoff = (AMODE == MODE_ATT)
        ? ((long long)(z >> 4) * Tn * Dn + (long long)(z & 15) * HSn) : sA * z;
    long long boff = (BMODE == MODE_ATT)
        ? ((long long)(z >> 4) * Tn * Dn + (long long)(z & 15) * HSn) : sB * z;
    long long coff = (CMODE == MODE_ATT)
        ? ((long long)(z >> 4) * Tn * Dn + (long long)(z & 15) * HSn) : sC * z;

    const __half* Ahp = Ah + aoff + (long long)blockIdx.x * 128 * lda;
    const __half* Alp = Al + aoff + (long long)blockIdx.x * 128 * lda;
    const __half* Bhp = Bh + boff + (long long)blockIdx.y * BN * ldb;
    const __half* Blp = Bl + boff + (long long)blockIdx.y * BN * ldb;

    float acc[4][NTN][4];
#pragma unroll
    for (int a = 0; a < 4; a++)
#pragma unroll
        for (int b = 0; b < NTN; b++)
#pragma unroll
            for (int c = 0; c < 4; c++) acc[a][b][c] = 0.f;

    const int NI = Kext >> 5;
    tg_load<BN>(sb0, Ahp, Alp, lda, Bhp, Blp, ldb, 0, tid);
    CP_COMMIT();
    for (int it = 0; it < NI; it++) {
        if (it + 1 < NI) {
            tg_load<BN>(sb0 + (uint32_t)(((it + 1) & 1) * TgCfg<BN>::STAGE),
                        Ahp, Alp, lda, Bhp, Blp, ldb, (it + 1) << 5, tid);
            CP_COMMIT();
            CP_WAIT1();
        } else {
            CP_WAIT0();
        }
        __syncthreads();
        tg_compute<BN>(sb0 + (uint32_t)((it & 1) * TgCfg<BN>::STAGE), wm, wn, lane, acc);
        __syncthreads();
    }

    // epilogue
    const int q = lane >> 2;
    const int cp2 = (lane & 3) * 2;
    const int gc = blockIdx.y * BN + wn * TgCfg<BN>::WN;
#pragma unroll
    for (int mt = 0; mt < 4; mt++) {
#pragma unroll
        for (int nt = 0; nt < NTN; nt++) {
            const float* a = acc[mt][nt];
            int cc = gc + nt * 8 + cp2;
#pragma unroll
            for (int half = 0; half < 2; half++) {
                int rr = blockIdx.x * 128 + wm * 64 + mt * 16 + q + half * 8;
                float v0 = a[half * 2 + 0] * oscale;
                float v1 = a[half * 2 + 1] * oscale;
                long long o = coff + (long long)rr * ldc + cc;
                if (EPI == EPI_BIAS_RESID || EPI == EPI_BIAS_GELU) {
                    v0 += bias[cc]; v1 += bias[cc + 1];
                }
                if (EPI == EPI_F32) {
                    *(float2*)(Cf + o) = make_float2(v0, v1);
                } else if (EPI == EPI_BIAS_RESID) {
                    float2 r = *(float2*)(Cf + o);
                    *(float2*)(Cf + o) = make_float2(v0 + r.x, v1 + r.y);
                } else {  // HILO / BIAS_GELU
                    if (EPI == EPI_BIAS_GELU) { v0 = gelu_exact(v0); v1 = gelu_exact(v1); }
                    __half h0 = __float2half_rn(v0), h1 = __float2half_rn(v1);
                    __half l0 = __float2half_rn(v0 - __half2float(h0));
                    __half l1 = __float2half_rn(v1 - __half2float(h1));
                    *(__half2*)(Ch + o) = __halves2half2(h0, h1);
                    *(__half2*)(Cl + o) = __halves2half2(l0, l1);
                }
            }
        }
    }
}

// ---- softmax over rows of 512, fp32 in -> hi/lo fp16 out ----
__global__ void softmax_kernel(const float* __restrict__ att, __half* __restrict__ ph,
                               __half* __restrict__ pl) {
    long long row = blockIdx.x;
    const float* p = att + row * Tn;
    int tid = threadIdx.x;
    float4 v = ((const float4*)p)[tid];
    float m = fmaxf(fmaxf(v.x, v.y), fmaxf(v.z, v.w));
#pragma unroll
    for (int o = 16; o > 0; o >>= 1) m = fmaxf(m, __shfl_xor_sync(0xffffffffu, m, o));
    __shared__ float shm[4], shs[4];
    int w = tid >> 5;
    if ((tid & 31) == 0) shm[w] = m;
    __syncthreads();
    m = fmaxf(fmaxf(shm[0], shm[1]), fmaxf(shm[2], shm[3]));
    float4 e;
    e.x = expf(v.x - m); e.y = expf(v.y - m);
    e.z = expf(v.z - m); e.w = expf(v.w - m);
    float s = e.x + e.y + e.z + e.w;
    s = warp_sum(s);
    if ((tid & 31) == 0) shs[w] = s;
    __syncthreads();
    float inv = 1.0f / (shs[0] + shs[1] + shs[2] + shs[3]);
    float vv[4] = {e.x * inv, e.y * inv, e.z * inv, e.w * inv};
    __half h[4], l[4];
#pragma unroll
    for (int i = 0; i < 4; i++) {
        h[i] = __float2half_rn(vv[i]);
        l[i] = __float2half_rn(vv[i] - __half2float(h[i]));
    }
    long long o = row * Tn + tid * 4;
    *(__half2*)(ph + o)     = __halves2half2(h[0], h[1]);
    *(__half2*)(ph + o + 2) = __halves2half2(h[2], h[3]);
    *(__half2*)(pl + o)     = __halves2half2(l[0], l[1]);
    *(__half2*)(pl + o + 2) = __halves2half2(l[2], l[3]);
}

// ---- logits ----
__global__ void logits_kernel(const float* __restrict__ hf, const float* __restrict__ Wout,
                              const float* __restrict__ bout, float* __restrict__ out) {
    int b = blockIdx.x;
    const float* hb = hf + (long long)b * Tn * Dn;
    float a[3] = {0.f, 0.f, 0.f};
    for (int i = threadIdx.x; i < Tn * Dn; i += blockDim.x) {
        float v = hb[i];
        const float* wr = Wout + (long long)i * NCn;
        a[0] = fmaf(v, wr[0], a[0]);
        a[1] = fmaf(v, wr[1], a[1]);
        a[2] = fmaf(v, wr[2], a[2]);
    }
    __shared__ float sm[3][16];
    int w = threadIdx.x >> 5, ln = threadIdx.x & 31;
#pragma unroll
    for (int c = 0; c < 3; c++) {
        float v = warp_sum(a[c]);
        if (ln == 0) sm[c][w] = v;
    }
    __syncthreads();
    if (threadIdx.x < 3) {
        float t = 0.f;
#pragma unroll
        for (int i = 0; i < 16; i++) t += sm[threadIdx.x][i];
        out[b * NCn + threadIdx.x] = t + bout[threadIdx.x];
    }
}

}  // namespace enc

extern "C" void kernel_launch(void* const* d_in, const int* in_sizes, int n_in,
                              void* d_out, int out_size) {
    using namespace enc;
    (void)in_sizes; (void)n_in; (void)out_size;

    const int*   x     = (const int*)d_in[0];
    const float* tok   = (const float*)d_in[1];
    const float* pos   = (const float*)d_in[2];
    const float* Wq    = (const float*)d_in[3];
    const float* Wk    = (const float*)d_in[4];
    const float* Wv    = (const float*)d_in[5];
    const float* Wproj = (const float*)d_in[6];
    const float* bproj = (const float*)d_in[7];
    const float* ln1g  = (const float*)d_in[8];
    const float* ln1b  = (const float*)d_in[9];
    const float* ln2g  = (const float*)d_in[10];
    const float* ln2b  = (const float*)d_in[11];
    const float* W1    = (const float*)d_in[12];
    const float* b1    = (const float*)d_in[13];
    const float* W2    = (const float*)d_in[14];
    const float* b2    = (const float*)d_in[15];
    const float* lnfg  = (const float*)d_in[16];
    const float* lnfb  = (const float*)d_in[17];
    const float* Wout  = (const float*)d_in[18];
    const float* bout  = (const float*)d_in[19];
    float* out = (float*)d_out;

    constexpr long long TT = (long long)Tn * Tn;

    static float *ph = nullptr, *pz, *patt;
    static __half *zh, *zl, *qh, *ql, *pph, *ppl, *vth, *vtl, *fh, *fl;
    static __half *wqh, *wql, *wph, *wpl, *w1h, *w1l, *w2h, *w2l;
    if (!ph) {
        cudaGetSymbolAddress((void**)&ph,   g_h);
        cudaGetSymbolAddress((void**)&pz,   g_z);
        cudaGetSymbolAddress((void**)&patt, g_att);
        cudaGetSymbolAddress((void**)&zh, g_zh);
        cudaGetSymbolAddress((void**)&zl, g_zl);
        cudaGetSymbolAddress((void**)&qh, g_qkvh);
        cudaGetSymbolAddress((void**)&ql, g_qkvl);
        cudaGetSymbolAddress((void**)&pph, g_ph);
        cudaGetSymbolAddress((void**)&ppl, g_pl);
        cudaGetSymbolAddress((void**)&vth, g_vth);
        cudaGetSymbolAddress((void**)&vtl, g_vtl);
        cudaGetSymbolAddress((void**)&fh, g_ffnh);
        cudaGetSymbolAddress((void**)&fl, g_ffnl);
        cudaGetSymbolAddress((void**)&wqh, g_wqkv_h);
        cudaGetSymbolAddress((void**)&wql, g_wqkv_l);
        cudaGetSymbolAddress((void**)&wph, g_wproj_h);
        cudaGetSymbolAddress((void**)&wpl, g_wproj_l);
        cudaGetSymbolAddress((void**)&w1h, g_w1_h);
        cudaGetSymbolAddress((void**)&w1l, g_w1_l);
        cudaGetSymbolAddress((void**)&w2h, g_w2_h);
        cudaGetSymbolAddress((void**)&w2l, g_w2_l);
        cudaFuncSetAttribute((const void*)tgemm<EPI_HILO, 128, MODE_LIN, MODE_LIN, MODE_LIN>,
                             cudaFuncAttributeMaxDynamicSharedMemorySize, TgCfg<128>::SMEM);
        cudaFuncSetAttribute((const void*)tgemm<EPI_F32, 128, MODE_ATT, MODE_ATT, MODE_LIN>,
                             cudaFuncAttributeMaxDynamicSharedMemorySize, TgCfg<128>::SMEM);
        cudaFuncSetAttribute((const void*)tgemm<EPI_HILO, 64, MODE_LIN, MODE_LIN, MODE_ATT>,
                             cudaFuncAttributeMaxDynamicSharedMemorySize, TgCfg<64>::SMEM);
        cudaFuncSetAttribute((const void*)tgemm<EPI_BIAS_RESID, 128, MODE_LIN, MODE_LIN, MODE_LIN>,
                             cudaFuncAttributeMaxDynamicSharedMemorySize, TgCfg<128>::SMEM);
        cudaFuncSetAttribute((const void*)tgemm<EPI_BIAS_GELU, 128, MODE_LIN, MODE_LIN, MODE_LIN>,
                             cudaFuncAttributeMaxDynamicSharedMemorySize, TgCfg<128>::SMEM);
    }

    // ---- prep ----
    embed_kernel<<<(BTn * Dn / 4 + 255) / 256, 256>>>(x, tok, pos);
    wprep_qkv<<<dim3(Dn / 32, HSn / 32, Ln * 3 * Hn), dim3(32, 8)>>>(Wq, Wk, Wv);
    wprep_lin<<<dim3(Dn / 32, Dn / 32, Ln),   dim3(32, 8)>>>(Wproj, wph, wpl, Dn, Dn);
    wprep_lin<<<dim3(Dn / 32, DFFn / 32, Ln), dim3(32, 8)>>>(W1, w1h, w1l, Dn, DFFn);
    wprep_lin<<<dim3(DFFn / 32, Dn / 32, Ln), dim3(32, 8)>>>(W2, w2h, w2l, DFFn, Dn);

    for (int l = 0; l < Ln; l++) {
        // z = LN1(h) -> hi/lo
        ln_kernel<true><<<BTn, 256>>>(ph, ln1g + l * Dn, ln1b + l * Dn, nullptr, zh, zl);
        // q,k,v = z @ W -> hi/lo fp16 directly
        tgemm<EPI_HILO, 128, MODE_LIN, MODE_LIN, MODE_LIN>
            <<<dim3(BTn / 128, Dn / 128, 3), 256, TgCfg<128>::SMEM>>>(
                zh, zl, Dn, 0LL,
                wqh + (long long)l * 3 * Dn * Dn, wql + (long long)l * 3 * Dn * Dn, Dn,
                (long long)Dn * Dn,
                nullptr, qh, ql, Dn, (long long)BTn * Dn, nullptr, Dn, INV_WSCALE);
        // V^T hi/lo
        vtrans_kernel<<<dim3(Tn / 32, HSn / 32, Bn * Hn), dim3(32, 8)>>>(
            qh + 2LL * BTn * Dn, ql + 2LL * BTn * Dn, vth, vtl);
        // scores = 0.125 * Q K^T (tensor)
        tgemm<EPI_F32, 128, MODE_ATT, MODE_ATT, MODE_LIN>
            <<<dim3(Tn / 128, Tn / 128, Bn * Hn), 256, TgCfg<128>::SMEM>>>(
                qh, ql, Dn, 0LL,
                qh + (long long)BTn * Dn, ql + (long long)BTn * Dn, Dn, 0LL,
                patt, nullptr, nullptr, Tn, TT, nullptr, HSn, 0.125f);
        // softmax -> P hi/lo
        softmax_kernel<<<Bn * Hn * Tn, 128>>>(patt, pph, ppl);
        // o = P V (tensor) -> zh/zl in [BT, H*HS] layout
        tgemm<EPI_HILO, 64, MODE_LIN, MODE_LIN, MODE_ATT>
            <<<dim3(Tn / 128, 1, Bn * Hn), 256, TgCfg<64>::SMEM>>>(
                pph, ppl, Tn, TT,
                vth, vtl, Tn, (long long)HSn * Tn,
                nullptr, zh, zl, Dn, 0LL, nullptr, Tn, 1.0f);
        // h += o @ Wproj + bproj
        tgemm<EPI_BIAS_RESID, 128, MODE_LIN, MODE_LIN, MODE_LIN>
            <<<dim3(BTn / 128, Dn / 128, 1), 256, TgCfg<128>::SMEM>>>(
                zh, zl, Dn, 0LL,
                wph + (long long)l * Dn * Dn, wpl + (long long)l * Dn * Dn, Dn, 0LL,
                ph, nullptr, nullptr, Dn, 0LL, bproj + l * Dn, Dn, INV_WSCALE);
        // z = LN2(h) -> hi/lo
        ln_kernel<true><<<BTn, 256>>>(ph, ln2g + l * Dn, ln2b + l * Dn, nullptr, zh, zl);
        // ffn = gelu(z @ W1 + b1) -> hi/lo
        tgemm<EPI_BIAS_GELU, 128, MODE_LIN, MODE_LIN, MODE_LIN>
            <<<dim3(BTn / 128, DFFn / 128, 1), 256, TgCfg<128>::SMEM>>>(
                zh, zl, Dn, 0LL,
                w1h + (long long)l * Dn * DFFn, w1l + (long long)l * Dn * DFFn, Dn, 0LL,
                nullptr, fh, fl, DFFn, 0LL, b1 + l * DFFn, Dn, INV_WSCALE);
        // h += ffn @ W2 + b2
        tgemm<EPI_BIAS_RESID, 128, MODE_LIN, MODE_LIN, MODE_LIN>
            <<<dim3(BTn / 128, Dn / 128, 1), 256, TgCfg<128>::SMEM>>>(
                fh, fl, DFFn, 0LL,
                w2h + (long long)l * DFFn * Dn, w2l + (long long)l * DFFn * Dn, DFFn, 0LL,
                ph, nullptr, nullptr, Dn, 0LL, b2 + l * Dn, DFFn, INV_WSCALE);
    }
    ln_kernel<false><<<BTn, 256>>>(ph, lnfg, lnfb, pz, nullptr, nullptr);
    logits_kernel<<<Bn, 512>>>(pz, Wout, bout, out);
}

// round 8
// speedup vs baseline: 2.8777x; 1.1922x over previous
#include <cuda_runtime.h>
#include <cuda_fp16.h>
#include <cuda_bf16.h>
#include <math.h>
#include <stdint.h>

#define DI __device__ __forceinline__

// ===================== portable PTX helpers (plain sm_103) =====================
DI uint32_t smem_u32(const void* p) {
    uint32_t a;
    asm("{ .reg .u64 t; cvta.to.shared.u64 t, %1; cvt.u32.u64 %0, t; }" : "=r"(a) : "l"(p));
    return a;
}
DI void cp16(uint32_t d, const void* s) {
    asm volatile("cp.async.cg.shared.global [%0], [%1], 16;" :: "r"(d), "l"(s) : "memory");
}
#define CP_COMMIT() asm volatile("cp.async.commit_group;" ::: "memory")
#define CP_WAIT1()  asm volatile("cp.async.wait_group 1;" ::: "memory")
#define CP_WAIT0()  asm volatile("cp.async.wait_group 0;" ::: "memory")

DI void ldsm4(uint32_t addr, uint32_t* r) {
    asm volatile("ldmatrix.sync.aligned.m8n8.x4.shared.b16 {%0,%1,%2,%3}, [%4];"
                 : "=r"(r[0]), "=r"(r[1]), "=r"(r[2]), "=r"(r[3]) : "r"(addr));
}
DI void ldsm2(uint32_t addr, uint32_t* r) {
    asm volatile("ldmatrix.sync.aligned.m8n8.x2.shared.b16 {%0,%1}, [%2];"
                 : "=r"(r[0]), "=r"(r[1]) : "r"(addr));
}
DI void mma16816(float* c, const uint32_t* a, const uint32_t* b) {
    asm volatile("mma.sync.aligned.m16n8k16.row.col.f32.f16.f16.f32 "
                 "{%0,%1,%2,%3},{%4,%5,%6,%7},{%8,%9},{%0,%1,%2,%3};"
                 : "+f"(c[0]), "+f"(c[1]), "+f"(c[2]), "+f"(c[3])
                 : "r"(a[0]), "r"(a[1]), "r"(a[2]), "r"(a[3]), "r"(b[0]), "r"(b[1]));
}

namespace enc {

constexpr int Bn = 16, Tn = 512, Dn = 1024, Hn = 16, HSn = 64, Ln = 4, DFFn = 4096, NCn = 3;
constexpr int BTn = Bn * Tn;  // 8192
constexpr float WSCALE = 64.0f;
constexpr float INV_WSCALE = 1.0f / 64.0f;

// ---- scratch ----
__device__ __align__(16) float g_h  [(size_t)BTn * Dn];
__device__ __align__(16) float g_z  [(size_t)BTn * Dn];
__device__ __align__(16) float g_att[(size_t)Bn * Hn * Tn * Tn];
__device__ __align__(16) float g_lpart[Bn * 16 * NCn];
// activations hi/lo fp16
__device__ __align__(16) __half g_zh  [(size_t)BTn * Dn];
__device__ __align__(16) __half g_zl  [(size_t)BTn * Dn];
__device__ __align__(16) __half g_qkvh[(size_t)3 * BTn * Dn];
__device__ __align__(16) __half g_qkvl[(size_t)3 * BTn * Dn];
__device__ __align__(16) __half g_ph  [(size_t)Bn * Hn * Tn * Tn];
__device__ __align__(16) __half g_pl  [(size_t)Bn * Hn * Tn * Tn];
__device__ __align__(16) __half g_vth [(size_t)BTn * Dn];
__device__ __align__(16) __half g_vtl [(size_t)BTn * Dn];
__device__ __align__(16) __half g_ffnh[(size_t)BTn * DFFn];
__device__ __align__(16) __half g_ffnl[(size_t)BTn * DFFn];
// fp16 hi/lo weights, [N,K] layout, scaled by 64
__device__ __align__(16) __half g_wqkv_h[(size_t)Ln * 3 * Dn * Dn];
__device__ __align__(16) __half g_wqkv_l[(size_t)Ln * 3 * Dn * Dn];
__device__ __align__(16) __half g_wproj_h[(size_t)Ln * Dn * Dn];
__device__ __align__(16) __half g_wproj_l[(size_t)Ln * Dn * Dn];
__device__ __align__(16) __half g_w1_h[(size_t)Ln * Dn * DFFn];
__device__ __align__(16) __half g_w1_l[(size_t)Ln * Dn * DFFn];
__device__ __align__(16) __half g_w2_h[(size_t)Ln * DFFn * Dn];
__device__ __align__(16) __half g_w2_l[(size_t)Ln * DFFn * Dn];

DI float warp_sum(float v) {
#pragma unroll
    for (int o = 16; o > 0; o >>= 1) v += __shfl_xor_sync(0xffffffffu, v, o);
    return v;
}
DI float gelu_exact(float x) {
    return 0.5f * x * (1.0f + erff(x * 0.70710678118654752440f));
}

// ---- layernorm; EMB fuses the embedding gather; HILO writes split fp16 ----
template <bool HILO, bool EMB>
__global__ void ln_kernel(const float* __restrict__ in, const float* __restrict__ gw,
                          const float* __restrict__ bw, float* __restrict__ outf,
                          __half* __restrict__ oh, __half* __restrict__ ol,
                          const int* __restrict__ xi, const float* __restrict__ tok,
                          const float* __restrict__ pos) {
    long long row = blockIdx.x;
    int tid = threadIdx.x;
    float4 x4;
    if (EMB) {
        int t = (int)(row & (Tn - 1));
        int tk = xi[row];
        float4 a = *(const float4*)(tok + (long long)tk * Dn + tid * 4);
        float4 p = *(const float4*)(pos + (long long)t * Dn + tid * 4);
        x4.x = a.x + p.x; x4.y = a.y + p.y; x4.z = a.z + p.z; x4.w = a.w + p.w;
        *(float4*)(g_h + row * Dn + tid * 4) = x4;   // residual stream
    } else {
        x4 = *(const float4*)(in + row * Dn + tid * 4);
    }
    float s  = x4.x + x4.y + x4.z + x4.w;
    float s2 = x4.x * x4.x + x4.y * x4.y + x4.z * x4.z + x4.w * x4.w;
    s = warp_sum(s); s2 = warp_sum(s2);
    __shared__ float sh[2][8];
    int w = tid >> 5;
    if ((tid & 31) == 0) { sh[0][w] = s; sh[1][w] = s2; }
    __syncthreads();
    float ts = 0.f, ts2 = 0.f;
#pragma unroll
    for (int i = 0; i < 8; i++) { ts += sh[0][i]; ts2 += sh[1][i]; }
    float mu = ts * (1.0f / Dn);
    float var = ts2 * (1.0f / Dn) - mu * mu;
    float rinv = rsqrtf(var + 1e-5f);
    float4 g4 = *(const float4*)(gw + tid * 4);
    float4 b4 = *(const float4*)(bw + tid * 4);
    float v[4];
    v[0] = (x4.x - mu) * rinv * g4.x + b4.x;
    v[1] = (x4.y - mu) * rinv * g4.y + b4.y;
    v[2] = (x4.z - mu) * rinv * g4.z + b4.z;
    v[3] = (x4.w - mu) * rinv * g4.w + b4.w;
    if (HILO) {
        __half h[4], l[4];
#pragma unroll
        for (int i = 0; i < 4; i++) {
            h[i] = __float2half_rn(v[i]);
            l[i] = __float2half_rn(v[i] - __half2float(h[i]));
        }
        long long o = row * Dn + tid * 4;
        *(__half2*)(oh + o)     = __halves2half2(h[0], h[1]);
        *(__half2*)(oh + o + 2) = __halves2half2(h[2], h[3]);
        *(__half2*)(ol + o)     = __halves2half2(l[0], l[1]);
        *(__half2*)(ol + o + 2) = __halves2half2(l[2], l[3]);
    } else {
        *(float4*)(outf + row * Dn + tid * 4) = make_float4(v[0], v[1], v[2], v[3]);
    }
}

// ---- weight prep: transpose [K,N] -> hi/lo fp16 [N,K], scale by 64 ----
__global__ void wprep_lin(const float* __restrict__ src, __half* __restrict__ dh,
                          __half* __restrict__ dl, int K, int N) {
    int l = blockIdx.z;
    src += (long long)l * K * N;
    dh += (long long)l * N * K;
    dl += (long long)l * N * K;
    __shared__ float t[32][33];
    int k0 = blockIdx.x * 32, n0 = blockIdx.y * 32;
    int tx = threadIdx.x, ty = threadIdx.y;
#pragma unroll
    for (int j = 0; j < 4; j++)
        t[ty + 8 * j][tx] = src[(long long)(k0 + ty + 8 * j) * N + n0 + tx];
    __syncthreads();
#pragma unroll
    for (int j = 0; j < 4; j++) {
        float v = t[tx][ty + 8 * j] * WSCALE;
        __half h = __float2half_rn(v);
        __half lo = __float2half_rn(v - __half2float(h));
        long long o = (long long)(n0 + ty + 8 * j) * K + k0 + tx;
        dh[o] = h; dl[o] = lo;
    }
}

// ---- qkv weight prep: [L,H,D,HS] -> [N=H*HS, K=D] hi/lo ----
__global__ void wprep_qkv(const float* __restrict__ Wq, const float* __restrict__ Wk,
                          const float* __restrict__ Wv) {
    int z = blockIdx.z;
    int h = z & 15, which = (z >> 4) % 3, l = z / 48;
    const float* W = which == 0 ? Wq : (which == 1 ? Wk : Wv);
    const float* src = W + ((long long)(l * Hn + h) * Dn) * HSn;
    long long base = ((long long)(l * 3 + which)) * Dn * Dn;
    __shared__ float t[32][33];
    int k0 = blockIdx.x * 32, n0 = blockIdx.y * 32;
    int tx = threadIdx.x, ty = threadIdx.y;
#pragma unroll
    for (int j = 0; j < 4; j++)
        t[ty + 8 * j][tx] = src[(long long)(k0 + ty + 8 * j) * HSn + n0 + tx];
    __syncthreads();
#pragma unroll
    for (int j = 0; j < 4; j++) {
        float v = t[tx][ty + 8 * j] * WSCALE;
        __half h2 = __float2half_rn(v);
        __half lo = __float2half_rn(v - __half2float(h2));
        long long o = base + (long long)(h * HSn + n0 + ty + 8 * j) * Dn + k0 + tx;
        g_wqkv_h[o] = h2; g_wqkv_l[o] = lo;
    }
}

// ---- V transpose: [b*T+t, h*64+e] fp16 hi/lo -> [bh, e, t] ----
__global__ void vtrans_kernel(const __half* __restrict__ vh, const __half* __restrict__ vl,
                              __half* __restrict__ oth, __half* __restrict__ otl) {
    int bh = blockIdx.z, b = bh >> 4, h = bh & 15;
    int t0 = blockIdx.x * 32, e0 = blockIdx.y * 32;
    __shared__ __half sh[32][34], sl[32][34];
    int tx = threadIdx.x, ty = threadIdx.y;
#pragma unroll
    for (int j = 0; j < 4; j++) {
        long long gi = ((long long)(b * Tn + t0 + ty + 8 * j)) * Dn + h * HSn + e0 + tx;
        sh[ty + 8 * j][tx] = vh[gi];
        sl[ty + 8 * j][tx] = vl[gi];
    }
    __syncthreads();
#pragma unroll
    for (int j = 0; j < 4; j++) {
        long long go = ((long long)bh * HSn + e0 + ty + 8 * j) * Tn + t0 + tx;
        oth[go] = sh[tx][ty + 8 * j];
        otl[go] = sl[tx][ty + 8 * j];
    }
}

// ===================== mma.sync fp16-split GEMM =====================
enum { EPI_F32 = 0, EPI_HILO = 1, EPI_BIAS_RESID = 2, EPI_BIAS_GELU = 3 };
enum { MODE_LIN = 0, MODE_ATT = 1 };

// 64B rows + chunk swizzle c' = c ^ ((r>>1)&3); stage: Ah | Al | Bh | Bl
template <int BN> struct TgCfg {
    static constexpr int A_B = 128 * 64;                 // 8192
    static constexpr int B_B = BN * 64;
    static constexpr int STAGE = 2 * A_B + 2 * B_B;
    static constexpr int SMEM = 3 * STAGE;
    static constexpr int WN = BN / 4;
    static constexpr int NTN = WN / 8;
};

DI uint32_t swz_addr(uint32_t base, int r, int ch) {
    return base + (uint32_t)(r * 64 + ((ch ^ ((r >> 1) & 3)) << 4));
}

template <int BN>
DI void tg_load(uint32_t sd, const __half* __restrict__ Ahp, const __half* __restrict__ Alp,
                int lda, const __half* __restrict__ Bhp, const __half* __restrict__ Blp,
                int ldb, int k0, int tid) {
#pragma unroll
    for (int j = 0; j < 2; j++) {
        int cid = tid + j * 256;
        int r = cid >> 2;
        int ch = cid & 3;
        uint32_t d = swz_addr(sd, r, ch);
        long long go = (long long)r * lda + k0 + ch * 8;
        cp16(d, Ahp + go);
        cp16(d + (uint32_t)TgCfg<BN>::A_B, Alp + go);
    }
#pragma unroll
    for (int j = 0; j < BN / 64; j++) {
        int cid = tid + j * 256;
        int r = cid >> 2;
        int ch = cid & 3;
        uint32_t d = swz_addr(sd + 2u * TgCfg<BN>::A_B, r, ch);
        long long go = (long long)r * ldb + k0 + ch * 8;
        cp16(d, Bhp + go);
        cp16(d + (uint32_t)TgCfg<BN>::B_B, Blp + go);
    }
}

// register-lean compute with swizzled ldmatrix addressing
template <int BN>
DI void tg_compute(uint32_t sb, int wm, int wn, int lane, float acc[4][TgCfg<BN>::NTN][4]) {
    constexpr int NTN = TgCfg<BN>::NTN;
    const uint32_t sbB = sb + 2u * TgCfg<BN>::A_B;
    const int i4 = lane >> 3;
    const int l8 = lane & 7;
#pragma unroll
    for (int ks = 0; ks < 2; ks++) {
        uint32_t bhf[NTN][2], blf[NTN][2];
#pragma unroll
        for (int nt = 0; nt < NTN; nt++) {
            int rowb = wn * TgCfg<BN>::WN + nt * 8 + l8;
            int chb  = ks * 2 + (i4 & 1);
            uint32_t bd = swz_addr(sbB, rowb, chb);
            ldsm2(bd, bhf[nt]);
            ldsm2(bd + (uint32_t)TgCfg<BN>::B_B, blf[nt]);
        }
#pragma unroll
        for (int mt = 0; mt < 4; mt++) {
            uint32_t ahf[4], alf[4];
            int row = wm * 64 + mt * 16 + (i4 & 1) * 8 + l8;
            int cha = ks * 2 + (i4 >> 1);
            uint32_t ad = swz_addr(sb, row, cha);
            ldsm4(ad, ahf);
            ldsm4(ad + (uint32_t)TgCfg<BN>::A_B, alf);
#pragma unroll
            for (int nt = 0; nt < NTN; nt++) {
                mma16816(acc[mt][nt], ahf, bhf[nt]);
                mma16816(acc[mt][nt], ahf, blf[nt]);
                mma16816(acc[mt][nt], alf, bhf[nt]);
            }
        }
    }
}

template <int EPI, int BN, int AMODE, int BMODE, int CMODE>
__global__ void __launch_bounds__(256, 2) tgemm(
    const __half* __restrict__ Ah, const __half* __restrict__ Al, int lda, long long sA,
    const __half* __restrict__ Bh, const __half* __restrict__ Bl, int ldb, long long sB,
    float* __restrict__ Cf, __half* __restrict__ Ch, __half* __restrict__ Cl,
    int ldc, long long sC, const float* __restrict__ bias, int Kext, float oscale)
{
    constexpr int NTN = TgCfg<BN>::NTN;
    constexpr uint32_t STG = (uint32_t)TgCfg<BN>::STAGE;
    extern __shared__ char smraw[];
    const uint32_t sb0 = smem_u32(smraw);
    const int tid = threadIdx.x;
    const int lane = tid & 31, wid = tid >> 5;
    const int wm = wid & 1, wn = wid >> 1;
    const int z = blockIdx.z;

    long long aoff = (AMODE == MODE_ATT)
        ? ((long long)(z >> 4) * Tn * Dn + (long long)(z & 15) * HSn) : sA * z;
    long long boff = (BMODE == MODE_ATT)
        ? ((long long)(z >> 4) * Tn * Dn + (long long)(z & 15) * HSn) : sB * z;
    long long coff = (CMODE == MODE_ATT)
        ? ((long long)(z >> 4) * Tn * Dn + (long long)(z & 15) * HSn) : sC * z;

    const __half* Ahp = Ah + aoff + (long long)blockIdx.x * 128 * lda;
    const __half* Alp = Al + aoff + (long long)blockIdx.x * 128 * lda;
    const __half* Bhp = Bh + boff + (long long)blockIdx.y * BN * ldb;
    const __half* Blp = Bl + boff + (long long)blockIdx.y * BN * ldb;

    float acc[4][NTN][4];
#pragma unroll
    for (int a = 0; a < 4; a++)
#pragma unroll
        for (int b = 0; b < NTN; b++)
#pragma unroll
            for (int c = 0; c < 4; c++) acc[a][b][c] = 0.f;

    const int NI = Kext >> 5;
    // prologue: stages 0,1
    tg_load<BN>(sb0, Ahp, Alp, lda, Bhp, Blp, ldb, 0, tid);
    CP_COMMIT();
    if (NI > 1) {
        tg_load<BN>(sb0 + STG, Ahp, Alp, lda, Bhp, Blp, ldb, 32, tid);
        CP_COMMIT();
    }
    int sidx = 0;                 // stage index of current iter (mod 3)
    for (int it = 0; it < NI; it++) {
        if (it < NI - 1) CP_WAIT1(); else CP_WAIT0();
        __syncthreads();
        if (it + 2 < NI) {
            int ns = sidx + 2; if (ns >= 3) ns -= 3;
            tg_load<BN>(sb0 + (uint32_t)ns * STG, Ahp, Alp, lda, Bhp, Blp, ldb,
                        (it + 2) << 5, tid);
            CP_COMMIT();
        }
        tg_compute<BN>(sb0 + (uint32_t)sidx * STG, wm, wn, lane, acc);
        if (++sidx == 3) sidx = 0;
    }

    // epilogue
    const int q = lane >> 2;
    const int cp2 = (lane & 3) * 2;
    const int gc = blockIdx.y * BN + wn * TgCfg<BN>::WN;
#pragma unroll
    for (int mt = 0; mt < 4; mt++) {
#pragma unroll
        for (int nt = 0; nt < NTN; nt++) {
            const float* a = acc[mt][nt];
            int cc = gc + nt * 8 + cp2;
#pragma unroll
            for (int half = 0; half < 2; half++) {
                int rr = blockIdx.x * 128 + wm * 64 + mt * 16 + q + half * 8;
                float v0 = a[half * 2 + 0] * oscale;
                float v1 = a[half * 2 + 1] * oscale;
                long long o = coff + (long long)rr * ldc + cc;
                if (EPI == EPI_BIAS_RESID || EPI == EPI_BIAS_GELU) {
                    v0 += bias[cc]; v1 += bias[cc + 1];
                }
                if (EPI == EPI_F32) {
                    *(float2*)(Cf + o) = make_float2(v0, v1);
                } else if (EPI == EPI_BIAS_RESID) {
                    float2 r = *(float2*)(Cf + o);
                    *(float2*)(Cf + o) = make_float2(v0 + r.x, v1 + r.y);
                } else {  // HILO / BIAS_GELU
                    if (EPI == EPI_BIAS_GELU) { v0 = gelu_exact(v0); v1 = gelu_exact(v1); }
                    __half h0 = __float2half_rn(v0), h1 = __float2half_rn(v1);
                    __half l0 = __float2half_rn(v0 - __half2float(h0));
                    __half l1 = __float2half_rn(v1 - __half2float(h1));
                    *(__half2*)(Ch + o) = __halves2half2(h0, h1);
                    *(__half2*)(Cl + o) = __halves2half2(l0, l1);
                }
            }
        }
    }
}

// ---- softmax over rows of 512, fp32 in -> hi/lo fp16 out ----
__global__ void softmax_kernel(const float* __restrict__ att, __half* __restrict__ ph,
                               __half* __restrict__ pl) {
    long long row = blockIdx.x;
    const float* p = att + row * Tn;
    int tid = threadIdx.x;
    float4 v = ((const float4*)p)[tid];
    float m = fmaxf(fmaxf(v.x, v.y), fmaxf(v.z, v.w));
#pragma unroll
    for (int o = 16; o > 0; o >>= 1) m = fmaxf(m, __shfl_xor_sync(0xffffffffu, m, o));
    __shared__ float shm[4], shs[4];
    int w = tid >> 5;
    if ((tid & 31) == 0) shm[w] = m;
    __syncthreads();
    m = fmaxf(fmaxf(shm[0], shm[1]), fmaxf(shm[2], shm[3]));
    float4 e;
    e.x = expf(v.x - m); e.y = expf(v.y - m);
    e.z = expf(v.z - m); e.w = expf(v.w - m);
    float s = e.x + e.y + e.z + e.w;
    s = warp_sum(s);
    if ((tid & 31) == 0) shs[w] = s;
    __syncthreads();
    float inv = 1.0f / (shs[0] + shs[1] + shs[2] + shs[3]);
    float vv[4] = {e.x * inv, e.y * inv, e.z * inv, e.w * inv};
    __half h[4], l[4];
#pragma unroll
    for (int i = 0; i < 4; i++) {
        h[i] = __float2half_rn(vv[i]);
        l[i] = __float2half_rn(vv[i] - __half2float(h[i]));
    }
    long long o = row * Tn + tid * 4;
    *(__half2*)(ph + o)     = __halves2half2(h[0], h[1]);
    *(__half2*)(ph + o + 2) = __halves2half2(h[2], h[3]);
    *(__half2*)(pl + o)     = __halves2half2(l[0], l[1]);
    *(__half2*)(pl + o + 2) = __halves2half2(l[2], l[3]);
}

// ---- logits: 2-stage deterministic reduction ----
__global__ void logits_part(const float* __restrict__ hf, const float* __restrict__ Wout) {
    int b = blockIdx.x, c = blockIdx.y;
    const int CHUNK = Tn * Dn / 16;  // 32768
    const float* hb = hf + (long long)b * Tn * Dn + c * CHUNK;
    const float* wb = Wout + ((long long)c * CHUNK) * NCn;
    float a[3] = {0.f, 0.f, 0.f};
    for (int i = threadIdx.x; i < CHUNK; i += blockDim.x) {
        float v = hb[i];
        const float* wr = wb + (long long)i * NCn;
        a[0] = fmaf(v, wr[0], a[0]);
        a[1] = fmaf(v, wr[1], a[1]);
        a[2] = fmaf(v, wr[2], a[2]);
    }
    __shared__ float sm[3][8];
    int w = threadIdx.x >> 5, ln = threadIdx.x & 31;
#pragma unroll
    for (int cc = 0; cc < 3; cc++) {
        float v = warp_sum(a[cc]);
        if (ln == 0) sm[cc][w] = v;
    }
    __syncthreads();
    if (threadIdx.x < 3) {
        float t = 0.f;
#pragma unroll
        for (int i = 0; i < 8; i++) t += sm[threadIdx.x][i];
        g_lpart[(b * 16 + c) * NCn + threadIdx.x] = t;
    }
}
__global__ void logits_final(const float* __restrict__ bout, float* __restrict__ out) {
    int t = threadIdx.x;
    if (t >= Bn * NCn) return;
    int b = t / NCn, c = t % NCn;
    float s = bout[c];
#pragma unroll
    for (int i = 0; i < 16; i++) s += g_lpart[(b * 16 + i) * NCn + c];
    out[b * NCn + c] = s;
}

}  // namespace enc

extern "C" void kernel_launch(void* const* d_in, const int* in_sizes, int n_in,
                              void* d_out, int out_size) {
    using namespace enc;
    (void)in_sizes; (void)n_in; (void)out_size;

    const int*   x     = (const int*)d_in[0];
    const float* tok   = (const float*)d_in[1];
    const float* pos   = (const float*)d_in[2];
    const float* Wq    = (const float*)d_in[3];
    const float* Wk    = (const float*)d_in[4];
    const float* Wv    = (const float*)d_in[5];
    const float* Wproj = (const float*)d_in[6];
    const float* bproj = (const float*)d_in[7];
    const float* ln1g  = (const float*)d_in[8];
    const float* ln1b  = (const float*)d_in[9];
    const float* ln2g  = (const float*)d_in[10];
    const float* ln2b  = (const float*)d_in[11];
    const float* W1    = (const float*)d_in[12];
    const float* b1    = (const float*)d_in[13];
    const float* W2    = (const float*)d_in[14];
    const float* b2    = (const float*)d_in[15];
    const float* lnfg  = (const float*)d_in[16];
    const float* lnfb  = (const float*)d_in[17];
    const float* Wout  = (const float*)d_in[18];
    const float* bout  = (const float*)d_in[19];
    float* out = (float*)d_out;

    constexpr long long TT = (long long)Tn * Tn;

    static float *ph = nullptr, *pz, *patt;
    static __half *zh, *zl, *qh, *ql, *pph, *ppl, *vth, *vtl, *fh, *fl;
    static __half *wqh, *wql, *wph, *wpl, *w1h, *w1l, *w2h, *w2l;
    if (!ph) {
        cudaGetSymbolAddress((void**)&ph,   g_h);
        cudaGetSymbolAddress((void**)&pz,   g_z);
        cudaGetSymbolAddress((void**)&patt, g_att);
        cudaGetSymbolAddress((void**)&zh, g_zh);
        cudaGetSymbolAddress((void**)&zl, g_zl);
        cudaGetSymbolAddress((void**)&qh, g_qkvh);
        cudaGetSymbolAddress((void**)&ql, g_qkvl);
        cudaGetSymbolAddress((void**)&pph, g_ph);
        cudaGetSymbolAddress((void**)&ppl, g_pl);
        cudaGetSymbolAddress((void**)&vth, g_vth);
        cudaGetSymbolAddress((void**)&vtl, g_vtl);
        cudaGetSymbolAddress((void**)&fh, g_ffnh);
        cudaGetSymbolAddress((void**)&fl, g_ffnl);
        cudaGetSymbolAddress((void**)&wqh, g_wqkv_h);
        cudaGetSymbolAddress((void**)&wql, g_wqkv_l);
        cudaGetSymbolAddress((void**)&wph, g_wproj_h);
        cudaGetSymbolAddress((void**)&wpl, g_wproj_l);
        cudaGetSymbolAddress((void**)&w1h, g_w1_h);
        cudaGetSymbolAddress((void**)&w1l, g_w1_l);
        cudaGetSymbolAddress((void**)&w2h, g_w2_h);
        cudaGetSymbolAddress((void**)&w2l, g_w2_l);
        cudaFuncSetAttribute((const void*)tgemm<EPI_HILO, 128, MODE_LIN, MODE_LIN, MODE_LIN>,
                             cudaFuncAttributeMaxDynamicSharedMemorySize, TgCfg<128>::SMEM);
        cudaFuncSetAttribute((const void*)tgemm<EPI_F32, 128, MODE_ATT, MODE_ATT, MODE_LIN>,
                             cudaFuncAttributeMaxDynamicSharedMemorySize, TgCfg<128>::SMEM);
        cudaFuncSetAttribute((const void*)tgemm<EPI_HILO, 64, MODE_LIN, MODE_LIN, MODE_ATT>,
                             cudaFuncAttributeMaxDynamicSharedMemorySize, TgCfg<64>::SMEM);
        cudaFuncSetAttribute((const void*)tgemm<EPI_BIAS_RESID, 128, MODE_LIN, MODE_LIN, MODE_LIN>,
                             cudaFuncAttributeMaxDynamicSharedMemorySize, TgCfg<128>::SMEM);
        cudaFuncSetAttribute((const void*)tgemm<EPI_BIAS_GELU, 128, MODE_LIN, MODE_LIN, MODE_LIN>,
                             cudaFuncAttributeMaxDynamicSharedMemorySize, TgCfg<128>::SMEM);
    }

    // ---- prep (weights first so ncu -s lands on tgemm) ----
    wprep_qkv<<<dim3(Dn / 32, HSn / 32, Ln * 3 * Hn), dim3(32, 8)>>>(Wq, Wk, Wv);
    wprep_lin<<<dim3(Dn / 32, Dn / 32, Ln),   dim3(32, 8)>>>(Wproj, wph, wpl, Dn, Dn);
    wprep_lin<<<dim3(Dn / 32, DFFn / 32, Ln), dim3(32, 8)>>>(W1, w1h, w1l, Dn, DFFn);
    wprep_lin<<<dim3(DFFn / 32, Dn / 32, Ln), dim3(32, 8)>>>(W2, w2h, w2l, DFFn, Dn);

    for (int l = 0; l < Ln; l++) {
        // z = LN1(h) -> hi/lo (layer 0 fuses the embedding gather)
        if (l == 0)
            ln_kernel<true, true><<<BTn, 256>>>(nullptr, ln1g, ln1b, nullptr, zh, zl,
                                                x, tok, pos);
        else
            ln_kernel<true, false><<<BTn, 256>>>(ph, ln1g + l * Dn, ln1b + l * Dn,
                                                 nullptr, zh, zl, nullptr, nullptr, nullptr);
        // q,k,v = z @ W -> hi/lo fp16 directly
        tgemm<EPI_HILO, 128, MODE_LIN, MODE_LIN, MODE_LIN>
            <<<dim3(BTn / 128, Dn / 128, 3), 256, TgCfg<128>::SMEM>>>(
                zh, zl, Dn, 0LL,
                wqh + (long long)l * 3 * Dn * Dn, wql + (long long)l * 3 * Dn * Dn, Dn,
                (long long)Dn * Dn,
                nullptr, qh, ql, Dn, (long long)BTn * Dn, nullptr, Dn, INV_WSCALE);
        // V^T hi/lo
        vtrans_kernel<<<dim3(Tn / 32, HSn / 32, Bn * Hn), dim3(32, 8)>>>(
            qh + 2LL * BTn * Dn, ql + 2LL * BTn * Dn, vth, vtl);
        // scores = 0.125 * Q K^T (tensor)
        tgemm<EPI_F32, 128, MODE_ATT, MODE_ATT, MODE_LIN>
            <<<dim3(Tn / 128, Tn / 128, Bn * Hn), 256, TgCfg<128>::SMEM>>>(
                qh, ql, Dn, 0LL,
                qh + (long long)BTn * Dn, ql + (long long)BTn * Dn, Dn, 0LL,
                patt, nullptr, nullptr, Tn, TT, nullptr, HSn, 0.125f);
        // softmax -> P hi/lo
        softmax_kernel<<<Bn * Hn * Tn, 128>>>(patt, pph, ppl);
        // o = P V (tensor) -> zh/zl in [BT, H*HS] layout
        tgemm<EPI_HILO, 64, MODE_LIN, MODE_LIN, MODE_ATT>
            <<<dim3(Tn / 128, 1, Bn * Hn), 256, TgCfg<64>::SMEM>>>(
                pph, ppl, Tn, TT,
                vth, vtl, Tn, (long long)HSn * Tn,
                nullptr, zh, zl, Dn, 0LL, nullptr, Tn, 1.0f);
        // h += o @ Wproj + bproj
        tgemm<EPI_BIAS_RESID, 128, MODE_LIN, MODE_LIN, MODE_LIN>
            <<<dim3(BTn / 128, Dn / 128, 1), 256, TgCfg<128>::SMEM>>>(
                zh, zl, Dn, 0LL,
                wph + (long long)l * Dn * Dn, wpl + (long long)l * Dn * Dn, Dn, 0LL,
                ph, nullptr, nullptr, Dn, 0LL, bproj + l * Dn, Dn, INV_WSCALE);
        // z = LN2(h) -> hi/lo
        ln_kernel<true, false><<<BTn, 256>>>(ph, ln2g + l * Dn, ln2b + l * Dn,
                                             nullptr, zh, zl, nullptr, nullptr, nullptr);
        // ffn = gelu(z @ W1 + b1) -> hi/lo
        tgemm<EPI_BIAS_GELU, 128, MODE_LIN, MODE_LIN, MODE_LIN>
            <<<dim3(BTn / 128, DFFn / 128, 1), 256, TgCfg<128>::SMEM>>>(
                zh, zl, Dn, 0LL,
                w1h + (long long)l * Dn * DFFn, w1l + (long long)l * Dn * DFFn, Dn, 0LL,
                nullptr, fh, fl, DFFn, 0LL, b1 + l * DFFn, Dn, INV_WSCALE);
        // h += ffn @ W2 + b2
        tgemm<EPI_BIAS_RESID, 128, MODE_LIN, MODE_LIN, MODE_LIN>
            <<<dim3(BTn / 128, Dn / 128, 1), 256, TgCfg<128>::SMEM>>>(
                fh, fl, DFFn, 0LL,
                w2h + (long long)l * DFFn * Dn, w2l + (long long)l * DFFn * Dn, DFFn, 0LL,
                ph, nullptr, nullptr, Dn, 0LL, b2 + l * Dn, DFFn, INV_WSCALE);
    }
    ln_kernel<false, false><<<BTn, 256>>>(ph, lnfg, lnfb, pz, nullptr, nullptr,
                                          nullptr, nullptr, nullptr);
    logits_part<<<dim3(Bn, 16), 256>>>(pz, Wout);
    logits_final<<<1, 64>>>(bout, out);
}

// round 9
// speedup vs baseline: 3.0666x; 1.0657x over previous
#include <cuda_runtime.h>
#include <cuda_fp16.h>
#include <cuda_bf16.h>
#include <math.h>
#include <stdint.h>

#define DI __device__ __forceinline__

// ===================== portable PTX helpers (plain sm_103) =====================
DI uint32_t smem_u32(const void* p) {
    uint32_t a;
    asm("{ .reg .u64 t; cvta.to.shared.u64 t, %1; cvt.u32.u64 %0, t; }" : "=r"(a) : "l"(p));
    return a;
}
DI void cp16(uint32_t d, const void* s) {
    asm volatile("cp.async.cg.shared.global [%0], [%1], 16;" :: "r"(d), "l"(s) : "memory");
}
#define CP_COMMIT() asm volatile("cp.async.commit_group;" ::: "memory")
#define CP_WAIT1()  asm volatile("cp.async.wait_group 1;" ::: "memory")
#define CP_WAIT0()  asm volatile("cp.async.wait_group 0;" ::: "memory")

DI void ldsm4(uint32_t addr, uint32_t* r) {
    asm volatile("ldmatrix.sync.aligned.m8n8.x4.shared.b16 {%0,%1,%2,%3}, [%4];"
                 : "=r"(r[0]), "=r"(r[1]), "=r"(r[2]), "=r"(r[3]) : "r"(addr));
}
DI void ldsm2(uint32_t addr, uint32_t* r) {
    asm volatile("ldmatrix.sync.aligned.m8n8.x2.shared.b16 {%0,%1}, [%2];"
                 : "=r"(r[0]), "=r"(r[1]) : "r"(addr));
}
DI void mma16816(float* c, const uint32_t* a, const uint32_t* b) {
    asm volatile("mma.sync.aligned.m16n8k16.row.col.f32.f16.f16.f32 "
                 "{%0,%1,%2,%3},{%4,%5,%6,%7},{%8,%9},{%0,%1,%2,%3};"
                 : "+f"(c[0]), "+f"(c[1]), "+f"(c[2]), "+f"(c[3])
                 : "r"(a[0]), "r"(a[1]), "r"(a[2]), "r"(a[3]), "r"(b[0]), "r"(b[1]));
}

namespace enc {

constexpr int Bn = 16, Tn = 512, Dn = 1024, Hn = 16, HSn = 64, Ln = 4, DFFn = 4096, NCn = 3;
constexpr int BTn = Bn * Tn;  // 8192
constexpr float WSCALE = 64.0f;
constexpr float INV_WSCALE = 1.0f / 64.0f;

// ---- scratch ----
__device__ __align__(16) float g_h  [(size_t)BTn * Dn];
__device__ __align__(16) float g_z  [(size_t)BTn * Dn];
__device__ __align__(16) float g_lpart[Bn * 16 * NCn];
// activations hi/lo fp16
__device__ __align__(16) __half g_zh  [(size_t)BTn * Dn];
__device__ __align__(16) __half g_zl  [(size_t)BTn * Dn];
__device__ __align__(16) __half g_qkvh[(size_t)3 * BTn * Dn];
__device__ __align__(16) __half g_qkvl[(size_t)3 * BTn * Dn];
__device__ __align__(16) __half g_vth [(size_t)BTn * Dn];
__device__ __align__(16) __half g_vtl [(size_t)BTn * Dn];
__device__ __align__(16) __half g_ffnh[(size_t)BTn * DFFn];
__device__ __align__(16) __half g_ffnl[(size_t)BTn * DFFn];
// fp16 hi/lo weights, [N,K] layout, scaled by 64
__device__ __align__(16) __half g_wqkv_h[(size_t)Ln * 3 * Dn * Dn];
__device__ __align__(16) __half g_wqkv_l[(size_t)Ln * 3 * Dn * Dn];
__device__ __align__(16) __half g_wproj_h[(size_t)Ln * Dn * Dn];
__device__ __align__(16) __half g_wproj_l[(size_t)Ln * Dn * Dn];
__device__ __align__(16) __half g_w1_h[(size_t)Ln * Dn * DFFn];
__device__ __align__(16) __half g_w1_l[(size_t)Ln * Dn * DFFn];
__device__ __align__(16) __half g_w2_h[(size_t)Ln * DFFn * Dn];
__device__ __align__(16) __half g_w2_l[(size_t)Ln * DFFn * Dn];

DI float warp_sum(float v) {
#pragma unroll
    for (int o = 16; o > 0; o >>= 1) v += __shfl_xor_sync(0xffffffffu, v, o);
    return v;
}
DI float gelu_exact(float x) {
    return 0.5f * x * (1.0f + erff(x * 0.70710678118654752440f));
}
DI uint32_t h2u2(__half2 h) { return *reinterpret_cast<uint32_t*>(&h); }

// ---- layernorm; EMB fuses the embedding gather; HILO writes split fp16 ----
template <bool HILO, bool EMB>
__global__ void ln_kernel(const float* __restrict__ in, const float* __restrict__ gw,
                          const float* __restrict__ bw, float* __restrict__ outf,
                          __half* __restrict__ oh, __half* __restrict__ ol,
                          const int* __restrict__ xi, const float* __restrict__ tok,
                          const float* __restrict__ pos) {
    long long row = blockIdx.x;
    int tid = threadIdx.x;
    float4 x4;
    if (EMB) {
        int t = (int)(row & (Tn - 1));
        int tk = xi[row];
        float4 a = *(const float4*)(tok + (long long)tk * Dn + tid * 4);
        float4 p = *(const float4*)(pos + (long long)t * Dn + tid * 4);
        x4.x = a.x + p.x; x4.y = a.y + p.y; x4.z = a.z + p.z; x4.w = a.w + p.w;
        *(float4*)(g_h + row * Dn + tid * 4) = x4;   // residual stream
    } else {
        x4 = *(const float4*)(in + row * Dn + tid * 4);
    }
    float s  = x4.x + x4.y + x4.z + x4.w;
    float s2 = x4.x * x4.x + x4.y * x4.y + x4.z * x4.z + x4.w * x4.w;
    s = warp_sum(s); s2 = warp_sum(s2);
    __shared__ float sh[2][8];
    int w = tid >> 5;
    if ((tid & 31) == 0) { sh[0][w] = s; sh[1][w] = s2; }
    __syncthreads();
    float ts = 0.f, ts2 = 0.f;
#pragma unroll
    for (int i = 0; i < 8; i++) { ts += sh[0][i]; ts2 += sh[1][i]; }
    float mu = ts * (1.0f / Dn);
    float var = ts2 * (1.0f / Dn) - mu * mu;
    float rinv = rsqrtf(var + 1e-5f);
    float4 g4 = *(const float4*)(gw + tid * 4);
    float4 b4 = *(const float4*)(bw + tid * 4);
    float v[4];
    v[0] = (x4.x - mu) * rinv * g4.x + b4.x;
    v[1] = (x4.y - mu) * rinv * g4.y + b4.y;
    v[2] = (x4.z - mu) * rinv * g4.z + b4.z;
    v[3] = (x4.w - mu) * rinv * g4.w + b4.w;
    if (HILO) {
        __half h[4], l[4];
#pragma unroll
        for (int i = 0; i < 4; i++) {
            h[i] = __float2half_rn(v[i]);
            l[i] = __float2half_rn(v[i] - __half2float(h[i]));
        }
        long long o = row * Dn + tid * 4;
        *(__half2*)(oh + o)     = __halves2half2(h[0], h[1]);
        *(__half2*)(oh + o + 2) = __halves2half2(h[2], h[3]);
        *(__half2*)(ol + o)     = __halves2half2(l[0], l[1]);
        *(__half2*)(ol + o + 2) = __halves2half2(l[2], l[3]);
    } else {
        *(float4*)(outf + row * Dn + tid * 4) = make_float4(v[0], v[1], v[2], v[3]);
    }
}

// ---- weight prep: transpose [K,N] -> hi/lo fp16 [N,K], scale by 64 ----
__global__ void wprep_lin(const float* __restrict__ src, __half* __restrict__ dh,
                          __half* __restrict__ dl, int K, int N) {
    int l = blockIdx.z;
    src += (long long)l * K * N;
    dh += (long long)l * N * K;
    dl += (long long)l * N * K;
    __shared__ float t[32][33];
    int k0 = blockIdx.x * 32, n0 = blockIdx.y * 32;
    int tx = threadIdx.x, ty = threadIdx.y;
#pragma unroll
    for (int j = 0; j < 4; j++)
        t[ty + 8 * j][tx] = src[(long long)(k0 + ty + 8 * j) * N + n0 + tx];
    __syncthreads();
#pragma unroll
    for (int j = 0; j < 4; j++) {
        float v = t[tx][ty + 8 * j] * WSCALE;
        __half h = __float2half_rn(v);
        __half lo = __float2half_rn(v - __half2float(h));
        long long o = (long long)(n0 + ty + 8 * j) * K + k0 + tx;
        dh[o] = h; dl[o] = lo;
    }
}

// ---- qkv weight prep: [L,H,D,HS] -> [N=H*HS, K=D] hi/lo ----
__global__ void wprep_qkv(const float* __restrict__ Wq, const float* __restrict__ Wk,
                          const float* __restrict__ Wv) {
    int z = blockIdx.z;
    int h = z & 15, which = (z >> 4) % 3, l = z / 48;
    const float* W = which == 0 ? Wq : (which == 1 ? Wk : Wv);
    const float* src = W + ((long long)(l * Hn + h) * Dn) * HSn;
    long long base = ((long long)(l * 3 + which)) * Dn * Dn;
    __shared__ float t[32][33];
    int k0 = blockIdx.x * 32, n0 = blockIdx.y * 32;
    int tx = threadIdx.x, ty = threadIdx.y;
#pragma unroll
    for (int j = 0; j < 4; j++)
        t[ty + 8 * j][tx] = src[(long long)(k0 + ty + 8 * j) * HSn + n0 + tx];
    __syncthreads();
#pragma unroll
    for (int j = 0; j < 4; j++) {
        float v = t[tx][ty + 8 * j] * WSCALE;
        __half h2 = __float2half_rn(v);
        __half lo = __float2half_rn(v - __half2float(h2));
        long long o = base + (long long)(h * HSn + n0 + ty + 8 * j) * Dn + k0 + tx;
        g_wqkv_h[o] = h2; g_wqkv_l[o] = lo;
    }
}

// ---- V transpose: [b*T+t, h*64+e] fp16 hi/lo -> [bh, e, t] ----
__global__ void vtrans_kernel(const __half* __restrict__ vh, const __half* __restrict__ vl,
                              __half* __restrict__ oth, __half* __restrict__ otl) {
    int bh = blockIdx.z, b = bh >> 4, h = bh & 15;
    int t0 = blockIdx.x * 32, e0 = blockIdx.y * 32;
    __shared__ __half sh[32][34], sl[32][34];
    int tx = threadIdx.x, ty = threadIdx.y;
#pragma unroll
    for (int j = 0; j < 4; j++) {
        long long gi = ((long long)(b * Tn + t0 + ty + 8 * j)) * Dn + h * HSn + e0 + tx;
        sh[ty + 8 * j][tx] = vh[gi];
        sl[ty + 8 * j][tx] = vl[gi];
    }
    __syncthreads();
#pragma unroll
    for (int j = 0; j < 4; j++) {
        long long go = ((long long)bh * HSn + e0 + ty + 8 * j) * Tn + t0 + tx;
        oth[go] = sh[tx][ty + 8 * j];
        otl[go] = sl[tx][ty + 8 * j];
    }
}

// ===================== mma.sync fp16-split GEMM =====================
enum { EPI_F32 = 0, EPI_HILO = 1, EPI_BIAS_RESID = 2, EPI_BIAS_GELU = 3 };

// 64B rows + chunk swizzle c' = c ^ ((r>>1)&3); stage: Ah | Al | Bh | Bl
template <int BN> struct TgCfg {
    static constexpr int A_B = 128 * 64;                 // 8192
    static constexpr int B_B = BN * 64;
    static constexpr int STAGE = 2 * A_B + 2 * B_B;
    static constexpr int SMEM = 3 * STAGE;
    static constexpr int WN = BN / 4;
    static constexpr int NTN = WN / 8;
};

DI uint32_t swz_addr(uint32_t base, int r, int ch) {
    return base + (uint32_t)(r * 64 + ((ch ^ ((r >> 1) & 3)) << 4));
}

template <int BN>
DI void tg_load(uint32_t sd, const __half* __restrict__ Ahp, const __half* __restrict__ Alp,
                int lda, const __half* __restrict__ Bhp, const __half* __restrict__ Blp,
                int ldb, int k0, int tid) {
#pragma unroll
    for (int j = 0; j < 2; j++) {
        int cid = tid + j * 256;
        int r = cid >> 2;
        int ch = cid & 3;
        uint32_t d = swz_addr(sd, r, ch);
        long long go = (long long)r * lda + k0 + ch * 8;
        cp16(d, Ahp + go);
        cp16(d + (uint32_t)TgCfg<BN>::A_B, Alp + go);
    }
#pragma unroll
    for (int j = 0; j < BN / 64; j++) {
        int cid = tid + j * 256;
        int r = cid >> 2;
        int ch = cid & 3;
        uint32_t d = swz_addr(sd + 2u * TgCfg<BN>::A_B, r, ch);
        long long go = (long long)r * ldb + k0 + ch * 8;
        cp16(d, Bhp + go);
        cp16(d + (uint32_t)TgCfg<BN>::B_B, Blp + go);
    }
}

// register-lean compute with swizzled ldmatrix addressing
template <int BN>
DI void tg_compute(uint32_t sb, int wm, int wn, int lane, float acc[4][TgCfg<BN>::NTN][4]) {
    constexpr int NTN = TgCfg<BN>::NTN;
    const uint32_t sbB = sb + 2u * TgCfg<BN>::A_B;
    const int i4 = lane >> 3;
    const int l8 = lane & 7;
#pragma unroll
    for (int ks = 0; ks < 2; ks++) {
        uint32_t bhf[NTN][2], blf[NTN][2];
#pragma unroll
        for (int nt = 0; nt < NTN; nt++) {
            int rowb = wn * TgCfg<BN>::WN + nt * 8 + l8;
            int chb  = ks * 2 + (i4 & 1);
            uint32_t bd = swz_addr(sbB, rowb, chb);
            ldsm2(bd, bhf[nt]);
            ldsm2(bd + (uint32_t)TgCfg<BN>::B_B, blf[nt]);
        }
#pragma unroll
        for (int mt = 0; mt < 4; mt++) {
            uint32_t ahf[4], alf[4];
            int row = wm * 64 + mt * 16 + (i4 & 1) * 8 + l8;
            int cha = ks * 2 + (i4 >> 1);
            uint32_t ad = swz_addr(sb, row, cha);
            ldsm4(ad, ahf);
            ldsm4(ad + (uint32_t)TgCfg<BN>::A_B, alf);
#pragma unroll
            for (int nt = 0; nt < NTN; nt++) {
                mma16816(acc[mt][nt], ahf, bhf[nt]);
                mma16816(acc[mt][nt], ahf, blf[nt]);
                mma16816(acc[mt][nt], alf, bhf[nt]);
            }
        }
    }
}

template <int EPI, int BN>
__global__ void __launch_bounds__(256, 2) tgemm(
    const __half* __restrict__ Ah, const __half* __restrict__ Al, int lda, long long sA,
    const __half* __restrict__ Bh, const __half* __restrict__ Bl, int ldb, long long sB,
    float* __restrict__ Cf, __half* __restrict__ Ch, __half* __restrict__ Cl,
    int ldc, long long sC, const float* __restrict__ bias, int Kext, float oscale)
{
    constexpr int NTN = TgCfg<BN>::NTN;
    constexpr uint32_t STG = (uint32_t)TgCfg<BN>::STAGE;
    extern __shared__ char smraw[];
    const uint32_t sb0 = smem_u32(smraw);
    const int tid = threadIdx.x;
    const int lane = tid & 31, wid = tid >> 5;
    const int wm = wid & 1, wn = wid >> 1;
    const int z = blockIdx.z;

    long long aoff = sA * z;
    long long boff = sB * z;
    long long coff = sC * z;

    const __half* Ahp = Ah + aoff + (long long)blockIdx.x * 128 * lda;
    const __half* Alp = Al + aoff + (long long)blockIdx.x * 128 * lda;
    const __half* Bhp = Bh + boff + (long long)blockIdx.y * BN * ldb;
    const __half* Blp = Bl + boff + (long long)blockIdx.y * BN * ldb;

    float acc[4][NTN][4];
#pragma unroll
    for (int a = 0; a < 4; a++)
#pragma unroll
        for (int b = 0; b < NTN; b++)
#pragma unroll
            for (int c = 0; c < 4; c++) acc[a][b][c] = 0.f;

    const int NI = Kext >> 5;
    // prologue: stages 0,1
    tg_load<BN>(sb0, Ahp, Alp, lda, Bhp, Blp, ldb, 0, tid);
    CP_COMMIT();
    if (NI > 1) {
        tg_load<BN>(sb0 + STG, Ahp, Alp, lda, Bhp, Blp, ldb, 32, tid);
        CP_COMMIT();
    }
    int sidx = 0;                 // stage index of current iter (mod 3)
    for (int it = 0; it < NI; it++) {
        if (it < NI - 1) CP_WAIT1(); else CP_WAIT0();
        __syncthreads();
        if (it + 2 < NI) {
            int ns = sidx + 2; if (ns >= 3) ns -= 3;
            tg_load<BN>(sb0 + (uint32_t)ns * STG, Ahp, Alp, lda, Bhp, Blp, ldb,
                        (it + 2) << 5, tid);
            CP_COMMIT();
        }
        tg_compute<BN>(sb0 + (uint32_t)sidx * STG, wm, wn, lane, acc);
        if (++sidx == 3) sidx = 0;
    }

    // epilogue
    const int q = lane >> 2;
    const int cp2 = (lane & 3) * 2;
    const int gc = blockIdx.y * BN + wn * TgCfg<BN>::WN;
#pragma unroll
    for (int mt = 0; mt < 4; mt++) {
#pragma unroll
        for (int nt = 0; nt < NTN; nt++) {
            const float* a = acc[mt][nt];
            int cc = gc + nt * 8 + cp2;
#pragma unroll
            for (int half = 0; half < 2; half++) {
                int rr = blockIdx.x * 128 + wm * 64 + mt * 16 + q + half * 8;
                float v0 = a[half * 2 + 0] * oscale;
                float v1 = a[half * 2 + 1] * oscale;
                long long o = coff + (long long)rr * ldc + cc;
                if (EPI == EPI_BIAS_RESID || EPI == EPI_BIAS_GELU) {
                    v0 += bias[cc]; v1 += bias[cc + 1];
                }
                if (EPI == EPI_F32) {
                    *(float2*)(Cf + o) = make_float2(v0, v1);
                } else if (EPI == EPI_BIAS_RESID) {
                    float2 r = *(float2*)(Cf + o);
                    *(float2*)(Cf + o) = make_float2(v0 + r.x, v1 + r.y);
                } else {  // HILO / BIAS_GELU
                    if (EPI == EPI_BIAS_GELU) { v0 = gelu_exact(v0); v1 = gelu_exact(v1); }
                    __half h0 = __float2half_rn(v0), h1 = __float2half_rn(v1);
                    __half l0 = __float2half_rn(v0 - __half2float(h0));
                    __half l1 = __float2half_rn(v1 - __half2float(h1));
                    *(__half2*)(Ch + o) = __halves2half2(h0, h1);
                    *(__half2*)(Cl + o) = __halves2half2(l0, l1);
                }
            }
        }
    }
}

// ===================== flash attention (fused QK^T + softmax + PV) =====================
// grid (Tn/128, 1, Bn*Hn); 256 thr; warp w owns q rows [w*16, w*16+16).
// smem: Qh 16K | Ql 16K | Kh 8K | Kl 8K | Vh 8K | Vl 8K = 64KB (8-chunk swizzle rows of 128B)
constexpr int FA_SMEM = 65536;

DI uint32_t swz8(uint32_t base, int r, int c) {
    return base + (uint32_t)(r * 128 + ((c ^ (r & 7)) << 4));
}

__global__ void __launch_bounds__(256, 2) flash_kernel(
    const __half* __restrict__ qkh, const __half* __restrict__ qkl,
    const __half* __restrict__ vth, const __half* __restrict__ vtl,
    __half* __restrict__ ohp, __half* __restrict__ olp)
{
    extern __shared__ char smraw[];
    const uint32_t sb = smem_u32(smraw);
    const uint32_t qhS = sb, qlS = sb + 16384, khS = sb + 32768, klS = sb + 40960,
                   vhS = sb + 49152, vlS = sb + 57344;
    const int tid = threadIdx.x, lane = tid & 31, w = tid >> 5;
    const int bz = blockIdx.z, b = bz >> 4, h = bz & 15;
    const int hc = h * 64;
    const long long qrow0 = (long long)b * Tn + blockIdx.x * 128;
    const __half* Qh = qkh;
    const __half* Kh = qkh + (long long)BTn * Dn;
    const __half* Ql = qkl;
    const __half* Kl = qkl + (long long)BTn * Dn;

    // load Q tile 128x64 hi/lo
#pragma unroll
    for (int i = 0; i < 4; i++) {
        int cid = tid + i * 256;          // 0..1023
        int r = cid >> 3, c = cid & 7;
        long long g = (qrow0 + r) * Dn + hc + c * 8;
        cp16(swz8(qhS, r, c), Qh + g);
        cp16(swz8(qlS, r, c), Ql + g);
    }
    CP_COMMIT();

    float oacc[8][4];
    float mrun[2] = {-3e38f, -3e38f}, lrun[2] = {0.f, 0.f};
#pragma unroll
    for (int e = 0; e < 8; e++)
#pragma unroll
        for (int i = 0; i < 4; i++) oacc[e][i] = 0.f;

    const int i4 = lane >> 3, l8 = lane & 7, sel = lane >> 3;
    const long long kvb = (long long)b * Tn;

    for (int j = 0; j < 8; j++) {
        __syncthreads();   // previous chunk's compute done before overwrite
#pragma unroll
        for (int i = 0; i < 2; i++) {
            int cid = tid + i * 256;      // 0..511
            int r = cid >> 3, c = cid & 7;
            long long gk = (kvb + j * 64 + r) * Dn + hc + c * 8;
            cp16(swz8(khS, r, c), Kh + gk);
            cp16(swz8(klS, r, c), Kl + gk);
            long long gv = ((long long)bz * 64 + r) * Tn + j * 64 + c * 8;
            cp16(swz8(vhS, r, c), vth + gv);
            cp16(swz8(vlS, r, c), vtl + gv);
        }
        CP_COMMIT();
        CP_WAIT0();
        __syncthreads();

        // ---- S = Q K^T (128 rows x 64 t-cols per warp: 16 rows x 64) ----
        float sacc[8][4];
#pragma unroll
        for (int e = 0; e < 8; e++)
#pragma unroll
            for (int i = 0; i < 4; i++) sacc[e][i] = 0.f;
#pragma unroll
        for (int ks = 0; ks < 4; ks++) {    // e = 64 = 4 x k16
            uint32_t qf[4], qlf[4];
            {
                int row = w * 16 + (i4 & 1) * 8 + l8;
                int c = ks * 2 + (i4 >> 1);
                ldsm4(swz8(qhS, row, c), qf);
                ldsm4(swz8(qlS, row, c), qlf);
            }
#pragma unroll
            for (int np = 0; np < 4; np++) {   // t-tile pairs
                uint32_t bh4[4], bl4[4];
                int row = np * 16 + ((sel >> 1) << 3) + l8;
                int c = ks * 2 + (sel & 1);
                ldsm4(swz8(khS, row, c), bh4);
                ldsm4(swz8(klS, row, c), bl4);
                mma16816(sacc[np * 2], qf, bh4);
                mma16816(sacc[np * 2], qf, bl4);
                mma16816(sacc[np * 2], qlf, bh4);
                mma16816(sacc[np * 2 + 1], qf, bh4 + 2);
                mma16816(sacc[np * 2 + 1], qf, bl4 + 2);
                mma16816(sacc[np * 2 + 1], qlf, bh4 + 2);
            }
        }
        // ---- online softmax (rows: r0=lane>>2, r1=r0+8; cols spread over lane&3) ----
        float m0 = -3e38f, m1 = -3e38f;
#pragma unroll
        for (int e = 0; e < 8; e++) {
            m0 = fmaxf(m0, fmaxf(sacc[e][0], sacc[e][1]));
            m1 = fmaxf(m1, fmaxf(sacc[e][2], sacc[e][3]));
        }
        m0 = fmaxf(m0, __shfl_xor_sync(0xffffffffu, m0, 1));
        m0 = fmaxf(m0, __shfl_xor_sync(0xffffffffu, m0, 2));
        m1 = fmaxf(m1, __shfl_xor_sync(0xffffffffu, m1, 1));
        m1 = fmaxf(m1, __shfl_xor_sync(0xffffffffu, m1, 2));
        float mn0 = fmaxf(mrun[0], m0 * 0.125f);
        float mn1 = fmaxf(mrun[1], m1 * 0.125f);
        float cr0 = __expf(mrun[0] - mn0);
        float cr1 = __expf(mrun[1] - mn1);
        mrun[0] = mn0; mrun[1] = mn1;
        float ls0 = 0.f, ls1 = 0.f;
#pragma unroll
        for (int e = 0; e < 8; e++) {
            sacc[e][0] = __expf(fmaf(sacc[e][0], 0.125f, -mn0));
            sacc[e][1] = __expf(fmaf(sacc[e][1], 0.125f, -mn0));
            sacc[e][2] = __expf(fmaf(sacc[e][2], 0.125f, -mn1));
            sacc[e][3] = __expf(fmaf(sacc[e][3], 0.125f, -mn1));
            ls0 += sacc[e][0] + sacc[e][1];
            ls1 += sacc[e][2] + sacc[e][3];
        }
        lrun[0] = lrun[0] * cr0 + ls0;
        lrun[1] = lrun[1] * cr1 + ls1;
#pragma unroll
        for (int e = 0; e < 8; e++) {
            oacc[e][0] *= cr0; oacc[e][1] *= cr0;
            oacc[e][2] *= cr1; oacc[e][3] *= cr1;
        }
        // ---- O += P V (3-pass, P split hi/lo in registers) ----
#pragma unroll
        for (int kt = 0; kt < 4; kt++) {
            int t0 = kt * 2, t1 = kt * 2 + 1;
            __half2 h0 = __floats2half2_rn(sacc[t0][0], sacc[t0][1]);
            __half2 h1 = __floats2half2_rn(sacc[t0][2], sacc[t0][3]);
            __half2 h2 = __floats2half2_rn(sacc[t1][0], sacc[t1][1]);
            __half2 h3 = __floats2half2_rn(sacc[t1][2], sacc[t1][3]);
            uint32_t pa[4] = {h2u2(h0), h2u2(h1), h2u2(h2), h2u2(h3)};
            float2 f0 = __half22float2(h0), f1 = __half22float2(h1),
                   f2 = __half22float2(h2), f3 = __half22float2(h3);
            uint32_t pl[4] = {
                h2u2(__floats2half2_rn(sacc[t0][0] - f0.x, sacc[t0][1] - f0.y)),
                h2u2(__floats2half2_rn(sacc[t0][2] - f1.x, sacc[t0][3] - f1.y)),
                h2u2(__floats2half2_rn(sacc[t1][0] - f2.x, sacc[t1][1] - f2.y)),
                h2u2(__floats2half2_rn(sacc[t1][2] - f3.x, sacc[t1][3] - f3.y))};
#pragma unroll
            for (int ep = 0; ep < 4; ep++) {   // e-tile pairs
                uint32_t vh4[4], vl4[4];
                int row = ep * 16 + ((sel >> 1) << 3) + l8;
                int c = kt * 2 + (sel & 1);
                ldsm4(swz8(vhS, row, c), vh4);
                ldsm4(swz8(vlS, row, c), vl4);
                mma16816(oacc[ep * 2], pa, vh4);
                mma16816(oacc[ep * 2], pa, vl4);
                mma16816(oacc[ep * 2], pl, vh4);
                mma16816(oacc[ep * 2 + 1], pa, vh4 + 2);
                mma16816(oacc[ep * 2 + 1], pa, vl4 + 2);
                mma16816(oacc[ep * 2 + 1], pl, vh4 + 2);
            }
        }
    }

    // finalize: o = O / l, write hi/lo to [bt, h*64+e]
    float l0 = lrun[0];
    l0 += __shfl_xor_sync(0xffffffffu, l0, 1);
    l0 += __shfl_xor_sync(0xffffffffu, l0, 2);
    float l1 = lrun[1];
    l1 += __shfl_xor_sync(0xffffffffu, l1, 1);
    l1 += __shfl_xor_sync(0xffffffffu, l1, 2);
    float inv0 = 1.0f / l0, inv1 = 1.0f / l1;
    long long bt0 = qrow0 + w * 16 + (lane >> 2);
    int colb = hc + (lane & 3) * 2;
#pragma unroll
    for (int e = 0; e < 8; e++) {
        long long o0 = bt0 * Dn + colb + e * 8;
        long long o1 = (bt0 + 8) * Dn + colb + e * 8;
        float v0 = oacc[e][0] * inv0, v1 = oacc[e][1] * inv0;
        float v2 = oacc[e][2] * inv1, v3 = oacc[e][3] * inv1;
        __half a0 = __float2half_rn(v0), a1 = __float2half_rn(v1);
        __half a2 = __float2half_rn(v2), a3 = __float2half_rn(v3);
        *(__half2*)(ohp + o0) = __halves2half2(a0, a1);
        *(__half2*)(ohp + o1) = __halves2half2(a2, a3);
        *(__half2*)(olp + o0) = __halves2half2(
            __float2half_rn(v0 - __half2float(a0)), __float2half_rn(v1 - __half2float(a1)));
        *(__half2*)(olp + o1) = __halves2half2(
            __float2half_rn(v2 - __half2float(a2)), __float2half_rn(v3 - __half2float(a3)));
    }
}

// ---- logits: 2-stage deterministic reduction ----
__global__ void logits_part(const float* __restrict__ hf, const float* __restrict__ Wout) {
    int b = blockIdx.x, c = blockIdx.y;
    const int CHUNK = Tn * Dn / 16;  // 32768
    const float* hb = hf + (long long)b * Tn * Dn + c * CHUNK;
    const float* wb = Wout + ((long long)c * CHUNK) * NCn;
    float a[3] = {0.f, 0.f, 0.f};
    for (int i = threadIdx.x; i < CHUNK; i += blockDim.x) {
        float v = hb[i];
        const float* wr = wb + (long long)i * NCn;
        a[0] = fmaf(v, wr[0], a[0]);
        a[1] = fmaf(v, wr[1], a[1]);
        a[2] = fmaf(v, wr[2], a[2]);
    }
    __shared__ float sm[3][8];
    int w = threadIdx.x >> 5, ln = threadIdx.x & 31;
#pragma unroll
    for (int cc = 0; cc < 3; cc++) {
        float v = warp_sum(a[cc]);
        if (ln == 0) sm[cc][w] = v;
    }
    __syncthreads();
    if (threadIdx.x < 3) {
        float t = 0.f;
#pragma unroll
        for (int i = 0; i < 8; i++) t += sm[threadIdx.x][i];
        g_lpart[(b * 16 + c) * NCn + threadIdx.x] = t;
    }
}
__global__ void logits_final(const float* __restrict__ bout, float* __restrict__ out) {
    int t = threadIdx.x;
    if (t >= Bn * NCn) return;
    int b = t / NCn, c = t % NCn;
    float s = bout[c];
#pragma unroll
    for (int i = 0; i < 16; i++) s += g_lpart[(b * 16 + i) * NCn + c];
    out[b * NCn + c] = s;
}

}  // namespace enc

extern "C" void kernel_launch(void* const* d_in, const int* in_sizes, int n_in,
                              void* d_out, int out_size) {
    using namespace enc;
    (void)in_sizes; (void)n_in; (void)out_size;

    const int*   x     = (const int*)d_in[0];
    const float* tok   = (const float*)d_in[1];
    const float* pos   = (const float*)d_in[2];
    const float* Wq    = (const float*)d_in[3];
    const float* Wk    = (const float*)d_in[4];
    const float* Wv    = (const float*)d_in[5];
    const float* Wproj = (const float*)d_in[6];
    const float* bproj = (const float*)d_in[7];
    const float* ln1g  = (const float*)d_in[8];
    const float* ln1b  = (const float*)d_in[9];
    const float* ln2g  = (const float*)d_in[10];
    const float* ln2b  = (const float*)d_in[11];
    const float* W1    = (const float*)d_in[12];
    const float* b1    = (const float*)d_in[13];
    const float* W2    = (const float*)d_in[14];
    const float* b2    = (const float*)d_in[15];
    const float* lnfg  = (const float*)d_in[16];
    const float* lnfb  = (const float*)d_in[17];
    const float* Wout  = (const float*)d_in[18];
    const float* bout  = (const float*)d_in[19];
    float* out = (float*)d_out;

    static float *ph = nullptr, *pz;
    static __half *zh, *zl, *qh, *ql, *vth, *vtl, *fh, *fl;
    static __half *wqh, *wql, *wph, *wpl, *w1h, *w1l, *w2h, *w2l;
    if (!ph) {
        cudaGetSymbolAddress((void**)&ph,   g_h);
        cudaGetSymbolAddress((void**)&pz,   g_z);
        cudaGetSymbolAddress((void**)&zh, g_zh);
        cudaGetSymbolAddress((void**)&zl, g_zl);
        cudaGetSymbolAddress((void**)&qh, g_qkvh);
        cudaGetSymbolAddress((void**)&ql, g_qkvl);
        cudaGetSymbolAddress((void**)&vth, g_vth);
        cudaGetSymbolAddress((void**)&vtl, g_vtl);
        cudaGetSymbolAddress((void**)&fh, g_ffnh);
        cudaGetSymbolAddress((void**)&fl, g_ffnl);
        cudaGetSymbolAddress((void**)&wqh, g_wqkv_h);
        cudaGetSymbolAddress((void**)&wql, g_wqkv_l);
        cudaGetSymbolAddress((void**)&wph, g_wproj_h);
        cudaGetSymbolAddress((void**)&wpl, g_wproj_l);
        cudaGetSymbolAddress((void**)&w1h, g_w1_h);
        cudaGetSymbolAddress((void**)&w1l, g_w1_l);
        cudaGetSymbolAddress((void**)&w2h, g_w2_h);
        cudaGetSymbolAddress((void**)&w2l, g_w2_l);
        cudaFuncSetAttribute((const void*)tgemm<EPI_HILO, 128>,
                             cudaFuncAttributeMaxDynamicSharedMemorySize, TgCfg<128>::SMEM);
        cudaFuncSetAttribute((const void*)tgemm<EPI_BIAS_RESID, 128>,
                             cudaFuncAttributeMaxDynamicSharedMemorySize, TgCfg<128>::SMEM);
        cudaFuncSetAttribute((const void*)tgemm<EPI_BIAS_GELU, 128>,
                             cudaFuncAttributeMaxDynamicSharedMemorySize, TgCfg<128>::SMEM);
        cudaFuncSetAttribute((const void*)flash_kernel,
                             cudaFuncAttributeMaxDynamicSharedMemorySize, FA_SMEM);
    }

    // ---- prep ----
    wprep_qkv<<<dim3(Dn / 32, HSn / 32, Ln * 3 * Hn), dim3(32, 8)>>>(Wq, Wk, Wv);
    wprep_lin<<<dim3(Dn / 32, Dn / 32, Ln),   dim3(32, 8)>>>(Wproj, wph, wpl, Dn, Dn);
    wprep_lin<<<dim3(Dn / 32, DFFn / 32, Ln), dim3(32, 8)>>>(W1, w1h, w1l, Dn, DFFn);
    wprep_lin<<<dim3(DFFn / 32, Dn / 32, Ln), dim3(32, 8)>>>(W2, w2h, w2l, DFFn, Dn);

    for (int l = 0; l < Ln; l++) {
        // z = LN1(h) -> hi/lo (layer 0 fuses the embedding gather)
        if (l == 0)
            ln_kernel<true, true><<<BTn, 256>>>(nullptr, ln1g, ln1b, nullptr, zh, zl,
                                                x, tok, pos);
        else
            ln_kernel<true, false><<<BTn, 256>>>(ph, ln1g + l * Dn, ln1b + l * Dn,
                                                 nullptr, zh, zl, nullptr, nullptr, nullptr);
        // q,k,v = z @ W -> hi/lo fp16
        tgemm<EPI_HILO, 128><<<dim3(BTn / 128, Dn / 128, 3), 256, TgCfg<128>::SMEM>>>(
            zh, zl, Dn, 0LL,
            wqh + (long long)l * 3 * Dn * Dn, wql + (long long)l * 3 * Dn * Dn, Dn,
            (long long)Dn * Dn,
            nullptr, qh, ql, Dn, (long long)BTn * Dn, nullptr, Dn, INV_WSCALE);
        // V^T hi/lo
        vtrans_kernel<<<dim3(Tn / 32, HSn / 32, Bn * Hn), dim3(32, 8)>>>(
            qh + 2LL * BTn * Dn, ql + 2LL * BTn * Dn, vth, vtl);
        // fused attention -> o hi/lo in zh/zl
        flash_kernel<<<dim3(Tn / 128, 1, Bn * Hn), 256, FA_SMEM>>>(
            qh, ql, vth, vtl, zh, zl);
        // h += o @ Wproj + bproj
        tgemm<EPI_BIAS_RESID, 128><<<dim3(BTn / 128, Dn / 128, 1), 256, TgCfg<128>::SMEM>>>(
            zh, zl, Dn, 0LL,
            wph + (long long)l * Dn * Dn, wpl + (long long)l * Dn * Dn, Dn, 0LL,
            ph, nullptr, nullptr, Dn, 0LL, bproj + l * Dn, Dn, INV_WSCALE);
        // z = LN2(h) -> hi/lo
        ln_kernel<true, false><<<BTn, 256>>>(ph, ln2g + l * Dn, ln2b + l * Dn,
                                             nullptr, zh, zl, nullptr, nullptr, nullptr);
        // ffn = gelu(z @ W1 + b1) -> hi/lo
        tgemm<EPI_BIAS_GELU, 128><<<dim3(BTn / 128, DFFn / 128, 1), 256, TgCfg<128>::SMEM>>>(
            zh, zl, Dn, 0LL,
            w1h + (long long)l * Dn * DFFn, w1l + (long long)l * Dn * DFFn, Dn, 0LL,
            nullptr, fh, fl, DFFn, 0LL, b1 + l * DFFn, Dn, INV_WSCALE);
        // h += ffn @ W2 + b2
        tgemm<EPI_BIAS_RESID, 128><<<dim3(BTn / 128, Dn / 128, 1), 256, TgCfg<128>::SMEM>>>(
            fh, fl, DFFn, 0LL,
            w2h + (long long)l * DFFn * Dn, w2l + (long long)l * DFFn * Dn, DFFn, 0LL,
            ph, nullptr, nullptr, Dn, 0LL, b2 + l * Dn, DFFn, INV_WSCALE);
    }
    ln_kernel<false, false><<<BTn, 256>>>(ph, lnfg, lnfb, pz, nullptr, nullptr,
                                          nullptr, nullptr, nullptr);
    logits_part<<<dim3(Bn, 16), 256>>>(pz, Wout);
    logits_final<<<1, 64>>>(bout, out);
}

// round 10
// speedup vs baseline: 3.7099x; 1.2098x over previous
#include <cuda_runtime.h>
#include <cuda_fp16.h>
#include <cuda_bf16.h>
#include <math.h>
#include <stdint.h>

#define DI __device__ __forceinline__

// ===================== portable PTX helpers (plain sm_103) =====================
DI uint32_t smem_u32(const void* p) {
    uint32_t a;
    asm("{ .reg .u64 t; cvta.to.shared.u64 t, %1; cvt.u32.u64 %0, t; }" : "=r"(a) : "l"(p));
    return a;
}
DI void cp16(uint32_t d, const void* s) {
    asm volatile("cp.async.cg.shared.global [%0], [%1], 16;" :: "r"(d), "l"(s) : "memory");
}
#define CP_COMMIT() asm volatile("cp.async.commit_group;" ::: "memory")
#define CP_WAIT1()  asm volatile("cp.async.wait_group 1;" ::: "memory")
#define CP_WAIT0()  asm volatile("cp.async.wait_group 0;" ::: "memory")

DI void ldsm4(uint32_t addr, uint32_t* r) {
    asm volatile("ldmatrix.sync.aligned.m8n8.x4.shared.b16 {%0,%1,%2,%3}, [%4];"
                 : "=r"(r[0]), "=r"(r[1]), "=r"(r[2]), "=r"(r[3]) : "r"(addr));
}
DI void ldsm2(uint32_t addr, uint32_t* r) {
    asm volatile("ldmatrix.sync.aligned.m8n8.x2.shared.b16 {%0,%1}, [%2];"
                 : "=r"(r[0]), "=r"(r[1]) : "r"(addr));
}
DI void mma16816(float* c, const uint32_t* a, const uint32_t* b) {
    asm volatile("mma.sync.aligned.m16n8k16.row.col.f32.f16.f16.f32 "
                 "{%0,%1,%2,%3},{%4,%5,%6,%7},{%8,%9},{%0,%1,%2,%3};"
                 : "+f"(c[0]), "+f"(c[1]), "+f"(c[2]), "+f"(c[3])
                 : "r"(a[0]), "r"(a[1]), "r"(a[2]), "r"(a[3]), "r"(b[0]), "r"(b[1]));
}

namespace enc {

constexpr int Bn = 16, Tn = 512, Dn = 1024, Hn = 16, HSn = 64, Ln = 4, DFFn = 4096, NCn = 3;
constexpr int BTn = Bn * Tn;  // 8192
constexpr float WSCALE = 64.0f;
constexpr float INV_WSCALE = 1.0f / 64.0f;

// ---- scratch ----
__device__ __align__(16) float g_h  [(size_t)BTn * Dn];
__device__ __align__(16) float g_z  [(size_t)BTn * Dn];
__device__ __align__(16) float g_lpart[Bn * 16 * NCn];
// activations hi/lo fp16
__device__ __align__(16) __half g_zh  [(size_t)BTn * Dn];
__device__ __align__(16) __half g_zl  [(size_t)BTn * Dn];
__device__ __align__(16) __half g_qkvh[(size_t)3 * BTn * Dn];
__device__ __align__(16) __half g_qkvl[(size_t)3 * BTn * Dn];
__device__ __align__(16) __half g_vth [(size_t)BTn * Dn];
__device__ __align__(16) __half g_vtl [(size_t)BTn * Dn];
__device__ __align__(16) __half g_ffnh[(size_t)BTn * DFFn];
// fp16 hi/lo weights, [N,K] layout, scaled by 64
__device__ __align__(16) __half g_wqkv_h[(size_t)Ln * 3 * Dn * Dn];
__device__ __align__(16) __half g_wqkv_l[(size_t)Ln * 3 * Dn * Dn];
__device__ __align__(16) __half g_wproj_h[(size_t)Ln * Dn * Dn];
__device__ __align__(16) __half g_wproj_l[(size_t)Ln * Dn * Dn];
__device__ __align__(16) __half g_w1_h[(size_t)Ln * Dn * DFFn];
__device__ __align__(16) __half g_w1_l[(size_t)Ln * Dn * DFFn];
__device__ __align__(16) __half g_w2_h[(size_t)Ln * DFFn * Dn];
__device__ __align__(16) __half g_w2_l[(size_t)Ln * DFFn * Dn];

DI float warp_sum(float v) {
#pragma unroll
    for (int o = 16; o > 0; o >>= 1) v += __shfl_xor_sync(0xffffffffu, v, o);
    return v;
}
DI float gelu_exact(float x) {
    return 0.5f * x * (1.0f + erff(x * 0.70710678118654752440f));
}
DI uint32_t h2u2(__half2 h) { return *reinterpret_cast<uint32_t*>(&h); }

// ---- layernorm; EMB fuses embedding; HILO writes hi (and lo if WLO) ----
template <bool HILO, bool EMB, bool WLO>
__global__ void ln_kernel(const float* __restrict__ in, const float* __restrict__ gw,
                          const float* __restrict__ bw, float* __restrict__ outf,
                          __half* __restrict__ oh, __half* __restrict__ ol,
                          const int* __restrict__ xi, const float* __restrict__ tok,
                          const float* __restrict__ pos) {
    long long row = blockIdx.x;
    int tid = threadIdx.x;
    float4 x4;
    if (EMB) {
        int t = (int)(row & (Tn - 1));
        int tk = xi[row];
        float4 a = *(const float4*)(tok + (long long)tk * Dn + tid * 4);
        float4 p = *(const float4*)(pos + (long long)t * Dn + tid * 4);
        x4.x = a.x + p.x; x4.y = a.y + p.y; x4.z = a.z + p.z; x4.w = a.w + p.w;
        *(float4*)(g_h + row * Dn + tid * 4) = x4;   // residual stream
    } else {
        x4 = *(const float4*)(in + row * Dn + tid * 4);
    }
    float s  = x4.x + x4.y + x4.z + x4.w;
    float s2 = x4.x * x4.x + x4.y * x4.y + x4.z * x4.z + x4.w * x4.w;
    s = warp_sum(s); s2 = warp_sum(s2);
    __shared__ float sh[2][8];
    int w = tid >> 5;
    if ((tid & 31) == 0) { sh[0][w] = s; sh[1][w] = s2; }
    __syncthreads();
    float ts = 0.f, ts2 = 0.f;
#pragma unroll
    for (int i = 0; i < 8; i++) { ts += sh[0][i]; ts2 += sh[1][i]; }
    float mu = ts * (1.0f / Dn);
    float var = ts2 * (1.0f / Dn) - mu * mu;
    float rinv = rsqrtf(var + 1e-5f);
    float4 g4 = *(const float4*)(gw + tid * 4);
    float4 b4 = *(const float4*)(bw + tid * 4);
    float v[4];
    v[0] = (x4.x - mu) * rinv * g4.x + b4.x;
    v[1] = (x4.y - mu) * rinv * g4.y + b4.y;
    v[2] = (x4.z - mu) * rinv * g4.z + b4.z;
    v[3] = (x4.w - mu) * rinv * g4.w + b4.w;
    if (HILO) {
        __half h[4];
#pragma unroll
        for (int i = 0; i < 4; i++) h[i] = __float2half_rn(v[i]);
        long long o = row * Dn + tid * 4;
        *(__half2*)(oh + o)     = __halves2half2(h[0], h[1]);
        *(__half2*)(oh + o + 2) = __halves2half2(h[2], h[3]);
        if (WLO) {
            __half l[4];
#pragma unroll
            for (int i = 0; i < 4; i++)
                l[i] = __float2half_rn(v[i] - __half2float(h[i]));
            *(__half2*)(ol + o)     = __halves2half2(l[0], l[1]);
            *(__half2*)(ol + o + 2) = __halves2half2(l[2], l[3]);
        }
    } else {
        *(float4*)(outf + row * Dn + tid * 4) = make_float4(v[0], v[1], v[2], v[3]);
    }
}

// ---- weight prep: transpose [K,N] -> hi/lo fp16 [N,K], scale by 64 ----
__global__ void wprep_lin(const float* __restrict__ src, __half* __restrict__ dh,
                          __half* __restrict__ dl, int K, int N) {
    int l = blockIdx.z;
    src += (long long)l * K * N;
    dh += (long long)l * N * K;
    dl += (long long)l * N * K;
    __shared__ float t[32][33];
    int k0 = blockIdx.x * 32, n0 = blockIdx.y * 32;
    int tx = threadIdx.x, ty = threadIdx.y;
#pragma unroll
    for (int j = 0; j < 4; j++)
        t[ty + 8 * j][tx] = src[(long long)(k0 + ty + 8 * j) * N + n0 + tx];
    __syncthreads();
#pragma unroll
    for (int j = 0; j < 4; j++) {
        float v = t[tx][ty + 8 * j] * WSCALE;
        __half h = __float2half_rn(v);
        __half lo = __float2half_rn(v - __half2float(h));
        long long o = (long long)(n0 + ty + 8 * j) * K + k0 + tx;
        dh[o] = h; dl[o] = lo;
    }
}

// ---- qkv weight prep: [L,H,D,HS] -> [N=H*HS, K=D] hi/lo ----
__global__ void wprep_qkv(const float* __restrict__ Wq, const float* __restrict__ Wk,
                          const float* __restrict__ Wv) {
    int z = blockIdx.z;
    int h = z & 15, which = (z >> 4) % 3, l = z / 48;
    const float* W = which == 0 ? Wq : (which == 1 ? Wk : Wv);
    const float* src = W + ((long long)(l * Hn + h) * Dn) * HSn;
    long long base = ((long long)(l * 3 + which)) * Dn * Dn;
    __shared__ float t[32][33];
    int k0 = blockIdx.x * 32, n0 = blockIdx.y * 32;
    int tx = threadIdx.x, ty = threadIdx.y;
#pragma unroll
    for (int j = 0; j < 4; j++)
        t[ty + 8 * j][tx] = src[(long long)(k0 + ty + 8 * j) * HSn + n0 + tx];
    __syncthreads();
#pragma unroll
    for (int j = 0; j < 4; j++) {
        float v = t[tx][ty + 8 * j] * WSCALE;
        __half h2 = __float2half_rn(v);
        __half lo = __float2half_rn(v - __half2float(h2));
        long long o = base + (long long)(h * HSn + n0 + ty + 8 * j) * Dn + k0 + tx;
        g_wqkv_h[o] = h2; g_wqkv_l[o] = lo;
    }
}

// ---- V transpose: [b*T+t, h*64+e] fp16 hi/lo -> [bh, e, t] ----
__global__ void vtrans_kernel(const __half* __restrict__ vh, const __half* __restrict__ vl,
                              __half* __restrict__ oth, __half* __restrict__ otl) {
    int bh = blockIdx.z, b = bh >> 4, h = bh & 15;
    int t0 = blockIdx.x * 32, e0 = blockIdx.y * 32;
    __shared__ __half sh[32][34], sl[32][34];
    int tx = threadIdx.x, ty = threadIdx.y;
#pragma unroll
    for (int j = 0; j < 4; j++) {
        long long gi = ((long long)(b * Tn + t0 + ty + 8 * j)) * Dn + h * HSn + e0 + tx;
        sh[ty + 8 * j][tx] = vh[gi];
        sl[ty + 8 * j][tx] = vl[gi];
    }
    __syncthreads();
#pragma unroll
    for (int j = 0; j < 4; j++) {
        long long go = ((long long)bh * HSn + e0 + ty + 8 * j) * Tn + t0 + tx;
        oth[go] = sh[tx][ty + 8 * j];
        otl[go] = sl[tx][ty + 8 * j];
    }
}

// ===================== mma.sync fp16-split GEMM =====================
// EPI_GELU_HI: bias+gelu, write hi only (consumer is a 2-pass GEMM)
enum { EPI_F32 = 0, EPI_HILO = 1, EPI_BIAS_RESID = 2, EPI_BIAS_GELU = 3, EPI_GELU_HI = 4 };

// 64B rows + chunk swizzle; stage: Ah [| Al] | Bh | Bl.  TWOP: drop Al (2-pass)
template <int BN, bool TWOP> struct TgCfg {
    static constexpr int A_B = 128 * 64;                 // 8192
    static constexpr int NA = TWOP ? 1 : 2;
    static constexpr int B_B = BN * 64;
    static constexpr int B_OFF = NA * A_B;
    static constexpr int STAGE = NA * A_B + 2 * B_B;
    static constexpr int SMEM = 3 * STAGE;
    static constexpr int WN = BN / 4;
    static constexpr int NTN = WN / 8;
};

DI uint32_t swz_addr(uint32_t base, int r, int ch) {
    return base + (uint32_t)(r * 64 + ((ch ^ ((r >> 1) & 3)) << 4));
}

template <int BN, bool TWOP>
DI void tg_load(uint32_t sd, const __half* __restrict__ Ahp, const __half* __restrict__ Alp,
                int lda, const __half* __restrict__ Bhp, const __half* __restrict__ Blp,
                int ldb, int k0, int tid) {
    using C = TgCfg<BN, TWOP>;
#pragma unroll
    for (int j = 0; j < 2; j++) {
        int cid = tid + j * 256;
        int r = cid >> 2;
        int ch = cid & 3;
        uint32_t d = swz_addr(sd, r, ch);
        long long go = (long long)r * lda + k0 + ch * 8;
        cp16(d, Ahp + go);
        if (!TWOP) cp16(d + (uint32_t)C::A_B, Alp + go);
    }
#pragma unroll
    for (int j = 0; j < BN / 64; j++) {
        int cid = tid + j * 256;
        int r = cid >> 2;
        int ch = cid & 3;
        uint32_t d = swz_addr(sd + (uint32_t)C::B_OFF, r, ch);
        long long go = (long long)r * ldb + k0 + ch * 8;
        cp16(d, Bhp + go);
        cp16(d + (uint32_t)C::B_B, Blp + go);
    }
}

template <int BN, bool TWOP>
DI void tg_compute(uint32_t sb, int wm, int wn, int lane,
                   float acc[4][TgCfg<BN, TWOP>::NTN][4]) {
    using C = TgCfg<BN, TWOP>;
    constexpr int NTN = C::NTN;
    const uint32_t sbB = sb + (uint32_t)C::B_OFF;
    const int i4 = lane >> 3;
    const int l8 = lane & 7;
#pragma unroll
    for (int ks = 0; ks < 2; ks++) {
        uint32_t bhf[NTN][2], blf[NTN][2];
#pragma unroll
        for (int nt = 0; nt < NTN; nt++) {
            int rowb = wn * C::WN + nt * 8 + l8;
            int chb  = ks * 2 + (i4 & 1);
            uint32_t bd = swz_addr(sbB, rowb, chb);
            ldsm2(bd, bhf[nt]);
            ldsm2(bd + (uint32_t)C::B_B, blf[nt]);
        }
#pragma unroll
        for (int mt = 0; mt < 4; mt++) {
            uint32_t ahf[4], alf[4];
            int row = wm * 64 + mt * 16 + (i4 & 1) * 8 + l8;
            int cha = ks * 2 + (i4 >> 1);
            uint32_t ad = swz_addr(sb, row, cha);
            ldsm4(ad, ahf);
            if (!TWOP) ldsm4(ad + (uint32_t)C::A_B, alf);
#pragma unroll
            for (int nt = 0; nt < NTN; nt++) {
                mma16816(acc[mt][nt], ahf, bhf[nt]);
                mma16816(acc[mt][nt], ahf, blf[nt]);
                if (!TWOP) mma16816(acc[mt][nt], alf, bhf[nt]);
            }
        }
    }
}

template <int EPI, int BN, bool TWOP>
__global__ void __launch_bounds__(256, 2) tgemm(
    const __half* __restrict__ Ah, const __half* __restrict__ Al, int lda, long long sA,
    const __half* __restrict__ Bh, const __half* __restrict__ Bl, int ldb, long long sB,
    float* __restrict__ Cf, __half* __restrict__ Ch, __half* __restrict__ Cl,
    int ldc, long long sC, const float* __restrict__ bias, int Kext, float oscale)
{
    using C = TgCfg<BN, TWOP>;
    constexpr int NTN = C::NTN;
    constexpr uint32_t STG = (uint32_t)C::STAGE;
    extern __shared__ char smraw[];
    const uint32_t sb0 = smem_u32(smraw);
    const int tid = threadIdx.x;
    const int lane = tid & 31, wid = tid >> 5;
    const int wm = wid & 1, wn = wid >> 1;
    const int z = blockIdx.z;

    long long aoff = sA * z;
    long long boff = sB * z;
    long long coff = sC * z;

    const __half* Ahp = Ah + aoff + (long long)blockIdx.x * 128 * lda;
    const __half* Alp = TWOP ? Ahp : (Al + aoff + (long long)blockIdx.x * 128 * lda);
    const __half* Bhp = Bh + boff + (long long)blockIdx.y * BN * ldb;
    const __half* Blp = Bl + boff + (long long)blockIdx.y * BN * ldb;

    float acc[4][NTN][4];
#pragma unroll
    for (int a = 0; a < 4; a++)
#pragma unroll
        for (int b = 0; b < NTN; b++)
#pragma unroll
            for (int c = 0; c < 4; c++) acc[a][b][c] = 0.f;

    const int NI = Kext >> 5;
    tg_load<BN, TWOP>(sb0, Ahp, Alp, lda, Bhp, Blp, ldb, 0, tid);
    CP_COMMIT();
    if (NI > 1) {
        tg_load<BN, TWOP>(sb0 + STG, Ahp, Alp, lda, Bhp, Blp, ldb, 32, tid);
        CP_COMMIT();
    }
    int sidx = 0;
    for (int it = 0; it < NI; it++) {
        if (it < NI - 1) CP_WAIT1(); else CP_WAIT0();
        __syncthreads();
        if (it + 2 < NI) {
            int ns = sidx + 2; if (ns >= 3) ns -= 3;
            tg_load<BN, TWOP>(sb0 + (uint32_t)ns * STG, Ahp, Alp, lda, Bhp, Blp, ldb,
                              (it + 2) << 5, tid);
            CP_COMMIT();
        }
        tg_compute<BN, TWOP>(sb0 + (uint32_t)sidx * STG, wm, wn, lane, acc);
        if (++sidx == 3) sidx = 0;
    }

    // epilogue
    const int q = lane >> 2;
    const int cp2 = (lane & 3) * 2;
    const int gc = blockIdx.y * BN + wn * C::WN;
#pragma unroll
    for (int mt = 0; mt < 4; mt++) {
#pragma unroll
        for (int nt = 0; nt < NTN; nt++) {
            const float* a = acc[mt][nt];
            int cc = gc + nt * 8 + cp2;
#pragma unroll
            for (int half = 0; half < 2; half++) {
                int rr = blockIdx.x * 128 + wm * 64 + mt * 16 + q + half * 8;
                float v0 = a[half * 2 + 0] * oscale;
                float v1 = a[half * 2 + 1] * oscale;
                long long o = coff + (long long)rr * ldc + cc;
                if (EPI == EPI_BIAS_RESID || EPI == EPI_BIAS_GELU || EPI == EPI_GELU_HI) {
                    v0 += bias[cc]; v1 += bias[cc + 1];
                }
                if (EPI == EPI_F32) {
                    *(float2*)(Cf + o) = make_float2(v0, v1);
                } else if (EPI == EPI_BIAS_RESID) {
                    float2 r = *(float2*)(Cf + o);
                    *(float2*)(Cf + o) = make_float2(v0 + r.x, v1 + r.y);
                } else {  // HILO / BIAS_GELU / GELU_HI
                    if (EPI == EPI_BIAS_GELU || EPI == EPI_GELU_HI) {
                        v0 = gelu_exact(v0); v1 = gelu_exact(v1);
                    }
                    __half h0 = __float2half_rn(v0), h1 = __float2half_rn(v1);
                    *(__half2*)(Ch + o) = __halves2half2(h0, h1);
                    if (EPI != EPI_GELU_HI) {
                        __half l0 = __float2half_rn(v0 - __half2float(h0));
                        __half l1 = __float2half_rn(v1 - __half2float(h1));
                        *(__half2*)(Cl + o) = __halves2half2(l0, l1);
                    }
                }
            }
        }
    }
}

// ===================== flash attention (fused QK^T + softmax + PV) =====================
constexpr int FA_SMEM = 65536;

DI uint32_t swz8(uint32_t base, int r, int c) {
    return base + (uint32_t)(r * 128 + ((c ^ (r & 7)) << 4));
}

__global__ void __launch_bounds__(256, 2) flash_kernel(
    const __half* __restrict__ qkh, const __half* __restrict__ qkl,
    const __half* __restrict__ vth, const __half* __restrict__ vtl,
    __half* __restrict__ ohp, __half* __restrict__ olp)
{
    extern __shared__ char smraw[];
    const uint32_t sb = smem_u32(smraw);
    const uint32_t qhS = sb, qlS = sb + 16384, khS = sb + 32768, klS = sb + 40960,
                   vhS = sb + 49152, vlS = sb + 57344;
    const int tid = threadIdx.x, lane = tid & 31, w = tid >> 5;
    const int bz = blockIdx.z, b = bz >> 4, h = bz & 15;
    const int hc = h * 64;
    const long long qrow0 = (long long)b * Tn + blockIdx.x * 128;
    const __half* Qh = qkh;
    const __half* Kh = qkh + (long long)BTn * Dn;
    const __half* Ql = qkl;
    const __half* Kl = qkl + (long long)BTn * Dn;

#pragma unroll
    for (int i = 0; i < 4; i++) {
        int cid = tid + i * 256;
        int r = cid >> 3, c = cid & 7;
        long long g = (qrow0 + r) * Dn + hc + c * 8;
        cp16(swz8(qhS, r, c), Qh + g);
        cp16(swz8(qlS, r, c), Ql + g);
    }
    CP_COMMIT();

    float oacc[8][4];
    float mrun[2] = {-3e38f, -3e38f}, lrun[2] = {0.f, 0.f};
#pragma unroll
    for (int e = 0; e < 8; e++)
#pragma unroll
        for (int i = 0; i < 4; i++) oacc[e][i] = 0.f;

    const int i4 = lane >> 3, l8 = lane & 7, sel = lane >> 3;
    const long long kvb = (long long)b * Tn;

    for (int j = 0; j < 8; j++) {
        __syncthreads();
#pragma unroll
        for (int i = 0; i < 2; i++) {
            int cid = tid + i * 256;
            int r = cid >> 3, c = cid & 7;
            long long gk = (kvb + j * 64 + r) * Dn + hc + c * 8;
            cp16(swz8(khS, r, c), Kh + gk);
            cp16(swz8(klS, r, c), Kl + gk);
            long long gv = ((long long)bz * 64 + r) * Tn + j * 64 + c * 8;
            cp16(swz8(vhS, r, c), vth + gv);
            cp16(swz8(vlS, r, c), vtl + gv);
        }
        CP_COMMIT();
        CP_WAIT0();
        __syncthreads();

        float sacc[8][4];
#pragma unroll
        for (int e = 0; e < 8; e++)
#pragma unroll
            for (int i = 0; i < 4; i++) sacc[e][i] = 0.f;
#pragma unroll
        for (int ks = 0; ks < 4; ks++) {
            uint32_t qf[4], qlf[4];
            {
                int row = w * 16 + (i4 & 1) * 8 + l8;
                int c = ks * 2 + (i4 >> 1);
                ldsm4(swz8(qhS, row, c), qf);
                ldsm4(swz8(qlS, row, c), qlf);
            }
#pragma unroll
            for (int np = 0; np < 4; np++) {
                uint32_t bh4[4], bl4[4];
                int row = np * 16 + ((sel >> 1) << 3) + l8;
                int c = ks * 2 + (sel & 1);
                ldsm4(swz8(khS, row, c), bh4);
                ldsm4(swz8(klS, row, c), bl4);
                mma16816(sacc[np * 2], qf, bh4);
                mma16816(sacc[np * 2], qf, bl4);
                mma16816(sacc[np * 2], qlf, bh4);
                mma16816(sacc[np * 2 + 1], qf, bh4 + 2);
                mma16816(sacc[np * 2 + 1], qf, bl4 + 2);
                mma16816(sacc[np * 2 + 1], qlf, bh4 + 2);
            }
        }
        float m0 = -3e38f, m1 = -3e38f;
#pragma unroll
        for (int e = 0; e < 8; e++) {
            m0 = fmaxf(m0, fmaxf(sacc[e][0], sacc[e][1]));
            m1 = fmaxf(m1, fmaxf(sacc[e][2], sacc[e][3]));
        }
        m0 = fmaxf(m0, __shfl_xor_sync(0xffffffffu, m0, 1));
        m0 = fmaxf(m0, __shfl_xor_sync(0xffffffffu, m0, 2));
        m1 = fmaxf(m1, __shfl_xor_sync(0xffffffffu, m1, 1));
        m1 = fmaxf(m1, __shfl_xor_sync(0xffffffffu, m1, 2));
        float mn0 = fmaxf(mrun[0], m0 * 0.125f);
        float mn1 = fmaxf(mrun[1], m1 * 0.125f);
        float cr0 = __expf(mrun[0] - mn0);
        float cr1 = __expf(mrun[1] - mn1);
        mrun[0] = mn0; mrun[1] = mn1;
        float ls0 = 0.f, ls1 = 0.f;
#pragma unroll
        for (int e = 0; e < 8; e++) {
            sacc[e][0] = __expf(fmaf(sacc[e][0], 0.125f, -mn0));
            sacc[e][1] = __expf(fmaf(sacc[e][1], 0.125f, -mn0));
            sacc[e][2] = __expf(fmaf(sacc[e][2], 0.125f, -mn1));
            sacc[e][3] = __expf(fmaf(sacc[e][3], 0.125f, -mn1));
            ls0 += sacc[e][0] + sacc[e][1];
            ls1 += sacc[e][2] + sacc[e][3];
        }
        lrun[0] = lrun[0] * cr0 + ls0;
        lrun[1] = lrun[1] * cr1 + ls1;
#pragma unroll
        for (int e = 0; e < 8; e++) {
            oacc[e][0] *= cr0; oacc[e][1] *= cr0;
            oacc[e][2] *= cr1; oacc[e][3] *= cr1;
        }
#pragma unroll
        for (int kt = 0; kt < 4; kt++) {
            int t0 = kt * 2, t1 = kt * 2 + 1;
            __half2 h0 = __floats2half2_rn(sacc[t0][0], sacc[t0][1]);
            __half2 h1 = __floats2half2_rn(sacc[t0][2], sacc[t0][3]);
            __half2 h2 = __floats2half2_rn(sacc[t1][0], sacc[t1][1]);
            __half2 h3 = __floats2half2_rn(sacc[t1][2], sacc[t1][3]);
            uint32_t pa[4] = {h2u2(h0), h2u2(h1), h2u2(h2), h2u2(h3)};
            float2 f0 = __half22float2(h0), f1 = __half22float2(h1),
                   f2 = __half22float2(h2), f3 = __half22float2(h3);
            uint32_t pl[4] = {
                h2u2(__floats2half2_rn(sacc[t0][0] - f0.x, sacc[t0][1] - f0.y)),
                h2u2(__floats2half2_rn(sacc[t0][2] - f1.x, sacc[t0][3] - f1.y)),
                h2u2(__floats2half2_rn(sacc[t1][0] - f2.x, sacc[t1][1] - f2.y)),
                h2u2(__floats2half2_rn(sacc[t1][2] - f3.x, sacc[t1][3] - f3.y))};
#pragma unroll
            for (int ep = 0; ep < 4; ep++) {
                uint32_t vh4[4], vl4[4];
                int row = ep * 16 + ((sel >> 1) << 3) + l8;
                int c = kt * 2 + (sel & 1);
                ldsm4(swz8(vhS, row, c), vh4);
                ldsm4(swz8(vlS, row, c), vl4);
                mma16816(oacc[ep * 2], pa, vh4);
                mma16816(oacc[ep * 2], pa, vl4);
                mma16816(oacc[ep * 2], pl, vh4);
                mma16816(oacc[ep * 2 + 1], pa, vh4 + 2);
                mma16816(oacc[ep * 2 + 1], pa, vl4 + 2);
                mma16816(oacc[ep * 2 + 1], pl, vh4 + 2);
            }
        }
    }

    float l0 = lrun[0];
    l0 += __shfl_xor_sync(0xffffffffu, l0, 1);
    l0 += __shfl_xor_sync(0xffffffffu, l0, 2);
    float l1 = lrun[1];
    l1 += __shfl_xor_sync(0xffffffffu, l1, 1);
    l1 += __shfl_xor_sync(0xffffffffu, l1, 2);
    float inv0 = 1.0f / l0, inv1 = 1.0f / l1;
    long long bt0 = qrow0 + w * 16 + (lane >> 2);
    int colb = hc + (lane & 3) * 2;
#pragma unroll
    for (int e = 0; e < 8; e++) {
        long long o0 = bt0 * Dn + colb + e * 8;
        long long o1 = (bt0 + 8) * Dn + colb + e * 8;
        float v0 = oacc[e][0] * inv0, v1 = oacc[e][1] * inv0;
        float v2 = oacc[e][2] * inv1, v3 = oacc[e][3] * inv1;
        __half a0 = __float2half_rn(v0), a1 = __float2half_rn(v1);
        __half a2 = __float2half_rn(v2), a3 = __float2half_rn(v3);
        *(__half2*)(ohp + o0) = __halves2half2(a0, a1);
        *(__half2*)(ohp + o1) = __halves2half2(a2, a3);
        *(__half2*)(olp + o0) = __halves2half2(
            __float2half_rn(v0 - __half2float(a0)), __float2half_rn(v1 - __half2float(a1)));
        *(__half2*)(olp + o1) = __halves2half2(
            __float2half_rn(v2 - __half2float(a2)), __float2half_rn(v3 - __half2float(a3)));
    }
}

// ---- logits: 2-stage deterministic reduction ----
__global__ void logits_part(const float* __restrict__ hf, const float* __restrict__ Wout) {
    int b = blockIdx.x, c = blockIdx.y;
    const int CHUNK = Tn * Dn / 16;
    const float* hb = hf + (long long)b * Tn * Dn + c * CHUNK;
    const float* wb = Wout + ((long long)c * CHUNK) * NCn;
    float a[3] = {0.f, 0.f, 0.f};
    for (int i = threadIdx.x; i < CHUNK; i += blockDim.x) {
        float v = hb[i];
        const float* wr = wb + (long long)i * NCn;
        a[0] = fmaf(v, wr[0], a[0]);
        a[1] = fmaf(v, wr[1], a[1]);
        a[2] = fmaf(v, wr[2], a[2]);
    }
    __shared__ float sm[3][8];
    int w = threadIdx.x >> 5, ln = threadIdx.x & 31;
#pragma unroll
    for (int cc = 0; cc < 3; cc++) {
        float v = warp_sum(a[cc]);
        if (ln == 0) sm[cc][w] = v;
    }
    __syncthreads();
    if (threadIdx.x < 3) {
        float t = 0.f;
#pragma unroll
        for (int i = 0; i < 8; i++) t += sm[threadIdx.x][i];
        g_lpart[(b * 16 + c) * NCn + threadIdx.x] = t;
    }
}
__global__ void logits_final(const float* __restrict__ bout, float* __restrict__ out) {
    int t = threadIdx.x;
    if (t >= Bn * NCn) return;
    int b = t / NCn, c = t % NCn;
    float s = bout[c];
#pragma unroll
    for (int i = 0; i < 16; i++) s += g_lpart[(b * 16 + i) * NCn + c];
    out[b * NCn + c] = s;
}

}  // namespace enc

extern "C" void kernel_launch(void* const* d_in, const int* in_sizes, int n_in,
                              void* d_out, int out_size) {
    using namespace enc;
    (void)in_sizes; (void)n_in; (void)out_size;

    const int*   x     = (const int*)d_in[0];
    const float* tok   = (const float*)d_in[1];
    const float* pos   = (const float*)d_in[2];
    const float* Wq    = (const float*)d_in[3];
    const float* Wk    = (const float*)d_in[4];
    const float* Wv    = (const float*)d_in[5];
    const float* Wproj = (const float*)d_in[6];
    const float* bproj = (const float*)d_in[7];
    const float* ln1g  = (const float*)d_in[8];
    const float* ln1b  = (const float*)d_in[9];
    const float* ln2g  = (const float*)d_in[10];
    const float* ln2b  = (const float*)d_in[11];
    const float* W1    = (const float*)d_in[12];
    const float* b1    = (const float*)d_in[13];
    const float* W2    = (const float*)d_in[14];
    const float* b2    = (const float*)d_in[15];
    const float* lnfg  = (const float*)d_in[16];
    const float* lnfb  = (const float*)d_in[17];
    const float* Wout  = (const float*)d_in[18];
    const float* bout  = (const float*)d_in[19];
    float* out = (float*)d_out;

    static float *ph = nullptr, *pz;
    static __half *zh, *zl, *qh, *ql, *vth, *vtl, *fh;
    static __half *wqh, *wql, *wph, *wpl, *w1h, *w1l, *w2h, *w2l;
    if (!ph) {
        cudaGetSymbolAddress((void**)&ph,   g_h);
        cudaGetSymbolAddress((void**)&pz,   g_z);
        cudaGetSymbolAddress((void**)&zh, g_zh);
        cudaGetSymbolAddress((void**)&zl, g_zl);
        cudaGetSymbolAddress((void**)&qh, g_qkvh);
        cudaGetSymbolAddress((void**)&ql, g_qkvl);
        cudaGetSymbolAddress((void**)&vth, g_vth);
        cudaGetSymbolAddress((void**)&vtl, g_vtl);
        cudaGetSymbolAddress((void**)&fh, g_ffnh);
        cudaGetSymbolAddress((void**)&wqh, g_wqkv_h);
        cudaGetSymbolAddress((void**)&wql, g_wqkv_l);
        cudaGetSymbolAddress((void**)&wph, g_wproj_h);
        cudaGetSymbolAddress((void**)&wpl, g_wproj_l);
        cudaGetSymbolAddress((void**)&w1h, g_w1_h);
        cudaGetSymbolAddress((void**)&w1l, g_w1_l);
        cudaGetSymbolAddress((void**)&w2h, g_w2_h);
        cudaGetSymbolAddress((void**)&w2l, g_w2_l);
        cudaFuncSetAttribute((const void*)tgemm<EPI_HILO, 128, false>,
                             cudaFuncAttributeMaxDynamicSharedMemorySize,
                             TgCfg<128, false>::SMEM);
        cudaFuncSetAttribute((const void*)tgemm<EPI_BIAS_RESID, 128, false>,
                             cudaFuncAttributeMaxDynamicSharedMemorySize,
                             TgCfg<128, false>::SMEM);
        cudaFuncSetAttribute((const void*)tgemm<EPI_GELU_HI, 128, true>,
                             cudaFuncAttributeMaxDynamicSharedMemorySize,
                             TgCfg<128, true>::SMEM);
        cudaFuncSetAttribute((const void*)tgemm<EPI_BIAS_RESID, 128, true>,
                             cudaFuncAttributeMaxDynamicSharedMemorySize,
                             TgCfg<128, true>::SMEM);
        cudaFuncSetAttribute((const void*)flash_kernel,
                             cudaFuncAttributeMaxDynamicSharedMemorySize, FA_SMEM);
    }

    // ---- prep needed for layer-0 front (W1/W2 prep deferred so ncu lands on tgemm) ----
    wprep_qkv<<<dim3(Dn / 32, HSn / 32, Ln * 3 * Hn), dim3(32, 8)>>>(Wq, Wk, Wv);
    wprep_lin<<<dim3(Dn / 32, Dn / 32, Ln),   dim3(32, 8)>>>(Wproj, wph, wpl, Dn, Dn);

    for (int l = 0; l < Ln; l++) {
        // z = LN1(h) -> hi/lo (layer 0 fuses the embedding gather)
        if (l == 0)
            ln_kernel<true, true, true><<<BTn, 256>>>(nullptr, ln1g, ln1b, nullptr, zh, zl,
                                                      x, tok, pos);
        else
            ln_kernel<true, false, true><<<BTn, 256>>>(ph, ln1g + l * Dn, ln1b + l * Dn,
                                                       nullptr, zh, zl,
                                                       nullptr, nullptr, nullptr);
        // q,k,v = z @ W -> hi/lo fp16 (3-pass)
        tgemm<EPI_HILO, 128, false>
            <<<dim3(BTn / 128, Dn / 128, 3), 256, TgCfg<128, false>::SMEM>>>(
                zh, zl, Dn, 0LL,
                wqh + (long long)l * 3 * Dn * Dn, wql + (long long)l * 3 * Dn * Dn, Dn,
                (long long)Dn * Dn,
                nullptr, qh, ql, Dn, (long long)BTn * Dn, nullptr, Dn, INV_WSCALE);
        // V^T hi/lo
        vtrans_kernel<<<dim3(Tn / 32, HSn / 32, Bn * Hn), dim3(32, 8)>>>(
            qh + 2LL * BTn * Dn, ql + 2LL * BTn * Dn, vth, vtl);
        // fused attention -> o hi/lo in zh/zl
        flash_kernel<<<dim3(Tn / 128, 1, Bn * Hn), 256, FA_SMEM>>>(
            qh, ql, vth, vtl, zh, zl);
        // h += o @ Wproj + bproj (3-pass)
        tgemm<EPI_BIAS_RESID, 128, false>
            <<<dim3(BTn / 128, Dn / 128, 1), 256, TgCfg<128, false>::SMEM>>>(
                zh, zl, Dn, 0LL,
                wph + (long long)l * Dn * Dn, wpl + (long long)l * Dn * Dn, Dn, 0LL,
                ph, nullptr, nullptr, Dn, 0LL, bproj + l * Dn, Dn, INV_WSCALE);
        // deferred FFN weight prep (once, before first FFN use)
        if (l == 0) {
            wprep_lin<<<dim3(Dn / 32, DFFn / 32, Ln), dim3(32, 8)>>>(W1, w1h, w1l, Dn, DFFn);
            wprep_lin<<<dim3(DFFn / 32, Dn / 32, Ln), dim3(32, 8)>>>(W2, w2h, w2l, DFFn, Dn);
        }
        // z = LN2(h) -> hi only (FFN1 is 2-pass)
        ln_kernel<true, false, false><<<BTn, 256>>>(ph, ln2g + l * Dn, ln2b + l * Dn,
                                                    nullptr, zh, nullptr,
                                                    nullptr, nullptr, nullptr);
        // ffn = gelu(z @ W1 + b1) -> hi only (2-pass)
        tgemm<EPI_GELU_HI, 128, true>
            <<<dim3(BTn / 128, DFFn / 128, 1), 256, TgCfg<128, true>::SMEM>>>(
                zh, nullptr, Dn, 0LL,
                w1h + (long long)l * Dn * DFFn, w1l + (long long)l * Dn * DFFn, Dn, 0LL,
                nullptr, fh, nullptr, DFFn, 0LL, b1 + l * DFFn, Dn, INV_WSCALE);
        // h += ffn @ W2 + b2 (2-pass)
        tgemm<EPI_BIAS_RESID, 128, true>
            <<<dim3(BTn / 128, Dn / 128, 1), 256, TgCfg<128, true>::SMEM>>>(
                fh, nullptr, DFFn, 0LL,
                w2h + (long long)l * DFFn * Dn, w2l + (long long)l * DFFn * Dn, DFFn, 0LL,
                ph, nullptr, nullptr, Dn, 0LL, b2 + l * Dn, DFFn, INV_WSCALE);
    }
    ln_kernel<false, false, false><<<BTn, 256>>>(ph, lnfg, lnfb, pz, nullptr, nullptr,
                                                 nullptr, nullptr, nullptr);
    logits_part<<<dim3(Bn, 16), 256>>>(pz, Wout);
    logits_final<<<1, 64>>>(bout, out);
}

// round 11
// speedup vs baseline: 4.1440x; 1.1170x over previous
#include <cuda_runtime.h>
#include <cuda_fp16.h>
#include <cuda_bf16.h>
#include <math.h>
#include <stdint.h>

#define DI __device__ __forceinline__

// ===================== portable PTX helpers (plain sm_103) =====================
DI uint32_t smem_u32(const void* p) {
    uint32_t a;
    asm("{ .reg .u64 t; cvta.to.shared.u64 t, %1; cvt.u32.u64 %0, t; }" : "=r"(a) : "l"(p));
    return a;
}
DI void cp16(uint32_t d, const void* s) {
    asm volatile("cp.async.cg.shared.global [%0], [%1], 16;" :: "r"(d), "l"(s) : "memory");
}
#define CP_COMMIT() asm volatile("cp.async.commit_group;" ::: "memory")
#define CP_WAIT1()  asm volatile("cp.async.wait_group 1;" ::: "memory")
#define CP_WAIT0()  asm volatile("cp.async.wait_group 0;" ::: "memory")

DI void ldsm4(uint32_t addr, uint32_t* r) {
    asm volatile("ldmatrix.sync.aligned.m8n8.x4.shared.b16 {%0,%1,%2,%3}, [%4];"
                 : "=r"(r[0]), "=r"(r[1]), "=r"(r[2]), "=r"(r[3]) : "r"(addr));
}
DI void ldsm2(uint32_t addr, uint32_t* r) {
    asm volatile("ldmatrix.sync.aligned.m8n8.x2.shared.b16 {%0,%1}, [%2];"
                 : "=r"(r[0]), "=r"(r[1]) : "r"(addr));
}
DI void mma16816(float* c, const uint32_t* a, const uint32_t* b) {
    asm volatile("mma.sync.aligned.m16n8k16.row.col.f32.f16.f16.f32 "
                 "{%0,%1,%2,%3},{%4,%5,%6,%7},{%8,%9},{%0,%1,%2,%3};"
                 : "+f"(c[0]), "+f"(c[1]), "+f"(c[2]), "+f"(c[3])
                 : "r"(a[0]), "r"(a[1]), "r"(a[2]), "r"(a[3]), "r"(b[0]), "r"(b[1]));
}

namespace enc {

constexpr int Bn = 16, Tn = 512, Dn = 1024, Hn = 16, HSn = 64, Ln = 4, DFFn = 4096, NCn = 3;
constexpr int BTn = Bn * Tn;  // 8192
constexpr float WSCALE = 64.0f;
constexpr float INV_WSCALE = 1.0f / 64.0f;

// ---- scratch ----
__device__ __align__(16) float g_h  [(size_t)BTn * Dn];
__device__ __align__(16) float g_z  [(size_t)BTn * Dn];
__device__ __align__(16) float g_lpart[Bn * 16 * NCn];
// activations hi/lo fp16
__device__ __align__(16) __half g_zh  [(size_t)BTn * Dn];
__device__ __align__(16) __half g_qkvh[(size_t)3 * BTn * Dn];
__device__ __align__(16) __half g_qkvl[(size_t)3 * BTn * Dn];
__device__ __align__(16) __half g_vth [(size_t)BTn * Dn];
__device__ __align__(16) __half g_vtl [(size_t)BTn * Dn];
__device__ __align__(16) __half g_ffnh[(size_t)BTn * DFFn];
// fp16 hi/lo weights, [N,K] layout, scaled by 64
__device__ __align__(16) __half g_wqkv_h[(size_t)Ln * 3 * Dn * Dn];
__device__ __align__(16) __half g_wqkv_l[(size_t)Ln * 3 * Dn * Dn];
__device__ __align__(16) __half g_wproj_h[(size_t)Ln * Dn * Dn];
__device__ __align__(16) __half g_wproj_l[(size_t)Ln * Dn * Dn];
__device__ __align__(16) __half g_w1_h[(size_t)Ln * Dn * DFFn];
__device__ __align__(16) __half g_w1_l[(size_t)Ln * Dn * DFFn];
__device__ __align__(16) __half g_w2_h[(size_t)Ln * DFFn * Dn];
__device__ __align__(16) __half g_w2_l[(size_t)Ln * DFFn * Dn];

DI float warp_sum(float v) {
#pragma unroll
    for (int o = 16; o > 0; o >>= 1) v += __shfl_xor_sync(0xffffffffu, v, o);
    return v;
}
DI float gelu_exact(float x) {
    return 0.5f * x * (1.0f + erff(x * 0.70710678118654752440f));
}
DI uint32_t h2u2(__half2 h) { return *reinterpret_cast<uint32_t*>(&h); }

// ---- layernorm; EMB fuses embedding; HILO writes hi fp16 ----
template <bool HILO, bool EMB>
__global__ void ln_kernel(const float* __restrict__ in, const float* __restrict__ gw,
                          const float* __restrict__ bw, float* __restrict__ outf,
                          __half* __restrict__ oh,
                          const int* __restrict__ xi, const float* __restrict__ tok,
                          const float* __restrict__ pos) {
    long long row = blockIdx.x;
    int tid = threadIdx.x;
    float4 x4;
    if (EMB) {
        int t = (int)(row & (Tn - 1));
        int tk = xi[row];
        float4 a = *(const float4*)(tok + (long long)tk * Dn + tid * 4);
        float4 p = *(const float4*)(pos + (long long)t * Dn + tid * 4);
        x4.x = a.x + p.x; x4.y = a.y + p.y; x4.z = a.z + p.z; x4.w = a.w + p.w;
        *(float4*)(g_h + row * Dn + tid * 4) = x4;   // residual stream
    } else {
        x4 = *(const float4*)(in + row * Dn + tid * 4);
    }
    float s  = x4.x + x4.y + x4.z + x4.w;
    float s2 = x4.x * x4.x + x4.y * x4.y + x4.z * x4.z + x4.w * x4.w;
    s = warp_sum(s); s2 = warp_sum(s2);
    __shared__ float sh[2][8];
    int w = tid >> 5;
    if ((tid & 31) == 0) { sh[0][w] = s; sh[1][w] = s2; }
    __syncthreads();
    float ts = 0.f, ts2 = 0.f;
#pragma unroll
    for (int i = 0; i < 8; i++) { ts += sh[0][i]; ts2 += sh[1][i]; }
    float mu = ts * (1.0f / Dn);
    float var = ts2 * (1.0f / Dn) - mu * mu;
    float rinv = rsqrtf(var + 1e-5f);
    float4 g4 = *(const float4*)(gw + tid * 4);
    float4 b4 = *(const float4*)(bw + tid * 4);
    float v[4];
    v[0] = (x4.x - mu) * rinv * g4.x + b4.x;
    v[1] = (x4.y - mu) * rinv * g4.y + b4.y;
    v[2] = (x4.z - mu) * rinv * g4.z + b4.z;
    v[3] = (x4.w - mu) * rinv * g4.w + b4.w;
    if (HILO) {
        __half h[4];
#pragma unroll
        for (int i = 0; i < 4; i++) h[i] = __float2half_rn(v[i]);
        long long o = row * Dn + tid * 4;
        *(__half2*)(oh + o)     = __halves2half2(h[0], h[1]);
        *(__half2*)(oh + o + 2) = __halves2half2(h[2], h[3]);
    } else {
        *(float4*)(outf + row * Dn + tid * 4) = make_float4(v[0], v[1], v[2], v[3]);
    }
}

// ---- weight prep: transpose [K,N] -> hi/lo fp16 [N,K], scale by 64 ----
__global__ void wprep_lin(const float* __restrict__ src, __half* __restrict__ dh,
                          __half* __restrict__ dl, int K, int N) {
    int l = blockIdx.z;
    src += (long long)l * K * N;
    dh += (long long)l * N * K;
    dl += (long long)l * N * K;
    __shared__ float t[32][33];
    int k0 = blockIdx.x * 32, n0 = blockIdx.y * 32;
    int tx = threadIdx.x, ty = threadIdx.y;
#pragma unroll
    for (int j = 0; j < 4; j++)
        t[ty + 8 * j][tx] = src[(long long)(k0 + ty + 8 * j) * N + n0 + tx];
    __syncthreads();
#pragma unroll
    for (int j = 0; j < 4; j++) {
        float v = t[tx][ty + 8 * j] * WSCALE;
        __half h = __float2half_rn(v);
        __half lo = __float2half_rn(v - __half2float(h));
        long long o = (long long)(n0 + ty + 8 * j) * K + k0 + tx;
        dh[o] = h; dl[o] = lo;
    }
}

// ---- qkv weight prep: [L,H,D,HS] -> [N=H*HS, K=D] hi/lo ----
__global__ void wprep_qkv(const float* __restrict__ Wq, const float* __restrict__ Wk,
                          const float* __restrict__ Wv) {
    int z = blockIdx.z;
    int h = z & 15, which = (z >> 4) % 3, l = z / 48;
    const float* W = which == 0 ? Wq : (which == 1 ? Wk : Wv);
    const float* src = W + ((long long)(l * Hn + h) * Dn) * HSn;
    long long base = ((long long)(l * 3 + which)) * Dn * Dn;
    __shared__ float t[32][33];
    int k0 = blockIdx.x * 32, n0 = blockIdx.y * 32;
    int tx = threadIdx.x, ty = threadIdx.y;
#pragma unroll
    for (int j = 0; j < 4; j++)
        t[ty + 8 * j][tx] = src[(long long)(k0 + ty + 8 * j) * HSn + n0 + tx];
    __syncthreads();
#pragma unroll
    for (int j = 0; j < 4; j++) {
        float v = t[tx][ty + 8 * j] * WSCALE;
        __half h2 = __float2half_rn(v);
        __half lo = __float2half_rn(v - __half2float(h2));
        long long o = base + (long long)(h * HSn + n0 + ty + 8 * j) * Dn + k0 + tx;
        g_wqkv_h[o] = h2; g_wqkv_l[o] = lo;
    }
}

// ---- V transpose: [b*T+t, h*64+e] fp16 hi/lo -> [bh, e, t] ----
__global__ void vtrans_kernel(const __half* __restrict__ vh, const __half* __restrict__ vl,
                              __half* __restrict__ oth, __half* __restrict__ otl) {
    int bh = blockIdx.z, b = bh >> 4, h = bh & 15;
    int t0 = blockIdx.x * 32, e0 = blockIdx.y * 32;
    __shared__ __half sh[32][34], sl[32][34];
    int tx = threadIdx.x, ty = threadIdx.y;
#pragma unroll
    for (int j = 0; j < 4; j++) {
        long long gi = ((long long)(b * Tn + t0 + ty + 8 * j)) * Dn + h * HSn + e0 + tx;
        sh[ty + 8 * j][tx] = vh[gi];
        sl[ty + 8 * j][tx] = vl[gi];
    }
    __syncthreads();
#pragma unroll
    for (int j = 0; j < 4; j++) {
        long long go = ((long long)bh * HSn + e0 + ty + 8 * j) * Tn + t0 + tx;
        oth[go] = sh[tx][ty + 8 * j];
        otl[go] = sl[tx][ty + 8 * j];
    }
}

// ===================== mma.sync fp16-split GEMM (2-pass: Ah x (Bh+Bl)) ========
enum { EPI_F32 = 0, EPI_HILO = 1, EPI_BIAS_RESID = 2, EPI_BIAS_GELU = 3, EPI_GELU_HI = 4 };

// 64B rows + chunk swizzle; stage: Ah | Bh | Bl
template <int BN> struct TgCfg {
    static constexpr int A_B = 128 * 64;                 // 8192
    static constexpr int B_B = BN * 64;
    static constexpr int B_OFF = A_B;
    static constexpr int STAGE = A_B + 2 * B_B;
    static constexpr int SMEM = 3 * STAGE;
    static constexpr int WN = BN / 4;
    static constexpr int NTN = WN / 8;
};

DI uint32_t swz_addr(uint32_t base, int r, int ch) {
    return base + (uint32_t)(r * 64 + ((ch ^ ((r >> 1) & 3)) << 4));
}

template <int BN>
DI void tg_load(uint32_t sd, const __half* __restrict__ Ahp, int lda,
                const __half* __restrict__ Bhp, const __half* __restrict__ Blp,
                int ldb, int k0, int tid) {
    using C = TgCfg<BN>;
#pragma unroll
    for (int j = 0; j < 2; j++) {
        int cid = tid + j * 256;
        int r = cid >> 2;
        int ch = cid & 3;
        uint32_t d = swz_addr(sd, r, ch);
        long long go = (long long)r * lda + k0 + ch * 8;
        cp16(d, Ahp + go);
    }
#pragma unroll
    for (int j = 0; j < BN / 64; j++) {
        int cid = tid + j * 256;
        int r = cid >> 2;
        int ch = cid & 3;
        uint32_t d = swz_addr(sd + (uint32_t)C::B_OFF, r, ch);
        long long go = (long long)r * ldb + k0 + ch * 8;
        cp16(d, Bhp + go);
        cp16(d + (uint32_t)C::B_B, Blp + go);
    }
}

template <int BN>
DI void tg_compute(uint32_t sb, int wm, int wn, int lane,
                   float acc[4][TgCfg<BN>::NTN][4]) {
    using C = TgCfg<BN>;
    constexpr int NTN = C::NTN;
    const uint32_t sbB = sb + (uint32_t)C::B_OFF;
    const int i4 = lane >> 3;
    const int l8 = lane & 7;
#pragma unroll
    for (int ks = 0; ks < 2; ks++) {
        uint32_t bhf[NTN][2], blf[NTN][2];
#pragma unroll
        for (int nt = 0; nt < NTN; nt++) {
            int rowb = wn * C::WN + nt * 8 + l8;
            int chb  = ks * 2 + (i4 & 1);
            uint32_t bd = swz_addr(sbB, rowb, chb);
            ldsm2(bd, bhf[nt]);
            ldsm2(bd + (uint32_t)C::B_B, blf[nt]);
        }
#pragma unroll
        for (int mt = 0; mt < 4; mt++) {
            uint32_t ahf[4];
            int row = wm * 64 + mt * 16 + (i4 & 1) * 8 + l8;
            int cha = ks * 2 + (i4 >> 1);
            uint32_t ad = swz_addr(sb, row, cha);
            ldsm4(ad, ahf);
#pragma unroll
            for (int nt = 0; nt < NTN; nt++) {
                mma16816(acc[mt][nt], ahf, bhf[nt]);
                mma16816(acc[mt][nt], ahf, blf[nt]);
            }
        }
    }
}

template <int EPI, int BN>
__global__ void __launch_bounds__(256, 2) tgemm(
    const __half* __restrict__ Ah, int lda, long long sA,
    const __half* __restrict__ Bh, const __half* __restrict__ Bl, int ldb, long long sB,
    float* __restrict__ Cf, __half* __restrict__ Ch, __half* __restrict__ Cl,
    int ldc, long long sC, const float* __restrict__ bias, int Kext, float oscale)
{
    using C = TgCfg<BN>;
    constexpr int NTN = C::NTN;
    constexpr uint32_t STG = (uint32_t)C::STAGE;
    extern __shared__ char smraw[];
    const uint32_t sb0 = smem_u32(smraw);
    const int tid = threadIdx.x;
    const int lane = tid & 31, wid = tid >> 5;
    const int wm = wid & 1, wn = wid >> 1;
    const int z = blockIdx.z;

    long long aoff = sA * z;
    long long boff = sB * z;
    long long coff = sC * z;

    const __half* Ahp = Ah + aoff + (long long)blockIdx.x * 128 * lda;
    const __half* Bhp = Bh + boff + (long long)blockIdx.y * BN * ldb;
    const __half* Blp = Bl + boff + (long long)blockIdx.y * BN * ldb;

    float acc[4][NTN][4];
#pragma unroll
    for (int a = 0; a < 4; a++)
#pragma unroll
        for (int b = 0; b < NTN; b++)
#pragma unroll
            for (int c = 0; c < 4; c++) acc[a][b][c] = 0.f;

    const int NI = Kext >> 5;
    tg_load<BN>(sb0, Ahp, lda, Bhp, Blp, ldb, 0, tid);
    CP_COMMIT();
    if (NI > 1) {
        tg_load<BN>(sb0 + STG, Ahp, lda, Bhp, Blp, ldb, 32, tid);
        CP_COMMIT();
    }
    int sidx = 0;
    for (int it = 0; it < NI; it++) {
        if (it < NI - 1) CP_WAIT1(); else CP_WAIT0();
        __syncthreads();
        if (it + 2 < NI) {
            int ns = sidx + 2; if (ns >= 3) ns -= 3;
            tg_load<BN>(sb0 + (uint32_t)ns * STG, Ahp, lda, Bhp, Blp, ldb,
                        (it + 2) << 5, tid);
            CP_COMMIT();
        }
        tg_compute<BN>(sb0 + (uint32_t)sidx * STG, wm, wn, lane, acc);
        if (++sidx == 3) sidx = 0;
    }

    // epilogue
    const int q = lane >> 2;
    const int cp2 = (lane & 3) * 2;
    const int gc = blockIdx.y * BN + wn * C::WN;
#pragma unroll
    for (int mt = 0; mt < 4; mt++) {
#pragma unroll
        for (int nt = 0; nt < NTN; nt++) {
            const float* a = acc[mt][nt];
            int cc = gc + nt * 8 + cp2;
#pragma unroll
            for (int half = 0; half < 2; half++) {
                int rr = blockIdx.x * 128 + wm * 64 + mt * 16 + q + half * 8;
                float v0 = a[half * 2 + 0] * oscale;
                float v1 = a[half * 2 + 1] * oscale;
                long long o = coff + (long long)rr * ldc + cc;
                if (EPI == EPI_BIAS_RESID || EPI == EPI_BIAS_GELU || EPI == EPI_GELU_HI) {
                    v0 += bias[cc]; v1 += bias[cc + 1];
                }
                if (EPI == EPI_F32) {
                    *(float2*)(Cf + o) = make_float2(v0, v1);
                } else if (EPI == EPI_BIAS_RESID) {
                    float2 r = *(float2*)(Cf + o);
                    *(float2*)(Cf + o) = make_float2(v0 + r.x, v1 + r.y);
                } else {  // HILO / BIAS_GELU / GELU_HI
                    if (EPI == EPI_BIAS_GELU || EPI == EPI_GELU_HI) {
                        v0 = gelu_exact(v0); v1 = gelu_exact(v1);
                    }
                    __half h0 = __float2half_rn(v0), h1 = __float2half_rn(v1);
                    *(__half2*)(Ch + o) = __halves2half2(h0, h1);
                    if (EPI != EPI_GELU_HI) {
                        __half l0 = __float2half_rn(v0 - __half2float(h0));
                        __half l1 = __float2half_rn(v1 - __half2float(h1));
                        *(__half2*)(Cl + o) = __halves2half2(l0, l1);
                    }
                }
            }
        }
    }
}

// ===================== flash attention (fused QK^T + softmax + PV) =====================
// attention stays full 3-pass hi/lo internally; output hi only (proj is 2-pass)
constexpr int FA_SMEM = 65536;

DI uint32_t swz8(uint32_t base, int r, int c) {
    return base + (uint32_t)(r * 128 + ((c ^ (r & 7)) << 4));
}

__global__ void __launch_bounds__(256, 2) flash_kernel(
    const __half* __restrict__ qkh, const __half* __restrict__ qkl,
    const __half* __restrict__ vth, const __half* __restrict__ vtl,
    __half* __restrict__ ohp)
{
    extern __shared__ char smraw[];
    const uint32_t sb = smem_u32(smraw);
    const uint32_t qhS = sb, qlS = sb + 16384, khS = sb + 32768, klS = sb + 40960,
                   vhS = sb + 49152, vlS = sb + 57344;
    const int tid = threadIdx.x, lane = tid & 31, w = tid >> 5;
    const int bz = blockIdx.z, b = bz >> 4, h = bz & 15;
    const int hc = h * 64;
    const long long qrow0 = (long long)b * Tn + blockIdx.x * 128;
    const __half* Qh = qkh;
    const __half* Kh = qkh + (long long)BTn * Dn;
    const __half* Ql = qkl;
    const __half* Kl = qkl + (long long)BTn * Dn;

#pragma unroll
    for (int i = 0; i < 4; i++) {
        int cid = tid + i * 256;
        int r = cid >> 3, c = cid & 7;
        long long g = (qrow0 + r) * Dn + hc + c * 8;
        cp16(swz8(qhS, r, c), Qh + g);
        cp16(swz8(qlS, r, c), Ql + g);
    }
    CP_COMMIT();

    float oacc[8][4];
    float mrun[2] = {-3e38f, -3e38f}, lrun[2] = {0.f, 0.f};
#pragma unroll
    for (int e = 0; e < 8; e++)
#pragma unroll
        for (int i = 0; i < 4; i++) oacc[e][i] = 0.f;

    const int i4 = lane >> 3, l8 = lane & 7, sel = lane >> 3;
    const long long kvb = (long long)b * Tn;

    for (int j = 0; j < 8; j++) {
        __syncthreads();
#pragma unroll
        for (int i = 0; i < 2; i++) {
            int cid = tid + i * 256;
            int r = cid >> 3, c = cid & 7;
            long long gk = (kvb + j * 64 + r) * Dn + hc + c * 8;
            cp16(swz8(khS, r, c), Kh + gk);
            cp16(swz8(klS, r, c), Kl + gk);
            long long gv = ((long long)bz * 64 + r) * Tn + j * 64 + c * 8;
            cp16(swz8(vhS, r, c), vth + gv);
            cp16(swz8(vlS, r, c), vtl + gv);
        }
        CP_COMMIT();
        CP_WAIT0();
        __syncthreads();

        float sacc[8][4];
#pragma unroll
        for (int e = 0; e < 8; e++)
#pragma unroll
            for (int i = 0; i < 4; i++) sacc[e][i] = 0.f;
#pragma unroll
        for (int ks = 0; ks < 4; ks++) {
            uint32_t qf[4], qlf[4];
            {
                int row = w * 16 + (i4 & 1) * 8 + l8;
                int c = ks * 2 + (i4 >> 1);
                ldsm4(swz8(qhS, row, c), qf);
                ldsm4(swz8(qlS, row, c), qlf);
            }
#pragma unroll
            for (int np = 0; np < 4; np++) {
                uint32_t bh4[4], bl4[4];
                int row = np * 16 + ((sel >> 1) << 3) + l8;
                int c = ks * 2 + (sel & 1);
                ldsm4(swz8(khS, row, c), bh4);
                ldsm4(swz8(klS, row, c), bl4);
                mma16816(sacc[np * 2], qf, bh4);
                mma16816(sacc[np * 2], qf, bl4);
                mma16816(sacc[np * 2], qlf, bh4);
                mma16816(sacc[np * 2 + 1], qf, bh4 + 2);
                mma16816(sacc[np * 2 + 1], qf, bl4 + 2);
                mma16816(sacc[np * 2 + 1], qlf, bh4 + 2);
            }
        }
        float m0 = -3e38f, m1 = -3e38f;
#pragma unroll
        for (int e = 0; e < 8; e++) {
            m0 = fmaxf(m0, fmaxf(sacc[e][0], sacc[e][1]));
            m1 = fmaxf(m1, fmaxf(sacc[e][2], sacc[e][3]));
        }
        m0 = fmaxf(m0, __shfl_xor_sync(0xffffffffu, m0, 1));
        m0 = fmaxf(m0, __shfl_xor_sync(0xffffffffu, m0, 2));
        m1 = fmaxf(m1, __shfl_xor_sync(0xffffffffu, m1, 1));
        m1 = fmaxf(m1, __shfl_xor_sync(0xffffffffu, m1, 2));
        float mn0 = fmaxf(mrun[0], m0 * 0.125f);
        float mn1 = fmaxf(mrun[1], m1 * 0.125f);
        float cr0 = __expf(mrun[0] - mn0);
        float cr1 = __expf(mrun[1] - mn1);
        mrun[0] = mn0; mrun[1] = mn1;
        float ls0 = 0.f, ls1 = 0.f;
#pragma unroll
        for (int e = 0; e < 8; e++) {
            sacc[e][0] = __expf(fmaf(sacc[e][0], 0.125f, -mn0));
            sacc[e][1] = __expf(fmaf(sacc[e][1], 0.125f, -mn0));
            sacc[e][2] = __expf(fmaf(sacc[e][2], 0.125f, -mn1));
            sacc[e][3] = __expf(fmaf(sacc[e][3], 0.125f, -mn1));
            ls0 += sacc[e][0] + sacc[e][1];
            ls1 += sacc[e][2] + sacc[e][3];
        }
        lrun[0] = lrun[0] * cr0 + ls0;
        lrun[1] = lrun[1] * cr1 + ls1;
#pragma unroll
        for (int e = 0; e < 8; e++) {
            oacc[e][0] *= cr0; oacc[e][1] *= cr0;
            oacc[e][2] *= cr1; oacc[e][3] *= cr1;
        }
#pragma unroll
        for (int kt = 0; kt < 4; kt++) {
            int t0 = kt * 2, t1 = kt * 2 + 1;
            __half2 h0 = __floats2half2_rn(sacc[t0][0], sacc[t0][1]);
            __half2 h1 = __floats2half2_rn(sacc[t0][2], sacc[t0][3]);
            __half2 h2 = __floats2half2_rn(sacc[t1][0], sacc[t1][1]);
            __half2 h3 = __floats2half2_rn(sacc[t1][2], sacc[t1][3]);
            uint32_t pa[4] = {h2u2(h0), h2u2(h1), h2u2(h2), h2u2(h3)};
            float2 f0 = __half22float2(h0), f1 = __half22float2(h1),
                   f2 = __half22float2(h2), f3 = __half22float2(h3);
            uint32_t pl[4] = {
                h2u2(__floats2half2_rn(sacc[t0][0] - f0.x, sacc[t0][1] - f0.y)),
                h2u2(__floats2half2_rn(sacc[t0][2] - f1.x, sacc[t0][3] - f1.y)),
                h2u2(__floats2half2_rn(sacc[t1][0] - f2.x, sacc[t1][1] - f2.y)),
                h2u2(__floats2half2_rn(sacc[t1][2] - f3.x, sacc[t1][3] - f3.y))};
#pragma unroll
            for (int ep = 0; ep < 4; ep++) {
                uint32_t vh4[4], vl4[4];
                int row = ep * 16 + ((sel >> 1) << 3) + l8;
                int c = kt * 2 + (sel & 1);
                ldsm4(swz8(vhS, row, c), vh4);
                ldsm4(swz8(vlS, row, c), vl4);
                mma16816(oacc[ep * 2], pa, vh4);
                mma16816(oacc[ep * 2], pa, vl4);
                mma16816(oacc[ep * 2], pl, vh4);
                mma16816(oacc[ep * 2 + 1], pa, vh4 + 2);
                mma16816(oacc[ep * 2 + 1], pa, vl4 + 2);
                mma16816(oacc[ep * 2 + 1], pl, vh4 + 2);
            }
        }
    }

    float l0 = lrun[0];
    l0 += __shfl_xor_sync(0xffffffffu, l0, 1);
    l0 += __shfl_xor_sync(0xffffffffu, l0, 2);
    float l1 = lrun[1];
    l1 += __shfl_xor_sync(0xffffffffu, l1, 1);
    l1 += __shfl_xor_sync(0xffffffffu, l1, 2);
    float inv0 = 1.0f / l0, inv1 = 1.0f / l1;
    long long bt0 = qrow0 + w * 16 + (lane >> 2);
    int colb = hc + (lane & 3) * 2;
#pragma unroll
    for (int e = 0; e < 8; e++) {
        long long o0 = bt0 * Dn + colb + e * 8;
        long long o1 = (bt0 + 8) * Dn + colb + e * 8;
        *(__half2*)(ohp + o0) = __floats2half2_rn(oacc[e][0] * inv0, oacc[e][1] * inv0);
        *(__half2*)(ohp + o1) = __floats2half2_rn(oacc[e][2] * inv1, oacc[e][3] * inv1);
    }
}

// ---- logits: 2-stage deterministic reduction ----
__global__ void logits_part(const float* __restrict__ hf, const float* __restrict__ Wout) {
    int b = blockIdx.x, c = blockIdx.y;
    const int CHUNK = Tn * Dn / 16;
    const float* hb = hf + (long long)b * Tn * Dn + c * CHUNK;
    const float* wb = Wout + ((long long)c * CHUNK) * NCn;
    float a[3] = {0.f, 0.f, 0.f};
    for (int i = threadIdx.x; i < CHUNK; i += blockDim.x) {
        float v = hb[i];
        const float* wr = wb + (long long)i * NCn;
        a[0] = fmaf(v, wr[0], a[0]);
        a[1] = fmaf(v, wr[1], a[1]);
        a[2] = fmaf(v, wr[2], a[2]);
    }
    __shared__ float sm[3][8];
    int w = threadIdx.x >> 5, ln = threadIdx.x & 31;
#pragma unroll
    for (int cc = 0; cc < 3; cc++) {
        float v = warp_sum(a[cc]);
        if (ln == 0) sm[cc][w] = v;
    }
    __syncthreads();
    if (threadIdx.x < 3) {
        float t = 0.f;
#pragma unroll
        for (int i = 0; i < 8; i++) t += sm[threadIdx.x][i];
        g_lpart[(b * 16 + c) * NCn + threadIdx.x] = t;
    }
}
__global__ void logits_final(const float* __restrict__ bout, float* __restrict__ out) {
    int t = threadIdx.x;
    if (t >= Bn * NCn) return;
    int b = t / NCn, c = t % NCn;
    float s = bout[c];
#pragma unroll
    for (int i = 0; i < 16; i++) s += g_lpart[(b * 16 + i) * NCn + c];
    out[b * NCn + c] = s;
}

}  // namespace enc

extern "C" void kernel_launch(void* const* d_in, const int* in_sizes, int n_in,
                              void* d_out, int out_size) {
    using namespace enc;
    (void)in_sizes; (void)n_in; (void)out_size;

    const int*   x     = (const int*)d_in[0];
    const float* tok   = (const float*)d_in[1];
    const float* pos   = (const float*)d_in[2];
    const float* Wq    = (const float*)d_in[3];
    const float* Wk    = (const float*)d_in[4];
    const float* Wv    = (const float*)d_in[5];
    const float* Wproj = (const float*)d_in[6];
    const float* bproj = (const float*)d_in[7];
    const float* ln1g  = (const float*)d_in[8];
    const float* ln1b  = (const float*)d_in[9];
    const float* ln2g  = (const float*)d_in[10];
    const float* ln2b  = (const float*)d_in[11];
    const float* W1    = (const float*)d_in[12];
    const float* b1    = (const float*)d_in[13];
    const float* W2    = (const float*)d_in[14];
    const float* b2    = (const float*)d_in[15];
    const float* lnfg  = (const float*)d_in[16];
    const float* lnfb  = (const float*)d_in[17];
    const float* Wout  = (const float*)d_in[18];
    const float* bout  = (const float*)d_in[19];
    float* out = (float*)d_out;

    static float *ph = nullptr, *pz;
    static __half *zh, *qh, *ql, *vth, *vtl, *fh;
    static __half *wqh, *wql, *wph, *wpl, *w1h, *w1l, *w2h, *w2l;
    if (!ph) {
        cudaGetSymbolAddress((void**)&ph,   g_h);
        cudaGetSymbolAddress((void**)&pz,   g_z);
        cudaGetSymbolAddress((void**)&zh, g_zh);
        cudaGetSymbolAddress((void**)&qh, g_qkvh);
        cudaGetSymbolAddress((void**)&ql, g_qkvl);
        cudaGetSymbolAddress((void**)&vth, g_vth);
        cudaGetSymbolAddress((void**)&vtl, g_vtl);
        cudaGetSymbolAddress((void**)&fh, g_ffnh);
        cudaGetSymbolAddress((void**)&wqh, g_wqkv_h);
        cudaGetSymbolAddress((void**)&wql, g_wqkv_l);
        cudaGetSymbolAddress((void**)&wph, g_wproj_h);
        cudaGetSymbolAddress((void**)&wpl, g_wproj_l);
        cudaGetSymbolAddress((void**)&w1h, g_w1_h);
        cudaGetSymbolAddress((void**)&w1l, g_w1_l);
        cudaGetSymbolAddress((void**)&w2h, g_w2_h);
        cudaGetSymbolAddress((void**)&w2l, g_w2_l);
        cudaFuncSetAttribute((const void*)tgemm<EPI_HILO, 128>,
                             cudaFuncAttributeMaxDynamicSharedMemorySize, TgCfg<128>::SMEM);
        cudaFuncSetAttribute((const void*)tgemm<EPI_BIAS_RESID, 128>,
                             cudaFuncAttributeMaxDynamicSharedMemorySize, TgCfg<128>::SMEM);
        cudaFuncSetAttribute((const void*)tgemm<EPI_GELU_HI, 128>,
                             cudaFuncAttributeMaxDynamicSharedMemorySize, TgCfg<128>::SMEM);
        cudaFuncSetAttribute((const void*)flash_kernel,
                             cudaFuncAttributeMaxDynamicSharedMemorySize, FA_SMEM);
    }

    // ---- prep needed for layer-0 front (FFN prep deferred) ----
    wprep_qkv<<<dim3(Dn / 32, HSn / 32, Ln * 3 * Hn), dim3(32, 8)>>>(Wq, Wk, Wv);
    wprep_lin<<<dim3(Dn / 32, Dn / 32, Ln),   dim3(32, 8)>>>(Wproj, wph, wpl, Dn, Dn);

    for (int l = 0; l < Ln; l++) {
        // z = LN1(h) -> hi only (QKV is 2-pass)
        if (l == 0)
            ln_kernel<true, true><<<BTn, 256>>>(nullptr, ln1g, ln1b, nullptr, zh,
                                                x, tok, pos);
        else
            ln_kernel<true, false><<<BTn, 256>>>(ph, ln1g + l * Dn, ln1b + l * Dn,
                                                 nullptr, zh, nullptr, nullptr, nullptr);
        // q,k,v = z @ W -> hi/lo fp16 (2-pass; output split kept for 3-pass attention)
        tgemm<EPI_HILO, 128><<<dim3(BTn / 128, Dn / 128, 3), 256, TgCfg<128>::SMEM>>>(
            zh, Dn, 0LL,
            wqh + (long long)l * 3 * Dn * Dn, wql + (long long)l * 3 * Dn * Dn, Dn,
            (long long)Dn * Dn,
            nullptr, qh, ql, Dn, (long long)BTn * Dn, nullptr, Dn, INV_WSCALE);
        // V^T hi/lo
        vtrans_kernel<<<dim3(Tn / 32, HSn / 32, Bn * Hn), dim3(32, 8)>>>(
            qh + 2LL * BTn * Dn, ql + 2LL * BTn * Dn, vth, vtl);
        // fused attention -> o hi in zh (proj is 2-pass)
        flash_kernel<<<dim3(Tn / 128, 1, Bn * Hn), 256, FA_SMEM>>>(
            qh, ql, vth, vtl, zh);
        // h += o @ Wproj + bproj (2-pass)
        tgemm<EPI_BIAS_RESID, 128><<<dim3(BTn / 128, Dn / 128, 1), 256, TgCfg<128>::SMEM>>>(
            zh, Dn, 0LL,
            wph + (long long)l * Dn * Dn, wpl + (long long)l * Dn * Dn, Dn, 0LL,
            ph, nullptr, nullptr, Dn, 0LL, bproj + l * Dn, Dn, INV_WSCALE);
        // deferred FFN weight prep (once)
        if (l == 0) {
            wprep_lin<<<dim3(Dn / 32, DFFn / 32, Ln), dim3(32, 8)>>>(W1, w1h, w1l, Dn, DFFn);
            wprep_lin<<<dim3(DFFn / 32, Dn / 32, Ln), dim3(32, 8)>>>(W2, w2h, w2l, DFFn, Dn);
        }
        // z = LN2(h) -> hi only
        ln_kernel<true, false><<<BTn, 256>>>(ph, ln2g + l * Dn, ln2b + l * Dn,
                                             nullptr, zh, nullptr, nullptr, nullptr);
        // ffn = gelu(z @ W1 + b1) -> hi only (2-pass)
        tgemm<EPI_GELU_HI, 128><<<dim3(BTn / 128, DFFn / 128, 1), 256, TgCfg<128>::SMEM>>>(
            zh, Dn, 0LL,
            w1h + (long long)l * Dn * DFFn, w1l + (long long)l * Dn * DFFn, Dn, 0LL,
            nullptr, fh, nullptr, DFFn, 0LL, b1 + l * DFFn, Dn, INV_WSCALE);
        // h += ffn @ W2 + b2 (2-pass)
        tgemm<EPI_BIAS_RESID, 128><<<dim3(BTn / 128, Dn / 128, 1), 256, TgCfg<128>::SMEM>>>(
            fh, DFFn, 0LL,
            w2h + (long long)l * DFFn * Dn, w2l + (long long)l * DFFn * Dn, DFFn, 0LL,
            ph, nullptr, nullptr, Dn, 0LL, b2 + l * Dn, DFFn, INV_WSCALE);
    }
    ln_kernel<false, false><<<BTn, 256>>>(ph, lnfg, lnfb, pz, nullptr,
                                          nullptr, nullptr, nullptr);
    logits_part<<<dim3(Bn, 16), 256>>>(pz, Wout);
    logits_final<<<1, 64>>>(bout, out);
}

// round 12
// speedup vs baseline: 4.4464x; 1.0730x over previous
#include <cuda_runtime.h>
#include <cuda_fp16.h>
#include <cuda_bf16.h>
#include <math.h>
#include <stdint.h>

#define DI __device__ __forceinline__

// ===================== portable PTX helpers (plain sm_103) =====================
DI uint32_t smem_u32(const void* p) {
    uint32_t a;
    asm("{ .reg .u64 t; cvta.to.shared.u64 t, %1; cvt.u32.u64 %0, t; }" : "=r"(a) : "l"(p));
    return a;
}
DI void cp16(uint32_t d, const void* s) {
    asm volatile("cp.async.cg.shared.global [%0], [%1], 16;" :: "r"(d), "l"(s) : "memory");
}
#define CP_COMMIT() asm volatile("cp.async.commit_group;" ::: "memory")
#define CP_WAIT0()  asm volatile("cp.async.wait_group 0;" ::: "memory")

DI void ldsm4(uint32_t addr, uint32_t* r) {
    asm volatile("ldmatrix.sync.aligned.m8n8.x4.shared.b16 {%0,%1,%2,%3}, [%4];"
                 : "=r"(r[0]), "=r"(r[1]), "=r"(r[2]), "=r"(r[3]) : "r"(addr));
}
DI void ldsm2(uint32_t addr, uint32_t* r) {
    asm volatile("ldmatrix.sync.aligned.m8n8.x2.shared.b16 {%0,%1}, [%2];"
                 : "=r"(r[0]), "=r"(r[1]) : "r"(addr));
}
DI void mma16816(float* c, const uint32_t* a, const uint32_t* b) {
    asm volatile("mma.sync.aligned.m16n8k16.row.col.f32.f16.f16.f32 "
                 "{%0,%1,%2,%3},{%4,%5,%6,%7},{%8,%9},{%0,%1,%2,%3};"
                 : "+f"(c[0]), "+f"(c[1]), "+f"(c[2]), "+f"(c[3])
                 : "r"(a[0]), "r"(a[1]), "r"(a[2]), "r"(a[3]), "r"(b[0]), "r"(b[1]));
}

namespace enc {

constexpr int Bn = 16, Tn = 512, Dn = 1024, Hn = 16, HSn = 64, Ln = 4, DFFn = 4096, NCn = 3;
constexpr int BTn = Bn * Tn;  // 8192
constexpr float WSCALE = 64.0f;
constexpr float INV_WSCALE = 1.0f / 64.0f;

// ---- scratch ----
__device__ __align__(16) float g_h  [(size_t)BTn * Dn];
__device__ __align__(16) float g_z  [(size_t)BTn * Dn];
__device__ __align__(16) float g_lpart[Bn * 16 * NCn];
// activations hi/lo fp16
__device__ __align__(16) __half g_zh  [(size_t)BTn * Dn];
__device__ __align__(16) __half g_qkvh[(size_t)3 * BTn * Dn];
__device__ __align__(16) __half g_qkvl[(size_t)3 * BTn * Dn];
__device__ __align__(16) __half g_vth [(size_t)BTn * Dn];
__device__ __align__(16) __half g_vtl [(size_t)BTn * Dn];
__device__ __align__(16) __half g_ffnh[(size_t)BTn * DFFn];
// fp16 hi/lo weights, [N,K] layout, scaled by 64
__device__ __align__(16) __half g_wqkv_h[(size_t)Ln * 3 * Dn * Dn];
__device__ __align__(16) __half g_wqkv_l[(size_t)Ln * 3 * Dn * Dn];
__device__ __align__(16) __half g_wproj_h[(size_t)Ln * Dn * Dn];
__device__ __align__(16) __half g_wproj_l[(size_t)Ln * Dn * Dn];
__device__ __align__(16) __half g_w1_h[(size_t)Ln * Dn * DFFn];
__device__ __align__(16) __half g_w1_l[(size_t)Ln * Dn * DFFn];
__device__ __align__(16) __half g_w2_h[(size_t)Ln * DFFn * Dn];
__device__ __align__(16) __half g_w2_l[(size_t)Ln * DFFn * Dn];

DI float warp_sum(float v) {
#pragma unroll
    for (int o = 16; o > 0; o >>= 1) v += __shfl_xor_sync(0xffffffffu, v, o);
    return v;
}
DI float gelu_exact(float x) {
    return 0.5f * x * (1.0f + erff(x * 0.70710678118654752440f));
}
DI uint32_t h2u2(__half2 h) { return *reinterpret_cast<uint32_t*>(&h); }

// 128B rows, 8 chunk XOR swizzle (shared by tgemm + flash)
DI uint32_t swz8(uint32_t base, int r, int c) {
    return base + (uint32_t)(r * 128 + ((c ^ (r & 7)) << 4));
}

// ---- layernorm; EMB fuses embedding; HILO writes hi fp16 ----
template <bool HILO, bool EMB>
__global__ void ln_kernel(const float* __restrict__ in, const float* __restrict__ gw,
                          const float* __restrict__ bw, float* __restrict__ outf,
                          __half* __restrict__ oh,
                          const int* __restrict__ xi, const float* __restrict__ tok,
                          const float* __restrict__ pos) {
    long long row = blockIdx.x;
    int tid = threadIdx.x;
    float4 x4;
    if (EMB) {
        int t = (int)(row & (Tn - 1));
        int tk = xi[row];
        float4 a = *(const float4*)(tok + (long long)tk * Dn + tid * 4);
        float4 p = *(const float4*)(pos + (long long)t * Dn + tid * 4);
        x4.x = a.x + p.x; x4.y = a.y + p.y; x4.z = a.z + p.z; x4.w = a.w + p.w;
        *(float4*)(g_h + row * Dn + tid * 4) = x4;   // residual stream
    } else {
        x4 = *(const float4*)(in + row * Dn + tid * 4);
    }
    float s  = x4.x + x4.y + x4.z + x4.w;
    float s2 = x4.x * x4.x + x4.y * x4.y + x4.z * x4.z + x4.w * x4.w;
    s = warp_sum(s); s2 = warp_sum(s2);
    __shared__ float sh[2][8];
    int w = tid >> 5;
    if ((tid & 31) == 0) { sh[0][w] = s; sh[1][w] = s2; }
    __syncthreads();
    float ts = 0.f, ts2 = 0.f;
#pragma unroll
    for (int i = 0; i < 8; i++) { ts += sh[0][i]; ts2 += sh[1][i]; }
    float mu = ts * (1.0f / Dn);
    float var = ts2 * (1.0f / Dn) - mu * mu;
    float rinv = rsqrtf(var + 1e-5f);
    float4 g4 = *(const float4*)(gw + tid * 4);
    float4 b4 = *(const float4*)(bw + tid * 4);
    float v[4];
    v[0] = (x4.x - mu) * rinv * g4.x + b4.x;
    v[1] = (x4.y - mu) * rinv * g4.y + b4.y;
    v[2] = (x4.z - mu) * rinv * g4.z + b4.z;
    v[3] = (x4.w - mu) * rinv * g4.w + b4.w;
    if (HILO) {
        __half h[4];
#pragma unroll
        for (int i = 0; i < 4; i++) h[i] = __float2half_rn(v[i]);
        long long o = row * Dn + tid * 4;
        *(__half2*)(oh + o)     = __halves2half2(h[0], h[1]);
        *(__half2*)(oh + o + 2) = __halves2half2(h[2], h[3]);
    } else {
        *(float4*)(outf + row * Dn + tid * 4) = make_float4(v[0], v[1], v[2], v[3]);
    }
}

// ---- weight prep: transpose [K,N] -> hi/lo fp16 [N,K], scale by 64 ----
__global__ void wprep_lin(const float* __restrict__ src, __half* __restrict__ dh,
                          __half* __restrict__ dl, int K, int N) {
    int l = blockIdx.z;
    src += (long long)l * K * N;
    dh += (long long)l * N * K;
    dl += (long long)l * N * K;
    __shared__ float t[32][33];
    int k0 = blockIdx.x * 32, n0 = blockIdx.y * 32;
    int tx = threadIdx.x, ty = threadIdx.y;
#pragma unroll
    for (int j = 0; j < 4; j++)
        t[ty + 8 * j][tx] = src[(long long)(k0 + ty + 8 * j) * N + n0 + tx];
    __syncthreads();
#pragma unroll
    for (int j = 0; j < 4; j++) {
        float v = t[tx][ty + 8 * j] * WSCALE;
        __half h = __float2half_rn(v);
        __half lo = __float2half_rn(v - __half2float(h));
        long long o = (long long)(n0 + ty + 8 * j) * K + k0 + tx;
        dh[o] = h; dl[o] = lo;
    }
}

// ---- qkv weight prep: [L,H,D,HS] -> [N=H*HS, K=D] hi/lo ----
__global__ void wprep_qkv(const float* __restrict__ Wq, const float* __restrict__ Wk,
                          const float* __restrict__ Wv) {
    int z = blockIdx.z;
    int h = z & 15, which = (z >> 4) % 3, l = z / 48;
    const float* W = which == 0 ? Wq : (which == 1 ? Wk : Wv);
    const float* src = W + ((long long)(l * Hn + h) * Dn) * HSn;
    long long base = ((long long)(l * 3 + which)) * Dn * Dn;
    __shared__ float t[32][33];
    int k0 = blockIdx.x * 32, n0 = blockIdx.y * 32;
    int tx = threadIdx.x, ty = threadIdx.y;
#pragma unroll
    for (int j = 0; j < 4; j++)
        t[ty + 8 * j][tx] = src[(long long)(k0 + ty + 8 * j) * HSn + n0 + tx];
    __syncthreads();
#pragma unroll
    for (int j = 0; j < 4; j++) {
        float v = t[tx][ty + 8 * j] * WSCALE;
        __half h2 = __float2half_rn(v);
        __half lo = __float2half_rn(v - __half2float(h2));
        long long o = base + (long long)(h * HSn + n0 + ty + 8 * j) * Dn + k0 + tx;
        g_wqkv_h[o] = h2; g_wqkv_l[o] = lo;
    }
}

// ---- V transpose: [b*T+t, h*64+e] fp16 hi/lo -> [bh, e, t] ----
__global__ void vtrans_kernel(const __half* __restrict__ vh, const __half* __restrict__ vl,
                              __half* __restrict__ oth, __half* __restrict__ otl) {
    int bh = blockIdx.z, b = bh >> 4, h = bh & 15;
    int t0 = blockIdx.x * 32, e0 = blockIdx.y * 32;
    __shared__ __half sh[32][34], sl[32][34];
    int tx = threadIdx.x, ty = threadIdx.y;
#pragma unroll
    for (int j = 0; j < 4; j++) {
        long long gi = ((long long)(b * Tn + t0 + ty + 8 * j)) * Dn + h * HSn + e0 + tx;
        sh[ty + 8 * j][tx] = vh[gi];
        sl[ty + 8 * j][tx] = vl[gi];
    }
    __syncthreads();
#pragma unroll
    for (int j = 0; j < 4; j++) {
        long long go = ((long long)bh * HSn + e0 + ty + 8 * j) * Tn + t0 + tx;
        oth[go] = sh[tx][ty + 8 * j];
        otl[go] = sl[tx][ty + 8 * j];
    }
}

// ===================== mma.sync fp16-split GEMM (2-pass, BK=64, 2-stage) ======
enum { EPI_F32 = 0, EPI_HILO = 1, EPI_BIAS_RESID = 2, EPI_BIAS_GELU = 3, EPI_GELU_HI = 4 };

// 128B rows + 8-chunk swizzle; stage: Ah | Bh | Bl   (BK=64 halfs = 128B)
template <int BN> struct TgCfg {
    static constexpr int A_B = 128 * 128;                // 16384
    static constexpr int B_B = BN * 128;
    static constexpr int B_OFF = A_B;
    static constexpr int STAGE = A_B + 2 * B_B;          // 49152 @ BN=128
    static constexpr int SMEM = 2 * STAGE;               // 98304
    static constexpr int WN = BN / 4;
    static constexpr int NTN = WN / 8;
};

template <int BN>
DI void tg_load(uint32_t sd, const __half* __restrict__ Ahp, int lda,
                const __half* __restrict__ Bhp, const __half* __restrict__ Blp,
                int ldb, int k0, int tid) {
    using C = TgCfg<BN>;
#pragma unroll
    for (int j = 0; j < 4; j++) {                 // A: 128 rows x 8 chunks = 1024 cp16
        int cid = tid + j * 256;
        int r = cid >> 3;
        int ch = cid & 7;
        long long go = (long long)r * lda + k0 + ch * 8;
        cp16(swz8(sd, r, ch), Ahp + go);
    }
#pragma unroll
    for (int j = 0; j < BN / 32; j++) {           // B: BN rows x 8 chunks, two halves
        int cid = tid + j * 256;
        int r = cid >> 3;
        int ch = cid & 7;
        uint32_t d = swz8(sd + (uint32_t)C::B_OFF, r, ch);
        long long go = (long long)r * ldb + k0 + ch * 8;
        cp16(d, Bhp + go);
        cp16(d + (uint32_t)C::B_B, Blp + go);
    }
}

template <int BN>
DI void tg_compute(uint32_t sb, int wm, int wn, int lane,
                   float acc[4][TgCfg<BN>::NTN][4]) {
    using C = TgCfg<BN>;
    constexpr int NTN = C::NTN;
    const uint32_t sbB = sb + (uint32_t)C::B_OFF;
    const int i4 = lane >> 3;
    const int l8 = lane & 7;
#pragma unroll
    for (int ks = 0; ks < 4; ks++) {              // BK=64 = 4 x k16
        uint32_t bhf[NTN][2], blf[NTN][2];
#pragma unroll
        for (int nt = 0; nt < NTN; nt++) {
            int rowb = wn * C::WN + nt * 8 + l8;
            int chb  = ks * 2 + (i4 & 1);
            uint32_t bd = swz8(sbB, rowb, chb);
            ldsm2(bd, bhf[nt]);
            ldsm2(bd + (uint32_t)C::B_B, blf[nt]);
        }
#pragma unroll
        for (int mt = 0; mt < 4; mt++) {
            uint32_t ahf[4];
            int row = wm * 64 + mt * 16 + (i4 & 1) * 8 + l8;
            int cha = ks * 2 + (i4 >> 1);
            ldsm4(swz8(sb, row, cha), ahf);
#pragma unroll
            for (int nt = 0; nt < NTN; nt++) {
                mma16816(acc[mt][nt], ahf, bhf[nt]);
                mma16816(acc[mt][nt], ahf, blf[nt]);
            }
        }
    }
}

template <int EPI, int BN>
__global__ void __launch_bounds__(256, 2) tgemm(
    const __half* __restrict__ Ah, int lda, long long sA,
    const __half* __restrict__ Bh, const __half* __restrict__ Bl, int ldb, long long sB,
    float* __restrict__ Cf, __half* __restrict__ Ch, __half* __restrict__ Cl,
    int ldc, long long sC, const float* __restrict__ bias, int Kext, float oscale)
{
    using C = TgCfg<BN>;
    constexpr int NTN = C::NTN;
    constexpr uint32_t STG = (uint32_t)C::STAGE;
    extern __shared__ char smraw[];
    const uint32_t sb0 = smem_u32(smraw);
    const int tid = threadIdx.x;
    const int lane = tid & 31, wid = tid >> 5;
    const int wm = wid & 1, wn = wid >> 1;
    const int z = blockIdx.z;

    long long aoff = sA * z;
    long long boff = sB * z;
    long long coff = sC * z;

    const __half* Ahp = Ah + aoff + (long long)blockIdx.x * 128 * lda;
    const __half* Bhp = Bh + boff + (long long)blockIdx.y * BN * ldb;
    const __half* Blp = Bl + boff + (long long)blockIdx.y * BN * ldb;

    float acc[4][NTN][4];
#pragma unroll
    for (int a = 0; a < 4; a++)
#pragma unroll
        for (int b = 0; b < NTN; b++)
#pragma unroll
            for (int c = 0; c < 4; c++) acc[a][b][c] = 0.f;

    const int NI = Kext >> 6;                    // BK = 64
    tg_load<BN>(sb0, Ahp, lda, Bhp, Blp, ldb, 0, tid);
    CP_COMMIT();
    for (int it = 0; it < NI; it++) {
        CP_WAIT0();                              // only load(it) in flight here
        __syncthreads();                         // protects buffer (it+1)&1 (read at it-1)
        if (it + 1 < NI) {
            tg_load<BN>(sb0 + (uint32_t)(((it + 1) & 1) * STG),
                        Ahp, lda, Bhp, Blp, ldb, (it + 1) << 6, tid);
            CP_COMMIT();
        }
        tg_compute<BN>(sb0 + (uint32_t)((it & 1) * STG), wm, wn, lane, acc);
    }

    // epilogue
    const int q = lane >> 2;
    const int cp2 = (lane & 3) * 2;
    const int gc = blockIdx.y * BN + wn * C::WN;
#pragma unroll
    for (int mt = 0; mt < 4; mt++) {
#pragma unroll
        for (int nt = 0; nt < NTN; nt++) {
            const float* a = acc[mt][nt];
            int cc = gc + nt * 8 + cp2;
#pragma unroll
            for (int half = 0; half < 2; half++) {
                int rr = blockIdx.x * 128 + wm * 64 + mt * 16 + q + half * 8;
                float v0 = a[half * 2 + 0] * oscale;
                float v1 = a[half * 2 + 1] * oscale;
                long long o = coff + (long long)rr * ldc + cc;
                if (EPI == EPI_BIAS_RESID || EPI == EPI_BIAS_GELU || EPI == EPI_GELU_HI) {
                    v0 += bias[cc]; v1 += bias[cc + 1];
                }
                if (EPI == EPI_F32) {
                    *(float2*)(Cf + o) = make_float2(v0, v1);
                } else if (EPI == EPI_BIAS_RESID) {
                    float2 r = *(float2*)(Cf + o);
                    *(float2*)(Cf + o) = make_float2(v0 + r.x, v1 + r.y);
                } else {  // HILO / BIAS_GELU / GELU_HI
                    if (EPI == EPI_BIAS_GELU || EPI == EPI_GELU_HI) {
                        v0 = gelu_exact(v0); v1 = gelu_exact(v1);
                    }
                    __half h0 = __float2half_rn(v0), h1 = __float2half_rn(v1);
                    *(__half2*)(Ch + o) = __halves2half2(h0, h1);
                    if (EPI != EPI_GELU_HI) {
                        __half l0 = __float2half_rn(v0 - __half2float(h0));
                        __half l1 = __float2half_rn(v1 - __half2float(h1));
                        *(__half2*)(Cl + o) = __halves2half2(l0, l1);
                    }
                }
            }
        }
    }
}

// ===================== flash attention (fused QK^T + softmax + PV) =====================
// attention stays full 3-pass hi/lo internally; output hi only (proj is 2-pass)
constexpr int FA_SMEM = 65536;

__global__ void __launch_bounds__(256, 2) flash_kernel(
    const __half* __restrict__ qkh, const __half* __restrict__ qkl,
    const __half* __restrict__ vth, const __half* __restrict__ vtl,
    __half* __restrict__ ohp)
{
    extern __shared__ char smraw[];
    const uint32_t sb = smem_u32(smraw);
    const uint32_t qhS = sb, qlS = sb + 16384, khS = sb + 32768, klS = sb + 40960,
                   vhS = sb + 49152, vlS = sb + 57344;
    const int tid = threadIdx.x, lane = tid & 31, w = tid >> 5;
    const int bz = blockIdx.z, b = bz >> 4, h = bz & 15;
    const int hc = h * 64;
    const long long qrow0 = (long long)b * Tn + blockIdx.x * 128;
    const __half* Qh = qkh;
    const __half* Kh = qkh + (long long)BTn * Dn;
    const __half* Ql = qkl;
    const __half* Kl = qkl + (long long)BTn * Dn;

#pragma unroll
    for (int i = 0; i < 4; i++) {
        int cid = tid + i * 256;
        int r = cid >> 3, c = cid & 7;
        long long g = (qrow0 + r) * Dn + hc + c * 8;
        cp16(swz8(qhS, r, c), Qh + g);
        cp16(swz8(qlS, r, c), Ql + g);
    }
    CP_COMMIT();

    float oacc[8][4];
    float mrun[2] = {-3e38f, -3e38f}, lrun[2] = {0.f, 0.f};
#pragma unroll
    for (int e = 0; e < 8; e++)
#pragma unroll
        for (int i = 0; i < 4; i++) oacc[e][i] = 0.f;

    const int i4 = lane >> 3, l8 = lane & 7, sel = lane >> 3;
    const long long kvb = (long long)b * Tn;

    for (int j = 0; j < 8; j++) {
        __syncthreads();
#pragma unroll
        for (int i = 0; i < 2; i++) {
            int cid = tid + i * 256;
            int r = cid >> 3, c = cid & 7;
            long long gk = (kvb + j * 64 + r) * Dn + hc + c * 8;
            cp16(swz8(khS, r, c), Kh + gk);
            cp16(swz8(klS, r, c), Kl + gk);
            long long gv = ((long long)bz * 64 + r) * Tn + j * 64 + c * 8;
            cp16(swz8(vhS, r, c), vth + gv);
            cp16(swz8(vlS, r, c), vtl + gv);
        }
        CP_COMMIT();
        CP_WAIT0();
        __syncthreads();

        float sacc[8][4];
#pragma unroll
        for (int e = 0; e < 8; e++)
#pragma unroll
            for (int i = 0; i < 4; i++) sacc[e][i] = 0.f;
#pragma unroll
        for (int ks = 0; ks < 4; ks++) {
            uint32_t qf[4], qlf[4];
            {
                int row = w * 16 + (i4 & 1) * 8 + l8;
                int c = ks * 2 + (i4 >> 1);
                ldsm4(swz8(qhS, row, c), qf);
                ldsm4(swz8(qlS, row, c), qlf);
            }
#pragma unroll
            for (int np = 0; np < 4; np++) {
                uint32_t bh4[4], bl4[4];
                int row = np * 16 + ((sel >> 1) << 3) + l8;
                int c = ks * 2 + (sel & 1);
                ldsm4(swz8(khS, row, c), bh4);
                ldsm4(swz8(klS, row, c), bl4);
                mma16816(sacc[np * 2], qf, bh4);
                mma16816(sacc[np * 2], qf, bl4);
                mma16816(sacc[np * 2], qlf, bh4);
                mma16816(sacc[np * 2 + 1], qf, bh4 + 2);
                mma16816(sacc[np * 2 + 1], qf, bl4 + 2);
                mma16816(sacc[np * 2 + 1], qlf, bh4 + 2);
            }
        }
        float m0 = -3e38f, m1 = -3e38f;
#pragma unroll
        for (int e = 0; e < 8; e++) {
            m0 = fmaxf(m0, fmaxf(sacc[e][0], sacc[e][1]));
            m1 = fmaxf(m1, fmaxf(sacc[e][2], sacc[e][3]));
        }
        m0 = fmaxf(m0, __shfl_xor_sync(0xffffffffu, m0, 1));
        m0 = fmaxf(m0, __shfl_xor_sync(0xffffffffu, m0, 2));
        m1 = fmaxf(m1, __shfl_xor_sync(0xffffffffu, m1, 1));
        m1 = fmaxf(m1, __shfl_xor_sync(0xffffffffu, m1, 2));
        float mn0 = fmaxf(mrun[0], m0 * 0.125f);
        float mn1 = fmaxf(mrun[1], m1 * 0.125f);
        float cr0 = __expf(mrun[0] - mn0);
        float cr1 = __expf(mrun[1] - mn1);
        mrun[0] = mn0; mrun[1] = mn1;
        float ls0 = 0.f, ls1 = 0.f;
#pragma unroll
        for (int e = 0; e < 8; e++) {
            sacc[e][0] = __expf(fmaf(sacc[e][0], 0.125f, -mn0));
            sacc[e][1] = __expf(fmaf(sacc[e][1], 0.125f, -mn0));
            sacc[e][2] = __expf(fmaf(sacc[e][2], 0.125f, -mn1));
            sacc[e][3] = __expf(fmaf(sacc[e][3], 0.125f, -mn1));
            ls0 += sacc[e][0] + sacc[e][1];
            ls1 += sacc[e][2] + sacc[e][3];
        }
        lrun[0] = lrun[0] * cr0 + ls0;
        lrun[1] = lrun[1] * cr1 + ls1;
#pragma unroll
        for (int e = 0; e < 8; e++) {
            oacc[e][0] *= cr0; oacc[e][1] *= cr0;
            oacc[e][2] *= cr1; oacc[e][3] *= cr1;
        }
#pragma unroll
        for (int kt = 0; kt < 4; kt++) {
            int t0 = kt * 2, t1 = kt * 2 + 1;
            __half2 h0 = __floats2half2_rn(sacc[t0][0], sacc[t0][1]);
            __half2 h1 = __floats2half2_rn(sacc[t0][2], sacc[t0][3]);
            __half2 h2 = __floats2half2_rn(sacc[t1][0], sacc[t1][1]);
            __half2 h3 = __floats2half2_rn(sacc[t1][2], sacc[t1][3]);
            uint32_t pa[4] = {h2u2(h0), h2u2(h1), h2u2(h2), h2u2(h3)};
            float2 f0 = __half22float2(h0), f1 = __half22float2(h1),
                   f2 = __half22float2(h2), f3 = __half22float2(h3);
            uint32_t pl[4] = {
                h2u2(__floats2half2_rn(sacc[t0][0] - f0.x, sacc[t0][1] - f0.y)),
                h2u2(__floats2half2_rn(sacc[t0][2] - f1.x, sacc[t0][3] - f1.y)),
                h2u2(__floats2half2_rn(sacc[t1][0] - f2.x, sacc[t1][1] - f2.y)),
                h2u2(__floats2half2_rn(sacc[t1][2] - f3.x, sacc[t1][3] - f3.y))};
#pragma unroll
            for (int ep = 0; ep < 4; ep++) {
                uint32_t vh4[4], vl4[4];
                int row = ep * 16 + ((sel >> 1) << 3) + l8;
                int c = kt * 2 + (sel & 1);
                ldsm4(swz8(vhS, row, c), vh4);
                ldsm4(swz8(vlS, row, c), vl4);
                mma16816(oacc[ep * 2], pa, vh4);
                mma16816(oacc[ep * 2], pa, vl4);
                mma16816(oacc[ep * 2], pl, vh4);
                mma16816(oacc[ep * 2 + 1], pa, vh4 + 2);
                mma16816(oacc[ep * 2 + 1], pa, vl4 + 2);
                mma16816(oacc[ep * 2 + 1], pl, vh4 + 2);
            }
        }
    }

    float l0 = lrun[0];
    l0 += __shfl_xor_sync(0xffffffffu, l0, 1);
    l0 += __shfl_xor_sync(0xffffffffu, l0, 2);
    float l1 = lrun[1];
    l1 += __shfl_xor_sync(0xffffffffu, l1, 1);
    l1 += __shfl_xor_sync(0xffffffffu, l1, 2);
    float inv0 = 1.0f / l0, inv1 = 1.0f / l1;
    long long bt0 = qrow0 + w * 16 + (lane >> 2);
    int colb = hc + (lane & 3) * 2;
#pragma unroll
    for (int e = 0; e < 8; e++) {
        long long o0 = bt0 * Dn + colb + e * 8;
        long long o1 = (bt0 + 8) * Dn + colb + e * 8;
        *(__half2*)(ohp + o0) = __floats2half2_rn(oacc[e][0] * inv0, oacc[e][1] * inv0);
        *(__half2*)(ohp + o1) = __floats2half2_rn(oacc[e][2] * inv1, oacc[e][3] * inv1);
    }
}

// ---- logits: 2-stage deterministic reduction ----
__global__ void logits_part(const float* __restrict__ hf, const float* __restrict__ Wout) {
    int b = blockIdx.x, c = blockIdx.y;
    const int CHUNK = Tn * Dn / 16;
    const float* hb = hf + (long long)b * Tn * Dn + c * CHUNK;
    const float* wb = Wout + ((long long)c * CHUNK) * NCn;
    float a[3] = {0.f, 0.f, 0.f};
    for (int i = threadIdx.x; i < CHUNK; i += blockDim.x) {
        float v = hb[i];
        const float* wr = wb + (long long)i * NCn;
        a[0] = fmaf(v, wr[0], a[0]);
        a[1] = fmaf(v, wr[1], a[1]);
        a[2] = fmaf(v, wr[2], a[2]);
    }
    __shared__ float sm[3][8];
    int w = threadIdx.x >> 5, ln = threadIdx.x & 31;
#pragma unroll
    for (int cc = 0; cc < 3; cc++) {
        float v = warp_sum(a[cc]);
        if (ln == 0) sm[cc][w] = v;
    }
    __syncthreads();
    if (threadIdx.x < 3) {
        float t = 0.f;
#pragma unroll
        for (int i = 0; i < 8; i++) t += sm[threadIdx.x][i];
        g_lpart[(b * 16 + c) * NCn + threadIdx.x] = t;
    }
}
__global__ void logits_final(const float* __restrict__ bout, float* __restrict__ out) {
    int t = threadIdx.x;
    if (t >= Bn * NCn) return;
    int b = t / NCn, c = t % NCn;
    float s = bout[c];
#pragma unroll
    for (int i = 0; i < 16; i++) s += g_lpart[(b * 16 + i) * NCn + c];
    out[b * NCn + c] = s;
}

}  // namespace enc

extern "C" void kernel_launch(void* const* d_in, const int* in_sizes, int n_in,
                              void* d_out, int out_size) {
    using namespace enc;
    (void)in_sizes; (void)n_in; (void)out_size;

    const int*   x     = (const int*)d_in[0];
    const float* tok   = (const float*)d_in[1];
    const float* pos   = (const float*)d_in[2];
    const float* Wq    = (const float*)d_in[3];
    const float* Wk    = (const float*)d_in[4];
    const float* Wv    = (const float*)d_in[5];
    const float* Wproj = (const float*)d_in[6];
    const float* bproj = (const float*)d_in[7];
    const float* ln1g  = (const float*)d_in[8];
    const float* ln1b  = (const float*)d_in[9];
    const float* ln2g  = (const float*)d_in[10];
    const float* ln2b  = (const float*)d_in[11];
    const float* W1    = (const float*)d_in[12];
    const float* b1    = (const float*)d_in[13];
    const float* W2    = (const float*)d_in[14];
    const float* b2    = (const float*)d_in[15];
    const float* lnfg  = (const float*)d_in[16];
    const float* lnfb  = (const float*)d_in[17];
    const float* Wout  = (const float*)d_in[18];
    const float* bout  = (const float*)d_in[19];
    float* out = (float*)d_out;

    static float *ph = nullptr, *pz;
    static __half *zh, *qh, *ql, *vth, *vtl, *fh;
    static __half *wqh, *wql, *wph, *wpl, *w1h, *w1l, *w2h, *w2l;
    if (!ph) {
        cudaGetSymbolAddress((void**)&ph,   g_h);
        cudaGetSymbolAddress((void**)&pz,   g_z);
        cudaGetSymbolAddress((void**)&zh, g_zh);
        cudaGetSymbolAddress((void**)&qh, g_qkvh);
        cudaGetSymbolAddress((void**)&ql, g_qkvl);
        cudaGetSymbolAddress((void**)&vth, g_vth);
        cudaGetSymbolAddress((void**)&vtl, g_vtl);
        cudaGetSymbolAddress((void**)&fh, g_ffnh);
        cudaGetSymbolAddress((void**)&wqh, g_wqkv_h);
        cudaGetSymbolAddress((void**)&wql, g_wqkv_l);
        cudaGetSymbolAddress((void**)&wph, g_wproj_h);
        cudaGetSymbolAddress((void**)&wpl, g_wproj_l);
        cudaGetSymbolAddress((void**)&w1h, g_w1_h);
        cudaGetSymbolAddress((void**)&w1l, g_w1_l);
        cudaGetSymbolAddress((void**)&w2h, g_w2_h);
        cudaGetSymbolAddress((void**)&w2l, g_w2_l);
        cudaFuncSetAttribute((const void*)tgemm<EPI_HILO, 128>,
                             cudaFuncAttributeMaxDynamicSharedMemorySize, TgCfg<128>::SMEM);
        cudaFuncSetAttribute((const void*)tgemm<EPI_BIAS_RESID, 128>,
                             cudaFuncAttributeMaxDynamicSharedMemorySize, TgCfg<128>::SMEM);
        cudaFuncSetAttribute((const void*)tgemm<EPI_GELU_HI, 128>,
                             cudaFuncAttributeMaxDynamicSharedMemorySize, TgCfg<128>::SMEM);
        cudaFuncSetAttribute((const void*)flash_kernel,
                             cudaFuncAttributeMaxDynamicSharedMemorySize, FA_SMEM);
    }

    // ---- prep needed for layer-0 front (FFN prep deferred) ----
    wprep_qkv<<<dim3(Dn / 32, HSn / 32, Ln * 3 * Hn), dim3(32, 8)>>>(Wq, Wk, Wv);
    wprep_lin<<<dim3(Dn / 32, Dn / 32, Ln),   dim3(32, 8)>>>(Wproj, wph, wpl, Dn, Dn);

    for (int l = 0; l < Ln; l++) {
        // z = LN1(h) -> hi only (QKV is 2-pass)
        if (l == 0)
            ln_kernel<true, true><<<BTn, 256>>>(nullptr, ln1g, ln1b, nullptr, zh,
                                                x, tok, pos);
        else
            ln_kernel<true, false><<<BTn, 256>>>(ph, ln1g + l * Dn, ln1b + l * Dn,
                                                 nullptr, zh, nullptr, nullptr, nullptr);
        // q,k,v = z @ W -> hi/lo fp16 (2-pass; output split kept for 3-pass attention)
        tgemm<EPI_HILO, 128><<<dim3(BTn / 128, Dn / 128, 3), 256, TgCfg<128>::SMEM>>>(
            zh, Dn, 0LL,
            wqh + (long long)l * 3 * Dn * Dn, wql + (long long)l * 3 * Dn * Dn, Dn,
            (long long)Dn * Dn,
            nullptr, qh, ql, Dn, (long long)BTn * Dn, nullptr, Dn, INV_WSCALE);
        // V^T hi/lo
        vtrans_kernel<<<dim3(Tn / 32, HSn / 32, Bn * Hn), dim3(32, 8)>>>(
            qh + 2LL * BTn * Dn, ql + 2LL * BTn * Dn, vth, vtl);
        // fused attention -> o hi in zh (proj is 2-pass)
        flash_kernel<<<dim3(Tn / 128, 1, Bn * Hn), 256, FA_SMEM>>>(
            qh, ql, vth, vtl, zh);
        // h += o @ Wproj + bproj (2-pass)
        tgemm<EPI_BIAS_RESID, 128><<<dim3(BTn / 128, Dn / 128, 1), 256, TgCfg<128>::SMEM>>>(
            zh, Dn, 0LL,
            wph + (long long)l * Dn * Dn, wpl + (long long)l * Dn * Dn, Dn, 0LL,
            ph, nullptr, nullptr, Dn, 0LL, bproj + l * Dn, Dn, INV_WSCALE);
        // deferred FFN weight prep (once)
        if (l == 0) {
            wprep_lin<<<dim3(Dn / 32, DFFn / 32, Ln), dim3(32, 8)>>>(W1, w1h, w1l, Dn, DFFn);
            wprep_lin<<<dim3(DFFn / 32, Dn / 32, Ln), dim3(32, 8)>>>(W2, w2h, w2l, DFFn, Dn);
        }
        // z = LN2(h) -> hi only
        ln_kernel<true, false><<<BTn, 256>>>(ph, ln2g + l * Dn, ln2b + l * Dn,
                                             nullptr, zh, nullptr, nullptr, nullptr);
        // ffn = gelu(z @ W1 + b1) -> hi only (2-pass)
        tgemm<EPI_GELU_HI, 128><<<dim3(BTn / 128, DFFn / 128, 1), 256, TgCfg<128>::SMEM>>>(
            zh, Dn, 0LL,
            w1h + (long long)l * Dn * DFFn, w1l + (long long)l * Dn * DFFn, Dn, 0LL,
            nullptr, fh, nullptr, DFFn, 0LL, b1 + l * DFFn, Dn, INV_WSCALE);
        // h += ffn @ W2 + b2 (2-pass)
        tgemm<EPI_BIAS_RESID, 128><<<dim3(BTn / 128, Dn / 128, 1), 256, TgCfg<128>::SMEM>>>(
            fh, DFFn, 0LL,
            w2h + (long long)l * DFFn * Dn, w2l + (long long)l * DFFn * Dn, DFFn, 0LL,
            ph, nullptr, nullptr, Dn, 0LL, b2 + l * Dn, DFFn, INV_WSCALE);
    }
    ln_kernel<false, false><<<BTn, 256>>>(ph, lnfg, lnfb, pz, nullptr,
                                          nullptr, nullptr, nullptr);
    logits_part<<<dim3(Bn, 16), 256>>>(pz, Wout);
    logits_final<<<1, 64>>>(bout, out);
}